// round 5
// baseline (speedup 1.0000x reference)
#include <cuda_runtime.h>
#include <math.h>

#define BB 64

// ---------------------------------------------------------------------------
// f32x2 packed FMA helpers
// ---------------------------------------------------------------------------
typedef unsigned long long u64t;
__device__ __forceinline__ u64t ffma2(u64t a, u64t b, u64t c) {
    u64t d;
    asm("fma.rn.f32x2 %0, %1, %2, %3;" : "=l"(d) : "l"(a), "l"(b), "l"(c));
    return d;
}
__device__ __forceinline__ float f2lo(u64t v) { return __uint_as_float((unsigned)v); }
__device__ __forceinline__ float f2hi(u64t v) { return __uint_as_float((unsigned)(v >> 32)); }
__device__ __forceinline__ float f2sum(u64t v) { return f2lo(v) + f2hi(v); }
__device__ __forceinline__ u64t packf2(float lo, float hi) {
    return (u64t)__float_as_uint(lo) | ((u64t)__float_as_uint(hi) << 32);
}

// ---------------------------------------------------------------------------
// Scratch
// ---------------------------------------------------------------------------
__device__ float g_pooled1[BB * 3];
__device__ float g_attn1[BB * 8];
__device__ float g_w1[BB * 64 * 3 * 49];
__device__ float g_conv1[BB * 64 * 112 * 112];
__device__ float g_pool1[BB * 64 * 56 * 56];
__device__ float g_pooled2[BB * 64];
__device__ float g_attn2[BB * 8];
__device__ float g_w2[BB * 128 * 64 * 9];
__device__ float g_conv2[BB * 128 * 28 * 28];
__device__ float g_pool2[BB * 128 * 14 * 14];
__device__ float g_rc1[BB * 256 * 49];
__device__ float g_rc2[BB * 256 * 49];
__device__ float g_rs[BB * 256 * 49];

__device__ float g_sum1[64],  g_sq1[64],  g_sc1[64],  g_sh1[64];
__device__ float g_sum2[128], g_sq2[128], g_sc2[128], g_sh2[128];
__device__ float g_sumr1[256], g_sqr1[256], g_scr1[256], g_shr1[256];
__device__ float g_sumr2[256], g_sqr2[256], g_scr2[256], g_shr2[256];
__device__ float g_sums[256],  g_sqs[256],  g_scs[256],  g_shs[256];

__device__ float g_T[50 * 1024];
__device__ float g_M[50 * 256];
__device__ float g_b2[50];

// ---------------------------------------------------------------------------
// bn scale/shift
// ---------------------------------------------------------------------------
__global__ void k_bnscale(const float* __restrict__ g, const float* __restrict__ be,
                          float cnt, int stage, int C) {
    int c = blockIdx.x * blockDim.x + threadIdx.x;
    if (c >= C) return;
    float *su, *sq, *sc, *sh;
    switch (stage) {
        case 0:  su = g_sum1;  sq = g_sq1;  sc = g_sc1;  sh = g_sh1;  break;
        case 1:  su = g_sum2;  sq = g_sq2;  sc = g_sc2;  sh = g_sh2;  break;
        case 2:  su = g_sumr1; sq = g_sqr1; sc = g_scr1; sh = g_shr1; break;
        case 3:  su = g_sumr2; sq = g_sqr2; sc = g_scr2; sh = g_shr2; break;
        default: su = g_sums;  sq = g_sqs;  sc = g_scs;  sh = g_shs;  break;
    }
    float m = su[c] / cnt;
    float v = sq[c] / cnt - m * m;
    float s = g[c] * rsqrtf(v + 1e-5f);
    sc[c] = s;
    sh[c] = be[c] - m * s;
}

// per-channel stats of rc1
__global__ void k_chstats(int which) {
    const float* src = which ? g_rc2 : g_rc1;
    float* su = which ? g_sumr2 : g_sumr1;
    float* sq = which ? g_sqr2 : g_sqr1;
    int c = blockIdx.x;
    float s = 0.f, q = 0.f;
    for (int t = threadIdx.x; t < BB * 49; t += 128) {
        int b = t / 49, p = t - b * 49;
        float v = src[(b * 256 + c) * 49 + p];
        s += v; q += v * v;
    }
    for (int o = 16; o; o >>= 1) {
        s += __shfl_down_sync(0xffffffffu, s, o);
        q += __shfl_down_sync(0xffffffffu, q, o);
    }
    __shared__ float rs[4], rq[4];
    int w = threadIdx.x >> 5;
    if ((threadIdx.x & 31) == 0) { rs[w] = s; rq[w] = q; }
    __syncthreads();
    if (threadIdx.x == 0) {
        su[c] = rs[0] + rs[1] + rs[2] + rs[3];
        sq[c] = rq[0] + rq[1] + rq[2] + rq[3];
    }
}

// stats of rc2 AND rs in one launch
__global__ void k_chstats2() {
    int c = blockIdx.x;
    float s2 = 0.f, q2 = 0.f, ss = 0.f, qs = 0.f;
    for (int t = threadIdx.x; t < BB * 49; t += 128) {
        int b = t / 49, p = t - b * 49;
        float v = g_rc2[(b * 256 + c) * 49 + p];
        s2 += v; q2 += v * v;
        float u = g_rs[(b * 256 + c) * 49 + p];
        ss += u; qs += u * u;
    }
    for (int o = 16; o; o >>= 1) {
        s2 += __shfl_down_sync(0xffffffffu, s2, o);
        q2 += __shfl_down_sync(0xffffffffu, q2, o);
        ss += __shfl_down_sync(0xffffffffu, ss, o);
        qs += __shfl_down_sync(0xffffffffu, qs, o);
    }
    __shared__ float r[4][4];
    int w = threadIdx.x >> 5;
    if ((threadIdx.x & 31) == 0) { r[w][0] = s2; r[w][1] = q2; r[w][2] = ss; r[w][3] = qs; }
    __syncthreads();
    if (threadIdx.x == 0) {
        g_sumr2[c] = r[0][0] + r[1][0] + r[2][0] + r[3][0];
        g_sqr2[c]  = r[0][1] + r[1][1] + r[2][1] + r[3][1];
        g_sums[c]  = r[0][2] + r[1][2] + r[2][2] + r[3][2];
        g_sqs[c]   = r[0][3] + r[1][3] + r[2][3] + r[3][3];
    }
}

// ---------------------------------------------------------------------------
// Stage-1 attention
// ---------------------------------------------------------------------------
__global__ void k_pooled1(const float* __restrict__ imgs) {
    int bc = blockIdx.x;
    int tid = threadIdx.x;
    if (bc == 0) {
        for (int i = tid; i < BB * 64; i += 256) g_pooled2[i] = 0.f;
        if (tid < 64)  { g_sum1[tid] = 0.f; g_sq1[tid] = 0.f; }
        if (tid < 128) { g_sum2[tid] = 0.f; g_sq2[tid] = 0.f; }
    }
    const float* p = imgs + (long)bc * 50176;
    float s = 0.f;
    for (int i = tid; i < 50176; i += 256) s += p[i];
    __shared__ float red[256];
    red[tid] = s; __syncthreads();
    for (int o = 128; o; o >>= 1) { if (tid < o) red[tid] += red[tid + o]; __syncthreads(); }
    if (tid == 0) g_pooled1[bc] = red[0] * (1.f / 50176.f);
}

__global__ void k_attn1(const float* __restrict__ fc1, const float* __restrict__ fc2,
                        const float* __restrict__ fc2b) {
    int b = threadIdx.x;
    if (b >= BB) return;
    float p[3];
    for (int c = 0; c < 3; c++) p[c] = g_pooled1[b * 3 + c];
    float h[8];
    for (int j = 0; j < 8; j++) {
        float s = 0.f;
        for (int c = 0; c < 3; c++) s += p[c] * fc1[j * 3 + c];
        h[j] = fmaxf(s, 0.f);
    }
    float lg[8], mx = -1e30f;
    for (int k = 0; k < 8; k++) {
        float s = fc2b[k];
        for (int j = 0; j < 8; j++) s += h[j] * fc2[k * 8 + j];
        lg[k] = s; mx = fmaxf(mx, s);
    }
    float den = 0.f;
    for (int k = 0; k < 8; k++) { lg[k] = expf(lg[k] - mx); den += lg[k]; }
    float inv = 1.f / den;
    for (int k = 0; k < 8; k++) g_attn1[b * 8 + k] = lg[k] * inv;
}

__global__ void k_w1agg(const float* __restrict__ dy1) {
    int idx = blockIdx.x * 256 + threadIdx.x;
    if (idx >= BB * 9408) return;
    int b = idx / 9408, i = idx - b * 9408;
    float s = 0.f;
#pragma unroll
    for (int k = 0; k < 8; k++) s += g_attn1[b * 8 + k] * dy1[k * 9408 + i];
    g_w1[idx] = s;
}

// ---------------------------------------------------------------------------
// Conv1: 3->64, 7x7 s2 p3. FFMA2 over kw pairs (tap 7 zero-padded).
// grid (28, 8 cog, 64 b), block 128 (112 active).
// ---------------------------------------------------------------------------
__global__ void __launch_bounds__(128) k_conv1(const float* __restrict__ imgs) {
    __shared__ __align__(16) float s_in[3 * 37 * 62];
    __shared__ __align__(16) float s_w[8 * 3 * 7 * 8];  // [co][ci][kh][8], slot7=0
    __shared__ float s_stat[16];
    int b = blockIdx.z, cog = blockIdx.y;
    int tr = blockIdx.x >> 2, tc = blockIdx.x & 3;
    int oh0 = tr * 16, ow0 = tc * 28;
    int tid = threadIdx.x;

    for (int t = tid; t < 1344; t += 128) {
        int co = t / 168, rem = t - co * 168;
        int ci = rem / 56, rem2 = rem - ci * 56;
        int kh = rem2 >> 3, kw = rem2 & 7;
        float v = 0.f;
        if (kw < 7)
            v = g_w1[b * 9408 + (cog * 8 + co) * 147 + ci * 49 + kh * 7 + kw];
        s_w[t] = v;
    }
    int ih0 = 2 * oh0 - 3, iw0 = 2 * ow0 - 3;
    for (int t = tid; t < 6882; t += 128) {
        int ci = t / 2294, rem = t - ci * 2294;
        int r = rem / 62, c = rem - r * 62;
        int ih = ih0 + r, iw = iw0 + c;
        float v = 0.f;
        if ((unsigned)ih < 224u && (unsigned)iw < 224u)
            v = imgs[((b * 3 + ci) * 224 + ih) * 224 + iw];
        s_in[t] = v;
    }
    if (tid < 16) s_stat[tid] = 0.f;
    __syncthreads();

    u64t acc2[4][8];
#pragma unroll
    for (int j = 0; j < 4; j++)
#pragma unroll
        for (int co = 0; co < 8; co++) acc2[j][co] = 0ull;

    int tx = tid % 28, ty = tid / 28;
    if (tid < 112) {
#pragma unroll 1
        for (int ci = 0; ci < 3; ci++) {
#pragma unroll 1
            for (int kh = 0; kh < 7; kh++) {
                int rbase = ci * 2294 + (8 * ty + kh) * 62 + 2 * tx;   // even
                u64t inp[4][4];
#pragma unroll
                for (int j = 0; j < 4; j++) {
                    const u64t* rp = (const u64t*)(s_in + rbase + 124 * j);
#pragma unroll
                    for (int p = 0; p < 4; p++) inp[j][p] = rp[p];
                }
#pragma unroll
                for (int co = 0; co < 8; co++) {
                    const u64t* wq = (const u64t*)(s_w + co * 168 + ci * 56 + kh * 8);
                    u64t w0 = wq[0], w1 = wq[1], w2 = wq[2], w3 = wq[3];
#pragma unroll
                    for (int j = 0; j < 4; j++) {
                        acc2[j][co] = ffma2(w0, inp[j][0], acc2[j][co]);
                        acc2[j][co] = ffma2(w1, inp[j][1], acc2[j][co]);
                        acc2[j][co] = ffma2(w2, inp[j][2], acc2[j][co]);
                        acc2[j][co] = ffma2(w3, inp[j][3], acc2[j][co]);
                    }
                }
            }
        }
    }
    float acc[4][8];
#pragma unroll
    for (int j = 0; j < 4; j++)
#pragma unroll
        for (int co = 0; co < 8; co++) acc[j][co] = f2sum(acc2[j][co]);

    if (tid < 112) {
#pragma unroll
        for (int co = 0; co < 8; co++) {
            long cb = ((long)(b * 64 + cog * 8 + co)) * 12544;
#pragma unroll
            for (int j = 0; j < 4; j++) {
                int oh = oh0 + 4 * ty + j;
                g_conv1[cb + oh * 112 + ow0 + tx] = acc[j][co];
            }
        }
    }
#pragma unroll
    for (int co = 0; co < 8; co++) {
        float s = acc[0][co] + acc[1][co] + acc[2][co] + acc[3][co];
        float q = acc[0][co] * acc[0][co] + acc[1][co] * acc[1][co]
                + acc[2][co] * acc[2][co] + acc[3][co] * acc[3][co];
        for (int o = 16; o; o >>= 1) {
            s += __shfl_down_sync(0xffffffffu, s, o);
            q += __shfl_down_sync(0xffffffffu, q, o);
        }
        if ((tid & 31) == 0) { atomicAdd(&s_stat[co], s); atomicAdd(&s_stat[8 + co], q); }
    }
    __syncthreads();
    if (tid < 8) {
        atomicAdd(&g_sum1[cog * 8 + tid], s_stat[tid]);
        atomicAdd(&g_sq1[cog * 8 + tid], s_stat[8 + tid]);
    }
}

// ---------------------------------------------------------------------------
// BN1 + maxpool3 s2 p1: 112->56, accumulate pooled2
// ---------------------------------------------------------------------------
__global__ void k_bnpool1() {
    int b = blockIdx.z, c = blockIdx.y;
    int p = blockIdx.x * 256 + threadIdx.x;
    float outv = 0.f;
    bool valid = (p < 3136);
    if (valid) {
        int oh = p / 56, ow = p - oh * 56;
        float sc = g_sc1[c], sh = g_sh1[c];
        const float* ip = g_conv1 + (long)(b * 64 + c) * 12544;
        float m = -1e30f;
#pragma unroll
        for (int r = 0; r < 3; r++) {
            int ih = 2 * oh - 1 + r;
            if ((unsigned)ih >= 112u) continue;
#pragma unroll
            for (int cc = 0; cc < 3; cc++) {
                int iw = 2 * ow - 1 + cc;
                if ((unsigned)iw >= 112u) continue;
                m = fmaxf(m, ip[ih * 112 + iw] * sc + sh);
            }
        }
        g_pool1[(b * 64 + c) * 3136 + p] = m;
        outv = m;
    }
    float s = valid ? outv : 0.f;
    for (int o = 16; o; o >>= 1) s += __shfl_down_sync(0xffffffffu, s, o);
    __shared__ float s_red;
    if (threadIdx.x == 0) s_red = 0.f;
    __syncthreads();
    if ((threadIdx.x & 31) == 0) atomicAdd(&s_red, s);
    __syncthreads();
    if (threadIdx.x == 0) atomicAdd(&g_pooled2[b * 64 + c], s_red);
}

// ---------------------------------------------------------------------------
// Stage-2 attention
// ---------------------------------------------------------------------------
__global__ void k_attn2(const float* __restrict__ fc1, const float* __restrict__ fc2,
                        const float* __restrict__ fc2b) {
    int b = threadIdx.x;
    if (b >= BB) return;
    float h[17];
    for (int j = 0; j < 17; j++) {
        float s = 0.f;
        for (int c = 0; c < 64; c++)
            s += (g_pooled2[b * 64 + c] * (1.f / 3136.f)) * fc1[j * 64 + c];
        h[j] = fmaxf(s, 0.f);
    }
    float lg[8], mx = -1e30f;
    for (int k = 0; k < 8; k++) {
        float s = fc2b[k];
        for (int j = 0; j < 17; j++) s += h[j] * fc2[k * 17 + j];
        lg[k] = s; mx = fmaxf(mx, s);
    }
    float den = 0.f;
    for (int k = 0; k < 8; k++) { lg[k] = expf(lg[k] - mx); den += lg[k]; }
    float inv = 1.f / den;
    for (int k = 0; k < 8; k++) g_attn2[b * 8 + k] = lg[k] * inv;
}

__global__ void k_w2agg(const float* __restrict__ dy2) {
    int idx = blockIdx.x * 256 + threadIdx.x;
    if (idx >= BB * 73728) return;
    int b = idx / 73728, i = idx - b * 73728;
    float s = 0.f;
#pragma unroll
    for (int k = 0; k < 8; k++) s += g_attn2[b * 8 + k] * dy2[k * 73728 + i];
    g_w2[idx] = s;
}

// ---------------------------------------------------------------------------
// Conv2: 64->128, 3x3 s2 p1: 56->28. FFMA2 over kw pairs (tap 3 = 0).
// grid (16 cog, 64 b), block 224 (196 active).
// ---------------------------------------------------------------------------
__global__ void __launch_bounds__(224) k_conv2() {
    __shared__ __align__(16) float s_in[2 * 3364];
    __shared__ __align__(16) float s_w[8 * 2 * 3 * 4];  // [co][ci][kh][4], slot3=0
    __shared__ float s_stat[16];
    int b = blockIdx.y, cog = blockIdx.x;
    int tid = threadIdx.x;
    int tx = tid % 28, tyq = tid / 28;

    for (int t = tid; t < 2 * 3364; t += 224) s_in[t] = 0.f;
    if (tid < 192) s_w[tid] = 0.f;
    if (tid < 16) s_stat[tid] = 0.f;
    __syncthreads();

    u64t acc2[4][8];
#pragma unroll
    for (int j = 0; j < 4; j++)
#pragma unroll
        for (int co = 0; co < 8; co++) acc2[j][co] = 0ull;

#pragma unroll 1
    for (int c0 = 0; c0 < 64; c0 += 2) {
        for (int t = tid; t < 2 * 3136; t += 224) {
            int ci = t / 3136, p = t - ci * 3136;
            int r = p / 56, c = p - r * 56;
            s_in[ci * 3364 + (r + 1) * 58 + (c + 1)] =
                g_pool1[(b * 64 + c0 + ci) * 3136 + p];
        }
        if (tid < 144) {
            int co = tid / 18, rem = tid - co * 18;
            int cil = rem / 9, k = rem - cil * 9;
            int kh = k / 3, kw = k - kh * 3;
            s_w[co * 24 + cil * 12 + kh * 4 + kw] =
                g_w2[b * 73728 + (cog * 8 + co) * 576 + (c0 + cil) * 9 + k];
        }
        __syncthreads();
        if (tid < 196) {
#pragma unroll
            for (int ci = 0; ci < 2; ci++) {
#pragma unroll
                for (int kh = 0; kh < 3; kh++) {
                    int rbase = ci * 3364 + (8 * tyq + kh) * 58 + 2 * tx;  // even
                    u64t inp[4][2];
#pragma unroll
                    for (int j = 0; j < 4; j++) {
                        const u64t* rp = (const u64t*)(s_in + rbase + 116 * j);
                        inp[j][0] = rp[0]; inp[j][1] = rp[1];
                    }
#pragma unroll
                    for (int co = 0; co < 8; co++) {
                        const u64t* wq = (const u64t*)(s_w + co * 24 + ci * 12 + kh * 4);
                        u64t w0 = wq[0], w1 = wq[1];
#pragma unroll
                        for (int j = 0; j < 4; j++) {
                            acc2[j][co] = ffma2(w0, inp[j][0], acc2[j][co]);
                            acc2[j][co] = ffma2(w1, inp[j][1], acc2[j][co]);
                        }
                    }
                }
            }
        }
        __syncthreads();
    }

    float acc[4][8];
#pragma unroll
    for (int j = 0; j < 4; j++)
#pragma unroll
        for (int co = 0; co < 8; co++) acc[j][co] = f2sum(acc2[j][co]);

    if (tid < 196) {
#pragma unroll
        for (int co = 0; co < 8; co++) {
            int cb = (b * 128 + cog * 8 + co) * 784;
#pragma unroll
            for (int j = 0; j < 4; j++) {
                int oh = 4 * tyq + j;
                g_conv2[cb + oh * 28 + tx] = acc[j][co];
            }
        }
    }
#pragma unroll
    for (int co = 0; co < 8; co++) {
        float s = acc[0][co] + acc[1][co] + acc[2][co] + acc[3][co];
        float q = acc[0][co] * acc[0][co] + acc[1][co] * acc[1][co]
                + acc[2][co] * acc[2][co] + acc[3][co] * acc[3][co];
        for (int o = 16; o; o >>= 1) {
            s += __shfl_down_sync(0xffffffffu, s, o);
            q += __shfl_down_sync(0xffffffffu, q, o);
        }
        if ((tid & 31) == 0) { atomicAdd(&s_stat[co], s); atomicAdd(&s_stat[8 + co], q); }
    }
    __syncthreads();
    if (tid < 8) {
        atomicAdd(&g_sum2[cog * 8 + tid], s_stat[tid]);
        atomicAdd(&g_sq2[cog * 8 + tid], s_stat[8 + tid]);
    }
}

// ---------------------------------------------------------------------------
// BN2 + maxpool3 s2 p1: 28->14
// ---------------------------------------------------------------------------
__global__ void k_bnpool2() {
    int b = blockIdx.y, c = blockIdx.x;
    int p = threadIdx.x;
    if (p >= 196) return;
    int oh = p / 14, ow = p - oh * 14;
    float sc = g_sc2[c], sh = g_sh2[c];
    const float* ip = g_conv2 + (b * 128 + c) * 784;
    float m = -1e30f;
#pragma unroll
    for (int r = 0; r < 3; r++) {
        int ih = 2 * oh - 1 + r;
        if ((unsigned)ih >= 28u) continue;
#pragma unroll
        for (int cc = 0; cc < 3; cc++) {
            int iw = 2 * ow - 1 + cc;
            if ((unsigned)iw >= 28u) continue;
            m = fmaxf(m, ip[ih * 28 + iw] * sc + sh);
        }
    }
    g_pool2[(b * 128 + c) * 196 + p] = m;
}

// ---------------------------------------------------------------------------
// resconv1: 128->256 3x3 s2, 14->7. FFMA2 kw(0,1) + scalar kw2.
// ---------------------------------------------------------------------------
__global__ void __launch_bounds__(196) k_resconv1(const float* __restrict__ w) {
    __shared__ __align__(16) float s_in[4 * 4 * 270];   // [bl][ci][15x18]
    __shared__ __align__(16) float s_w[32 * 4 * 3 * 4]; // [co][ci][kh][4]
    int bq = blockIdx.y, cog = blockIdx.x;
    int b0 = bq * 4;
    int tid = threadIdx.x;
    int px = tid % 49, yq = tid / 49;
    int oh = px / 7, ow = px - oh * 7;
    u64t acc2[4][8];
    float accS[4][8];
#pragma unroll
    for (int bl = 0; bl < 4; bl++)
#pragma unroll
        for (int co = 0; co < 8; co++) { acc2[bl][co] = 0ull; accS[bl][co] = 0.f; }

#pragma unroll 1
    for (int c0 = 0; c0 < 128; c0 += 4) {
        for (int t = tid; t < 4 * 4 * 270; t += 196) {
            int bl = t / 1080, rem = t - bl * 1080;
            int ci = rem / 270, pos = rem - ci * 270;
            int r = pos / 18, c = pos - r * 18;
            int ih = r - 1, iw = c - 1;
            float v = 0.f;
            if ((unsigned)ih < 14u && (unsigned)iw < 14u)
                v = g_pool2[((b0 + bl) * 128 + c0 + ci) * 196 + ih * 14 + iw];
            s_in[t] = v;
        }
        for (int t = tid; t < 32 * 36; t += 196) {
            int co = t / 36, rem = t - co * 36;
            int ci = rem / 9, k = rem - ci * 9;
            int kh = k / 3, kw = k - kh * 3;
            s_w[co * 48 + ci * 12 + kh * 4 + kw] =
                w[(cog * 32 + co) * 1152 + (c0 + ci) * 9 + k];
        }
        __syncthreads();
#pragma unroll 1
        for (int ci = 0; ci < 4; ci++) {
#pragma unroll
            for (int kh = 0; kh < 3; kh++) {
                u64t inp2[4];
                float inS[4];
#pragma unroll
                for (int bl = 0; bl < 4; bl++) {
                    int base = bl * 1080 + ci * 270 + (2 * oh + kh) * 18 + 2 * ow; // even
                    inp2[bl] = *(const u64t*)(s_in + base);
                    inS[bl] = s_in[base + 2];
                }
#pragma unroll
                for (int co = 0; co < 8; co++) {
                    int wo = (yq * 8 + co) * 48 + ci * 12 + kh * 4;
                    u64t wq = *(const u64t*)(s_w + wo);
                    float w2 = s_w[wo + 2];
#pragma unroll
                    for (int bl = 0; bl < 4; bl++) {
                        acc2[bl][co] = ffma2(wq, inp2[bl], acc2[bl][co]);
                        accS[bl][co] = fmaf(w2, inS[bl], accS[bl][co]);
                    }
                }
            }
        }
        __syncthreads();
    }
#pragma unroll
    for (int bl = 0; bl < 4; bl++)
#pragma unroll
        for (int co = 0; co < 8; co++)
            g_rc1[((b0 + bl) * 256 + cog * 32 + yq * 8 + co) * 49 + px] =
                f2sum(acc2[bl][co]) + accS[bl][co];
}

// ---------------------------------------------------------------------------
// resconv2: 256->256 3x3 s1, 7x7, bn+relu fused into staging.
// ---------------------------------------------------------------------------
__global__ void __launch_bounds__(196) k_resconv2(const float* __restrict__ w) {
    __shared__ __align__(16) float s_in[4 * 4 * 108];   // [bl][ci][9x12]
    __shared__ __align__(16) float s_w[32 * 4 * 3 * 4];
    int bq = blockIdx.y, cog = blockIdx.x;
    int b0 = bq * 4;
    int tid = threadIdx.x;
    int px = tid % 49, yq = tid / 49;
    int oh = px / 7, ow = px - oh * 7;
    u64t acc2[4][8];
    float accS[4][8];
#pragma unroll
    for (int bl = 0; bl < 4; bl++)
#pragma unroll
        for (int co = 0; co < 8; co++) { acc2[bl][co] = 0ull; accS[bl][co] = 0.f; }

#pragma unroll 1
    for (int c0 = 0; c0 < 256; c0 += 4) {
        for (int t = tid; t < 4 * 4 * 108; t += 196) {
            int bl = t / 432, rem = t - bl * 432;
            int ci = rem / 108, pos = rem - ci * 108;
            int r = pos / 12, c = pos - r * 12;
            int ih = r - 1, iw = c - 1;
            float v = 0.f;
            if ((unsigned)ih < 7u && (unsigned)iw < 7u) {
                float sc = g_scr1[c0 + ci], sh = g_shr1[c0 + ci];
                v = fmaxf(g_rc1[((b0 + bl) * 256 + c0 + ci) * 49 + ih * 7 + iw] * sc + sh, 0.f);
            }
            s_in[t] = v;
        }
        for (int t = tid; t < 32 * 36; t += 196) {
            int co = t / 36, rem = t - co * 36;
            int ci = rem / 9, k = rem - ci * 9;
            int kh = k / 3, kw = k - kh * 3;
            s_w[co * 48 + ci * 12 + kh * 4 + kw] =
                w[(cog * 32 + co) * 2304 + (c0 + ci) * 9 + k];
        }
        __syncthreads();
#pragma unroll 1
        for (int ci = 0; ci < 4; ci++) {
#pragma unroll
            for (int kh = 0; kh < 3; kh++) {
                u64t inp2[4];
                float inS[4];
#pragma unroll
                for (int bl = 0; bl < 4; bl++) {
                    int base = bl * 432 + ci * 108 + (oh + kh) * 12 + ow;  // parity varies
                    inp2[bl] = packf2(s_in[base], s_in[base + 1]);
                    inS[bl] = s_in[base + 2];
                }
#pragma unroll
                for (int co = 0; co < 8; co++) {
                    int wo = (yq * 8 + co) * 48 + ci * 12 + kh * 4;
                    u64t wq = *(const u64t*)(s_w + wo);
                    float w2 = s_w[wo + 2];
#pragma unroll
                    for (int bl = 0; bl < 4; bl++) {
                        acc2[bl][co] = ffma2(wq, inp2[bl], acc2[bl][co]);
                        accS[bl][co] = fmaf(w2, inS[bl], accS[bl][co]);
                    }
                }
            }
        }
        __syncthreads();
    }
#pragma unroll
    for (int bl = 0; bl < 4; bl++)
#pragma unroll
        for (int co = 0; co < 8; co++)
            g_rc2[((b0 + bl) * 256 + cog * 32 + yq * 8 + co) * 49 + px] =
                f2sum(acc2[bl][co]) + accS[bl][co];
}

// ---------------------------------------------------------------------------
// shortcut 1x1 s2: smem-staged, ci-paired FFMA2. grid (8 cog, 64 b), block 196.
// ---------------------------------------------------------------------------
__global__ void __launch_bounds__(196) k_shortcut(const float* __restrict__ w) {
    __shared__ __align__(16) float s_c[128 * 49];   // [ci][px] center samples
    __shared__ __align__(16) float s_wv[32 * 128];  // [co][ci]
    int b = blockIdx.y, cog = blockIdx.x;
    int tid = threadIdx.x;
    int px = tid % 49, yq = tid / 49;

    for (int t = tid; t < 128 * 49; t += 196) {
        int ci = t / 49, p = t - ci * 49;
        int oh = p / 7, ow = p - oh * 7;
        s_c[t] = g_pool2[(b * 128 + ci) * 196 + oh * 28 + ow * 2];
    }
    for (int t = tid; t < 32 * 128; t += 196) {
        int co = t >> 7, ci = t & 127;
        s_wv[t] = w[(cog * 32 + co) * 128 + ci];
    }
    __syncthreads();

    u64t acc2[8];
#pragma unroll
    for (int co = 0; co < 8; co++) acc2[co] = 0ull;
#pragma unroll 1
    for (int cp = 0; cp < 64; cp++) {
        u64t in2 = packf2(s_c[(2 * cp) * 49 + px], s_c[(2 * cp + 1) * 49 + px]);
#pragma unroll
        for (int co = 0; co < 8; co++) {
            u64t w2 = *(const u64t*)(s_wv + (yq * 8 + co) * 128 + 2 * cp);
            acc2[co] = ffma2(w2, in2, acc2[co]);
        }
    }
#pragma unroll
    for (int co = 0; co < 8; co++)
        g_rs[(b * 256 + cog * 32 + yq * 8 + co) * 49 + px] = f2sum(acc2[co]);
}

// ---------------------------------------------------------------------------
// tail: y = mean relu(bn(rc2)+bn(rs)); out = y M^T + b2  (merged)
// ---------------------------------------------------------------------------
__global__ void k_tail(float* __restrict__ out) {
    __shared__ float s_y[256];
    int b = blockIdx.x, c = threadIdx.x;
    float sc2 = g_scr2[c], sh2 = g_shr2[c], scs = g_scs[c], shs = g_shs[c];
    const float* p2 = g_rc2 + (b * 256 + c) * 49;
    const float* ps = g_rs + (b * 256 + c) * 49;
    float s = 0.f;
    for (int p = 0; p < 49; p++) {
        float v = p2[p] * sc2 + sh2 + ps[p] * scs + shs;
        s += fmaxf(v, 0.f);
    }
    s_y[c] = s * (1.f / 49.f);
    __syncthreads();
    if (c < 50) {
        float acc = g_b2[c];
        for (int k = 0; k < 256; k++) acc += s_y[k] * g_M[c * 256 + k];
        out[b * 50 + c] = acc;
    }
}

// ---------------------------------------------------------------------------
// Tail fold (softmax attention collapses to 1x1 conv: wo@wv)
// ---------------------------------------------------------------------------
__global__ void k_foldT(const float* __restrict__ fcw, const float* __restrict__ wo) {
    int idx = blockIdx.x * 256 + threadIdx.x;
    if (idx >= 50 * 1024) return;
    int i = idx / 1024, j = idx - i * 1024;
    float s = 0.f;
    for (int c = 0; c < 256; c++) s += fcw[i * 256 + c] * wo[c * 1024 + j];
    g_T[idx] = s;
}

__global__ void k_foldM(const float* __restrict__ wv) {
    int idx = blockIdx.x * 256 + threadIdx.x;
    if (idx >= 50 * 256) return;
    int i = idx / 256, c = idx - i * 256;
    float s = 0.f;
    for (int j = 0; j < 1024; j++) s += g_T[i * 1024 + j] * wv[j * 256 + c];
    g_M[idx] = s;
}

__global__ void k_foldb(const float* __restrict__ fcw, const float* __restrict__ bo,
                        const float* __restrict__ fcb) {
    int i = threadIdx.x;
    if (i >= 50) return;
    float s = 0.f;
    for (int c = 0; c < 256; c++) s += fcw[i * 256 + c] * bo[c];
    g_b2[i] = s + fcb[i];
}

// ---------------------------------------------------------------------------
// Launch (k_conv1 is the 4th launch -> ncu profile target)
// ---------------------------------------------------------------------------
extern "C" void kernel_launch(void* const* d_in, const int* in_sizes, int n_in,
                              void* d_out, int out_size) {
    const float* imgs   = (const float*)d_in[0];
    const float* a1f1   = (const float*)d_in[1];
    const float* a1f2   = (const float*)d_in[2];
    const float* a1f2b  = (const float*)d_in[3];
    const float* dy1    = (const float*)d_in[4];
    const float* bn1g   = (const float*)d_in[5];
    const float* bn1b   = (const float*)d_in[6];
    const float* a2f1   = (const float*)d_in[7];
    const float* a2f2   = (const float*)d_in[8];
    const float* a2f2b  = (const float*)d_in[9];
    const float* dy2    = (const float*)d_in[10];
    const float* bn2g   = (const float*)d_in[11];
    const float* bn2b   = (const float*)d_in[12];
    const float* rc1w   = (const float*)d_in[13];
    const float* rbn1g  = (const float*)d_in[14];
    const float* rbn1b  = (const float*)d_in[15];
    const float* rc2w   = (const float*)d_in[16];
    const float* rbn2g  = (const float*)d_in[17];
    const float* rbn2b  = (const float*)d_in[18];
    const float* rsw    = (const float*)d_in[19];
    const float* rbnsg  = (const float*)d_in[20];
    const float* rbnsb  = (const float*)d_in[21];
    const float* wv     = (const float*)d_in[24];
    const float* wo     = (const float*)d_in[25];
    const float* bo     = (const float*)d_in[26];
    const float* fcw    = (const float*)d_in[27];
    const float* fcb    = (const float*)d_in[28];
    float* out = (float*)d_out;
    (void)in_sizes; (void)n_in; (void)out_size;

    // stage 1 front (block 0 of pooled1 zeroes accumulators)
    k_pooled1<<<192, 256>>>(imgs);
    k_attn1<<<1, 64>>>(a1f1, a1f2, a1f2b);
    k_w1agg<<<(BB * 9408 + 255) / 256, 256>>>(dy1);
    k_conv1<<<dim3(28, 8, BB), 128>>>(imgs);   // <- 4th launch (profiled)

    // tail fold (independent)
    k_foldT<<<200, 256>>>(fcw, wo);
    k_foldM<<<50, 256>>>(wv);
    k_foldb<<<1, 64>>>(fcw, bo, fcb);

    k_bnscale<<<1, 64>>>(bn1g, bn1b, 802816.f, 0, 64);
    k_bnpool1<<<dim3(13, 64, BB), 256>>>();

    // stage 2
    k_attn2<<<1, 64>>>(a2f1, a2f2, a2f2b);
    k_w2agg<<<(BB * 73728 + 255) / 256, 256>>>(dy2);
    k_conv2<<<dim3(16, BB), 224>>>();
    k_bnscale<<<1, 128>>>(bn2g, bn2b, 50176.f, 1, 128);
    k_bnpool2<<<dim3(128, BB), 196>>>();

    // residual block
    k_resconv1<<<dim3(8, BB / 4), 196>>>(rc1w);
    k_shortcut<<<dim3(8, BB), 196>>>(rsw);
    k_chstats<<<256, 128>>>(0);
    k_bnscale<<<1, 256>>>(rbn1g, rbn1b, 3136.f, 2, 256);
    k_resconv2<<<dim3(8, BB / 4), 196>>>(rc2w);
    k_chstats2<<<256, 128>>>();
    k_bnscale<<<1, 256>>>(rbn2g, rbn2b, 3136.f, 3, 256);
    k_bnscale<<<1, 256>>>(rbnsg, rbnsb, 3136.f, 4, 256);

    k_tail<<<64, 256>>>(out);
}

// round 6
// speedup vs baseline: 1.9422x; 1.9422x over previous
#include <cuda_runtime.h>
#include <math.h>

#define BB 64

// ---------------------------------------------------------------------------
// Scratch
// ---------------------------------------------------------------------------
__device__ float g_pooled1[BB * 3];
__device__ float g_attn1[BB * 8];
__device__ float g_w1[BB * 64 * 3 * 49];
__device__ float g_conv1[BB * 64 * 112 * 112];
__device__ float g_pool1[BB * 64 * 56 * 56];
__device__ float g_pooled2[BB * 64];
__device__ float g_attn2[BB * 8];
__device__ float g_w2[BB * 128 * 64 * 9];
__device__ float g_conv2[BB * 128 * 28 * 28];
__device__ float g_pool2[BB * 128 * 14 * 14];
__device__ float g_rc1[BB * 256 * 49];
__device__ float g_rc2[BB * 256 * 49];
__device__ float g_rs[BB * 256 * 49];

__device__ float g_sum1[64],  g_sq1[64],  g_sc1[64],  g_sh1[64];
__device__ float g_sum2[128], g_sq2[128], g_sc2[128], g_sh2[128];
__device__ float g_sumr1[256], g_sqr1[256], g_scr1[256], g_shr1[256];
__device__ float g_sumr2[256], g_sqr2[256], g_scr2[256], g_shr2[256];
__device__ float g_sums[256],  g_sqs[256],  g_scs[256],  g_shs[256];

__device__ float g_T[50 * 1024];
__device__ float g_M[50 * 256];
__device__ float g_b2[50];

// ---------------------------------------------------------------------------
// bn scale/shift
// ---------------------------------------------------------------------------
__global__ void k_bnscale(const float* __restrict__ g, const float* __restrict__ be,
                          float cnt, int stage, int C) {
    int c = blockIdx.x * blockDim.x + threadIdx.x;
    if (c >= C) return;
    float *su, *sq, *sc, *sh;
    switch (stage) {
        case 0:  su = g_sum1;  sq = g_sq1;  sc = g_sc1;  sh = g_sh1;  break;
        case 1:  su = g_sum2;  sq = g_sq2;  sc = g_sc2;  sh = g_sh2;  break;
        case 2:  su = g_sumr1; sq = g_sqr1; sc = g_scr1; sh = g_shr1; break;
        case 3:  su = g_sumr2; sq = g_sqr2; sc = g_scr2; sh = g_shr2; break;
        default: su = g_sums;  sq = g_sqs;  sc = g_scs;  sh = g_shs;  break;
    }
    float m = su[c] / cnt;
    float v = sq[c] / cnt - m * m;
    float s = g[c] * rsqrtf(v + 1e-5f);
    sc[c] = s;
    sh[c] = be[c] - m * s;
}

// per-channel stats of rc1
__global__ void k_chstats(int which) {
    const float* src = which ? g_rc2 : g_rc1;
    float* su = which ? g_sumr2 : g_sumr1;
    float* sq = which ? g_sqr2 : g_sqr1;
    int c = blockIdx.x;
    float s = 0.f, q = 0.f;
    for (int t = threadIdx.x; t < BB * 49; t += 128) {
        int b = t / 49, p = t - b * 49;
        float v = src[(b * 256 + c) * 49 + p];
        s += v; q += v * v;
    }
    for (int o = 16; o; o >>= 1) {
        s += __shfl_down_sync(0xffffffffu, s, o);
        q += __shfl_down_sync(0xffffffffu, q, o);
    }
    __shared__ float rs[4], rq[4];
    int w = threadIdx.x >> 5;
    if ((threadIdx.x & 31) == 0) { rs[w] = s; rq[w] = q; }
    __syncthreads();
    if (threadIdx.x == 0) {
        su[c] = rs[0] + rs[1] + rs[2] + rs[3];
        sq[c] = rq[0] + rq[1] + rq[2] + rq[3];
    }
}

// stats of rc2 AND rs in one launch
__global__ void k_chstats2() {
    int c = blockIdx.x;
    float s2 = 0.f, q2 = 0.f, ss = 0.f, qs = 0.f;
    for (int t = threadIdx.x; t < BB * 49; t += 128) {
        int b = t / 49, p = t - b * 49;
        float v = g_rc2[(b * 256 + c) * 49 + p];
        s2 += v; q2 += v * v;
        float u = g_rs[(b * 256 + c) * 49 + p];
        ss += u; qs += u * u;
    }
    for (int o = 16; o; o >>= 1) {
        s2 += __shfl_down_sync(0xffffffffu, s2, o);
        q2 += __shfl_down_sync(0xffffffffu, q2, o);
        ss += __shfl_down_sync(0xffffffffu, ss, o);
        qs += __shfl_down_sync(0xffffffffu, qs, o);
    }
    __shared__ float r[4][4];
    int w = threadIdx.x >> 5;
    if ((threadIdx.x & 31) == 0) { r[w][0] = s2; r[w][1] = q2; r[w][2] = ss; r[w][3] = qs; }
    __syncthreads();
    if (threadIdx.x == 0) {
        g_sumr2[c] = r[0][0] + r[1][0] + r[2][0] + r[3][0];
        g_sqr2[c]  = r[0][1] + r[1][1] + r[2][1] + r[3][1];
        g_sums[c]  = r[0][2] + r[1][2] + r[2][2] + r[3][2];
        g_sqs[c]   = r[0][3] + r[1][3] + r[2][3] + r[3][3];
    }
}

// ---------------------------------------------------------------------------
// Stage-1 attention
// ---------------------------------------------------------------------------
__global__ void k_pooled1(const float* __restrict__ imgs) {
    int bc = blockIdx.x;
    int tid = threadIdx.x;
    if (bc == 0) {
        for (int i = tid; i < BB * 64; i += 256) g_pooled2[i] = 0.f;
        if (tid < 64)  { g_sum1[tid] = 0.f; g_sq1[tid] = 0.f; }
        if (tid < 128) { g_sum2[tid] = 0.f; g_sq2[tid] = 0.f; }
    }
    const float* p = imgs + (long)bc * 50176;
    float s = 0.f;
    for (int i = tid; i < 50176; i += 256) s += p[i];
    __shared__ float red[256];
    red[tid] = s; __syncthreads();
    for (int o = 128; o; o >>= 1) { if (tid < o) red[tid] += red[tid + o]; __syncthreads(); }
    if (tid == 0) g_pooled1[bc] = red[0] * (1.f / 50176.f);
}

__global__ void k_attn1(const float* __restrict__ fc1, const float* __restrict__ fc2,
                        const float* __restrict__ fc2b) {
    int b = threadIdx.x;
    if (b >= BB) return;
    float p[3];
    for (int c = 0; c < 3; c++) p[c] = g_pooled1[b * 3 + c];
    float h[8];
    for (int j = 0; j < 8; j++) {
        float s = 0.f;
        for (int c = 0; c < 3; c++) s += p[c] * fc1[j * 3 + c];
        h[j] = fmaxf(s, 0.f);
    }
    float lg[8], mx = -1e30f;
    for (int k = 0; k < 8; k++) {
        float s = fc2b[k];
        for (int j = 0; j < 8; j++) s += h[j] * fc2[k * 8 + j];
        lg[k] = s; mx = fmaxf(mx, s);
    }
    float den = 0.f;
    for (int k = 0; k < 8; k++) { lg[k] = expf(lg[k] - mx); den += lg[k]; }
    float inv = 1.f / den;
    for (int k = 0; k < 8; k++) g_attn1[b * 8 + k] = lg[k] * inv;
}

__global__ void k_w1agg(const float* __restrict__ dy1) {
    int idx = blockIdx.x * 256 + threadIdx.x;
    if (idx >= BB * 9408) return;
    int b = idx / 9408, i = idx - b * 9408;
    float s = 0.f;
#pragma unroll
    for (int k = 0; k < 8; k++) s += g_attn1[b * 8 + k] * dy1[k * 9408 + i];
    g_w1[idx] = s;
}

// ---------------------------------------------------------------------------
// Conv1: 3->64, 7x7 s2 p3. Scalar FFMA, register-hoisted (R4 proven form).
// ---------------------------------------------------------------------------
__global__ void __launch_bounds__(128) k_conv1(const float* __restrict__ imgs) {
    __shared__ __align__(16) float s_in[3 * 37 * 62];
    __shared__ __align__(16) float s_w[8 * 3 * 7 * 8];
    __shared__ float s_stat[16];
    int b = blockIdx.z, cog = blockIdx.y;
    int tr = blockIdx.x >> 2, tc = blockIdx.x & 3;
    int oh0 = tr * 16, ow0 = tc * 28;
    int tid = threadIdx.x;

    for (int t = tid; t < 8 * 147; t += 128) {
        int co = t / 147, rem = t - co * 147;
        int ci = rem / 49, rem2 = rem - ci * 49;
        int kh = rem2 / 7, kw = rem2 - kh * 7;
        s_w[((co * 3 + ci) * 7 + kh) * 8 + kw] = g_w1[b * 9408 + (cog * 8 + co) * 147 + rem];
    }
    int ih0 = 2 * oh0 - 3, iw0 = 2 * ow0 - 3;
    for (int t = tid; t < 6882; t += 128) {
        int ci = t / 2294, rem = t - ci * 2294;
        int r = rem / 62, c = rem - r * 62;
        int ih = ih0 + r, iw = iw0 + c;
        float v = 0.f;
        if ((unsigned)ih < 224u && (unsigned)iw < 224u)
            v = imgs[((b * 3 + ci) * 224 + ih) * 224 + iw];
        s_in[t] = v;
    }
    if (tid < 16) s_stat[tid] = 0.f;
    __syncthreads();

    float acc[4][8];
#pragma unroll
    for (int j = 0; j < 4; j++)
#pragma unroll
        for (int co = 0; co < 8; co++) acc[j][co] = 0.f;

    int tx = tid % 28, ty = tid / 28;
    if (tid < 112) {
#pragma unroll 1
        for (int ci = 0; ci < 3; ci++) {
#pragma unroll 1
            for (int kh = 0; kh < 7; kh++) {
                int rbase = ci * 2294 + (8 * ty + kh) * 62 + 2 * tx;
                float in[4][8];
#pragma unroll
                for (int j = 0; j < 4; j++) {
                    const float2* rp = (const float2*)(s_in + rbase + 124 * j);
#pragma unroll
                    for (int p = 0; p < 4; p++) {
                        float2 v = rp[p];
                        in[j][2 * p] = v.x; in[j][2 * p + 1] = v.y;
                    }
                }
#pragma unroll
                for (int co = 0; co < 8; co++) {
                    const float4* wp = (const float4*)(s_w + ((co * 3 + ci) * 7 + kh) * 8);
                    float4 wa = wp[0], wb = wp[1];
                    float w[7] = {wa.x, wa.y, wa.z, wa.w, wb.x, wb.y, wb.z};
#pragma unroll
                    for (int j = 0; j < 4; j++)
#pragma unroll
                        for (int kw = 0; kw < 7; kw++)
                            acc[j][co] += w[kw] * in[j][kw];
                }
            }
        }
#pragma unroll
        for (int co = 0; co < 8; co++) {
            long cb = ((long)(b * 64 + cog * 8 + co)) * 12544;
#pragma unroll
            for (int j = 0; j < 4; j++) {
                int oh = oh0 + 4 * ty + j;
                g_conv1[cb + oh * 112 + ow0 + tx] = acc[j][co];
            }
        }
    }
#pragma unroll
    for (int co = 0; co < 8; co++) {
        float s = acc[0][co] + acc[1][co] + acc[2][co] + acc[3][co];
        float q = acc[0][co] * acc[0][co] + acc[1][co] * acc[1][co]
                + acc[2][co] * acc[2][co] + acc[3][co] * acc[3][co];
        for (int o = 16; o; o >>= 1) {
            s += __shfl_down_sync(0xffffffffu, s, o);
            q += __shfl_down_sync(0xffffffffu, q, o);
        }
        if ((tid & 31) == 0) { atomicAdd(&s_stat[co], s); atomicAdd(&s_stat[8 + co], q); }
    }
    __syncthreads();
    if (tid < 8) {
        atomicAdd(&g_sum1[cog * 8 + tid], s_stat[tid]);
        atomicAdd(&g_sq1[cog * 8 + tid], s_stat[8 + tid]);
    }
}

// ---------------------------------------------------------------------------
// BN1 + maxpool3 s2 p1: 112->56, accumulate pooled2
// ---------------------------------------------------------------------------
__global__ void k_bnpool1() {
    int b = blockIdx.z, c = blockIdx.y;
    int p = blockIdx.x * 256 + threadIdx.x;
    float outv = 0.f;
    bool valid = (p < 3136);
    if (valid) {
        int oh = p / 56, ow = p - oh * 56;
        float sc = g_sc1[c], sh = g_sh1[c];
        const float* ip = g_conv1 + (long)(b * 64 + c) * 12544;
        float m = -1e30f;
#pragma unroll
        for (int r = 0; r < 3; r++) {
            int ih = 2 * oh - 1 + r;
            if ((unsigned)ih >= 112u) continue;
#pragma unroll
            for (int cc = 0; cc < 3; cc++) {
                int iw = 2 * ow - 1 + cc;
                if ((unsigned)iw >= 112u) continue;
                m = fmaxf(m, ip[ih * 112 + iw] * sc + sh);
            }
        }
        g_pool1[(b * 64 + c) * 3136 + p] = m;
        outv = m;
    }
    float s = valid ? outv : 0.f;
    for (int o = 16; o; o >>= 1) s += __shfl_down_sync(0xffffffffu, s, o);
    __shared__ float s_red;
    if (threadIdx.x == 0) s_red = 0.f;
    __syncthreads();
    if ((threadIdx.x & 31) == 0) atomicAdd(&s_red, s);
    __syncthreads();
    if (threadIdx.x == 0) atomicAdd(&g_pooled2[b * 64 + c], s_red);
}

// ---------------------------------------------------------------------------
// Stage-2 attention
// ---------------------------------------------------------------------------
__global__ void k_attn2(const float* __restrict__ fc1, const float* __restrict__ fc2,
                        const float* __restrict__ fc2b) {
    int b = threadIdx.x;
    if (b >= BB) return;
    float h[17];
    for (int j = 0; j < 17; j++) {
        float s = 0.f;
        for (int c = 0; c < 64; c++)
            s += (g_pooled2[b * 64 + c] * (1.f / 3136.f)) * fc1[j * 64 + c];
        h[j] = fmaxf(s, 0.f);
    }
    float lg[8], mx = -1e30f;
    for (int k = 0; k < 8; k++) {
        float s = fc2b[k];
        for (int j = 0; j < 17; j++) s += h[j] * fc2[k * 17 + j];
        lg[k] = s; mx = fmaxf(mx, s);
    }
    float den = 0.f;
    for (int k = 0; k < 8; k++) { lg[k] = expf(lg[k] - mx); den += lg[k]; }
    float inv = 1.f / den;
    for (int k = 0; k < 8; k++) g_attn2[b * 8 + k] = lg[k] * inv;
}

__global__ void k_w2agg(const float* __restrict__ dy2) {
    int idx = blockIdx.x * 256 + threadIdx.x;
    if (idx >= BB * 73728) return;
    int b = idx / 73728, i = idx - b * 73728;
    float s = 0.f;
#pragma unroll
    for (int k = 0; k < 8; k++) s += g_attn2[b * 8 + k] * dy2[k * 73728 + i];
    g_w2[idx] = s;
}

// ---------------------------------------------------------------------------
// Conv2: 64->128, 3x3 s2 p1: 56->28. 16 co/block, register double-buffer
// pipeline (LDG of next ci-chunk overlaps compute). grid (8 cog, 64 b), 224 thr.
// ---------------------------------------------------------------------------
__global__ void __launch_bounds__(224) k_conv2() {
    __shared__ __align__(16) float s_in[2 * 3364];       // 2 x 58x58 padded
    __shared__ __align__(16) float s_w[16 * 2 * 3 * 4];  // [co][ci][kh][4], slot3=0
    __shared__ float s_stat[32];
    int b = blockIdx.y, cog = blockIdx.x;
    int tid = threadIdx.x;
    int tx = tid % 28, tyq = tid / 28;

    for (int t = tid; t < 2 * 3364; t += 224) s_in[t] = 0.f;
    for (int t = tid; t < 384; t += 224) s_w[t] = 0.f;
    if (tid < 32) s_stat[tid] = 0.f;

    // precompute smem store indices for input staging
    int sidx[28];
#pragma unroll
    for (int k = 0; k < 28; k++) {
        int t = tid + 224 * k;
        int ci = t / 3136, p = t - ci * 3136;
        int r = p / 56, c = p - r * 56;
        sidx[k] = ci * 3364 + (r + 1) * 58 + (c + 1);
    }
    // weight staging indices (288 values, <=2 per thread)
    int w_ld0, w_st0, w_ld1, w_st1;
    {
        int t = tid;
        int co = t / 18, rem = t - co * 18, ci = rem / 9, k9 = rem - ci * 9;
        int kh = k9 / 3, kw = k9 - kh * 3;
        w_ld0 = (cog * 16 + co) * 576 + ci * 9 + k9;
        w_st0 = co * 24 + ci * 12 + kh * 4 + kw;
        t = tid + 224;
        co = t / 18; rem = t - co * 18; ci = rem / 9; k9 = rem - ci * 9;
        kh = k9 / 3; kw = k9 - kh * 3;
        w_ld1 = (cog * 16 + co) * 576 + ci * 9 + k9;
        w_st1 = co * 24 + ci * 12 + kh * 4 + kw;
    }
    __syncthreads();

    const float* base = g_pool1 + (long)(b * 64) * 3136;
    const float* wbase = g_w2 + b * 73728;
    float r_in[28], r_w0, r_w1 = 0.f;
#pragma unroll
    for (int k = 0; k < 28; k++) r_in[k] = base[tid + 224 * k];
    r_w0 = wbase[w_ld0];
    if (tid < 64) r_w1 = wbase[w_ld1];

    float acc[4][16];
#pragma unroll
    for (int j = 0; j < 4; j++)
#pragma unroll
        for (int co = 0; co < 16; co++) acc[j][co] = 0.f;

#pragma unroll 1
    for (int c0 = 0; c0 < 64; c0 += 2) {
#pragma unroll
        for (int k = 0; k < 28; k++) s_in[sidx[k]] = r_in[k];
        s_w[w_st0] = r_w0;
        if (tid < 64) s_w[w_st1] = r_w1;
        __syncthreads();
        if (c0 + 2 < 64) {
            const float* src = base + (c0 + 2) * 3136;
#pragma unroll
            for (int k = 0; k < 28; k++) r_in[k] = src[tid + 224 * k];
            r_w0 = wbase[w_ld0 + (c0 + 2) * 9];
            if (tid < 64) r_w1 = wbase[w_ld1 + (c0 + 2) * 9];
        }
        if (tid < 196) {
#pragma unroll
            for (int ci = 0; ci < 2; ci++) {
#pragma unroll
                for (int kh = 0; kh < 3; kh++) {
                    int rbase = ci * 3364 + (8 * tyq + kh) * 58 + 2 * tx;  // even
                    float in[4][4];
#pragma unroll
                    for (int j = 0; j < 4; j++) {
                        const float2* rp = (const float2*)(s_in + rbase + 116 * j);
                        float2 v0 = rp[0], v1 = rp[1];
                        in[j][0] = v0.x; in[j][1] = v0.y; in[j][2] = v1.x; in[j][3] = v1.y;
                    }
#pragma unroll
                    for (int co = 0; co < 16; co++) {
                        const float4* wp = (const float4*)(s_w + co * 24 + ci * 12 + kh * 4);
                        float4 w = wp[0];
#pragma unroll
                        for (int j = 0; j < 4; j++) {
                            acc[j][co] += w.x * in[j][0];
                            acc[j][co] += w.y * in[j][1];
                            acc[j][co] += w.z * in[j][2];
                        }
                    }
                }
            }
        }
        __syncthreads();
    }

    if (tid < 196) {
#pragma unroll
        for (int co = 0; co < 16; co++) {
            int cb = (b * 128 + cog * 16 + co) * 784;
#pragma unroll
            for (int j = 0; j < 4; j++) {
                int oh = 4 * tyq + j;
                g_conv2[cb + oh * 28 + tx] = acc[j][co];
            }
        }
    }
#pragma unroll
    for (int co = 0; co < 16; co++) {
        float s = acc[0][co] + acc[1][co] + acc[2][co] + acc[3][co];
        float q = acc[0][co] * acc[0][co] + acc[1][co] * acc[1][co]
                + acc[2][co] * acc[2][co] + acc[3][co] * acc[3][co];
        for (int o = 16; o; o >>= 1) {
            s += __shfl_down_sync(0xffffffffu, s, o);
            q += __shfl_down_sync(0xffffffffu, q, o);
        }
        if ((tid & 31) == 0) { atomicAdd(&s_stat[co], s); atomicAdd(&s_stat[16 + co], q); }
    }
    __syncthreads();
    if (tid < 16) {
        atomicAdd(&g_sum2[cog * 16 + tid], s_stat[tid]);
        atomicAdd(&g_sq2[cog * 16 + tid], s_stat[16 + tid]);
    }
}

// ---------------------------------------------------------------------------
// BN2 + maxpool3 s2 p1: 28->14
// ---------------------------------------------------------------------------
__global__ void k_bnpool2() {
    int b = blockIdx.y, c = blockIdx.x;
    int p = threadIdx.x;
    if (p >= 196) return;
    int oh = p / 14, ow = p - oh * 14;
    float sc = g_sc2[c], sh = g_sh2[c];
    const float* ip = g_conv2 + (b * 128 + c) * 784;
    float m = -1e30f;
#pragma unroll
    for (int r = 0; r < 3; r++) {
        int ih = 2 * oh - 1 + r;
        if ((unsigned)ih >= 28u) continue;
#pragma unroll
        for (int cc = 0; cc < 3; cc++) {
            int iw = 2 * ow - 1 + cc;
            if ((unsigned)iw >= 28u) continue;
            m = fmaxf(m, ip[ih * 28 + iw] * sc + sh);
        }
    }
    g_pool2[(b * 128 + c) * 196 + p] = m;
}

// ---------------------------------------------------------------------------
// resconv1: 128->256 3x3 s2, 14->7. 4 batches/block, pipelined staging.
// grid (8 cog, 16 bq), block 196.
// ---------------------------------------------------------------------------
__global__ void __launch_bounds__(196) k_resconv1(const float* __restrict__ w) {
    __shared__ __align__(16) float s_in[4 * 1080];      // [bl][ci][15x18]
    __shared__ __align__(16) float s_w[32 * 48];        // [co][ci][kh][4]
    int bq = blockIdx.y, cog = blockIdx.x;
    int b0 = bq * 4;
    int tid = threadIdx.x;
    int px = tid % 49, yq = tid / 49;
    int oh = px / 7, ow = px - oh * 7;

    for (int t = tid; t < 4320; t += 196) s_in[t] = 0.f;
    for (int t = tid; t < 1536; t += 196) s_w[t] = 0.f;

    int ld[16], sidx[16];
#pragma unroll
    for (int k = 0; k < 16; k++) {
        int t = tid + 196 * k;               // < 3136
        int bl = t / 784, rem = t - bl * 784;
        int ci = rem / 196, p = rem - ci * 196;
        int r = p / 14, c = p - r * 14;
        ld[k] = bl * 25088 + rem;
        sidx[k] = bl * 1080 + ci * 270 + (r + 1) * 18 + (c + 1);
    }
    int wld[6], wst[6];
#pragma unroll
    for (int k = 0; k < 6; k++) {
        int t = tid + 196 * k;
        if (t < 1152) {
            int co = t / 36, rem = t - co * 36;
            int ci = rem / 9, k9 = rem - ci * 9;
            int kh = k9 / 3, kw = k9 - kh * 3;
            wld[k] = (cog * 32 + co) * 1152 + ci * 9 + k9;
            wst[k] = co * 48 + ci * 12 + kh * 4 + kw;
        } else { wld[k] = -1; wst[k] = 1537 - 1; }
    }
    __syncthreads();

    const float* base = g_pool2 + (long)(b0 * 128) * 196;
    float r_in[16], r_w[6];
#pragma unroll
    for (int k = 0; k < 16; k++) r_in[k] = base[ld[k]];
#pragma unroll
    for (int k = 0; k < 6; k++) r_w[k] = (wld[k] >= 0) ? w[wld[k]] : 0.f;

    float acc[4][8];
#pragma unroll
    for (int bl = 0; bl < 4; bl++)
#pragma unroll
        for (int co = 0; co < 8; co++) acc[bl][co] = 0.f;

#pragma unroll 1
    for (int c0 = 0; c0 < 128; c0 += 4) {
#pragma unroll
        for (int k = 0; k < 16; k++) s_in[sidx[k]] = r_in[k];
#pragma unroll
        for (int k = 0; k < 6; k++) if (wld[k] >= 0) s_w[wst[k]] = r_w[k];
        __syncthreads();
        if (c0 + 4 < 128) {
            const float* src = base + (c0 + 4) * 196;
#pragma unroll
            for (int k = 0; k < 16; k++) r_in[k] = src[ld[k]];
#pragma unroll
            for (int k = 0; k < 6; k++)
                if (wld[k] >= 0) r_w[k] = w[wld[k] + (c0 + 4) * 9];
        }
#pragma unroll
        for (int ci = 0; ci < 4; ci++) {
#pragma unroll
            for (int kh = 0; kh < 3; kh++) {
                float in[4][3];
#pragma unroll
                for (int bl = 0; bl < 4; bl++) {
                    int bs = bl * 1080 + ci * 270 + (2 * oh + kh) * 18 + 2 * ow;
                    in[bl][0] = s_in[bs];
                    in[bl][1] = s_in[bs + 1];
                    in[bl][2] = s_in[bs + 2];
                }
#pragma unroll
                for (int co = 0; co < 8; co++) {
                    const float4* wp = (const float4*)(s_w + (yq * 8 + co) * 48 + ci * 12 + kh * 4);
                    float4 wv = wp[0];
#pragma unroll
                    for (int bl = 0; bl < 4; bl++) {
                        acc[bl][co] += wv.x * in[bl][0];
                        acc[bl][co] += wv.y * in[bl][1];
                        acc[bl][co] += wv.z * in[bl][2];
                    }
                }
            }
        }
        __syncthreads();
    }
#pragma unroll
    for (int bl = 0; bl < 4; bl++)
#pragma unroll
        for (int co = 0; co < 8; co++)
            g_rc1[((b0 + bl) * 256 + cog * 32 + yq * 8 + co) * 49 + px] = acc[bl][co];
}

// ---------------------------------------------------------------------------
// resconv2: 256->256 3x3 s1, 7x7. bn+relu applied at register-load time.
// grid (8 cog, 16 bq), block 196, pipelined.
// ---------------------------------------------------------------------------
__global__ void __launch_bounds__(196) k_resconv2(const float* __restrict__ w) {
    __shared__ __align__(16) float s_in[4 * 432];       // [bl][ci][9x12]
    __shared__ __align__(16) float s_w[32 * 48];
    int bq = blockIdx.y, cog = blockIdx.x;
    int b0 = bq * 4;
    int tid = threadIdx.x;
    int px = tid % 49, yq = tid / 49;
    int oh = px / 7, ow = px - oh * 7;

    for (int t = tid; t < 1728; t += 196) s_in[t] = 0.f;
    for (int t = tid; t < 1536; t += 196) s_w[t] = 0.f;

    int ld[4], sidx[4], cidx[4];
#pragma unroll
    for (int k = 0; k < 4; k++) {
        int t = tid + 196 * k;               // < 784
        int bl = t / 196, rem = t - bl * 196;
        int ci = rem / 49, p = rem - ci * 49;
        int r = p / 7, c = p - r * 7;
        ld[k] = bl * 12544 + rem;
        sidx[k] = bl * 432 + ci * 108 + (r + 1) * 12 + (c + 1);
        cidx[k] = ci;
    }
    int wld[6], wst[6];
#pragma unroll
    for (int k = 0; k < 6; k++) {
        int t = tid + 196 * k;
        if (t < 1152) {
            int co = t / 36, rem = t - co * 36;
            int ci = rem / 9, k9 = rem - ci * 9;
            int kh = k9 / 3, kw = k9 - kh * 3;
            wld[k] = (cog * 32 + co) * 2304 + ci * 9 + k9;
            wst[k] = co * 48 + ci * 12 + kh * 4 + kw;
        } else { wld[k] = -1; wst[k] = 0; }
    }
    __syncthreads();

    const float* base = g_rc1 + (long)(b0 * 256) * 49;
    float r_in[4], r_w[6];
#pragma unroll
    for (int k = 0; k < 4; k++) {
        float sc = g_scr1[cidx[k]], sh = g_shr1[cidx[k]];
        r_in[k] = fmaxf(base[ld[k]] * sc + sh, 0.f);
    }
#pragma unroll
    for (int k = 0; k < 6; k++) r_w[k] = (wld[k] >= 0) ? w[wld[k]] : 0.f;

    float acc[4][8];
#pragma unroll
    for (int bl = 0; bl < 4; bl++)
#pragma unroll
        for (int co = 0; co < 8; co++) acc[bl][co] = 0.f;

#pragma unroll 1
    for (int c0 = 0; c0 < 256; c0 += 4) {
#pragma unroll
        for (int k = 0; k < 4; k++) s_in[sidx[k]] = r_in[k];
#pragma unroll
        for (int k = 0; k < 6; k++) if (wld[k] >= 0) s_w[wst[k]] = r_w[k];
        __syncthreads();
        if (c0 + 4 < 256) {
            const float* src = base + (c0 + 4) * 49;
#pragma unroll
            for (int k = 0; k < 4; k++) {
                int ch = c0 + 4 + cidx[k];
                float sc = g_scr1[ch], sh = g_shr1[ch];
                r_in[k] = fmaxf(src[ld[k]] * sc + sh, 0.f);
            }
#pragma unroll
            for (int k = 0; k < 6; k++)
                if (wld[k] >= 0) r_w[k] = w[wld[k] + (c0 + 4) * 9];
        }
#pragma unroll
        for (int ci = 0; ci < 4; ci++) {
#pragma unroll
            for (int kh = 0; kh < 3; kh++) {
                float in[4][3];
#pragma unroll
                for (int bl = 0; bl < 4; bl++) {
                    int bs = bl * 432 + ci * 108 + (oh + kh) * 12 + ow;
                    in[bl][0] = s_in[bs];
                    in[bl][1] = s_in[bs + 1];
                    in[bl][2] = s_in[bs + 2];
                }
#pragma unroll
                for (int co = 0; co < 8; co++) {
                    const float4* wp = (const float4*)(s_w + (yq * 8 + co) * 48 + ci * 12 + kh * 4);
                    float4 wv = wp[0];
#pragma unroll
                    for (int bl = 0; bl < 4; bl++) {
                        acc[bl][co] += wv.x * in[bl][0];
                        acc[bl][co] += wv.y * in[bl][1];
                        acc[bl][co] += wv.z * in[bl][2];
                    }
                }
            }
        }
        __syncthreads();
    }
#pragma unroll
    for (int bl = 0; bl < 4; bl++)
#pragma unroll
        for (int co = 0; co < 8; co++)
            g_rc2[((b0 + bl) * 256 + cog * 32 + yq * 8 + co) * 49 + px] = acc[bl][co];
}

// ---------------------------------------------------------------------------
// shortcut 1x1 s2, smem staged, scalar. grid (8 cog, 64 b), block 196.
// ---------------------------------------------------------------------------
__global__ void __launch_bounds__(196) k_shortcut(const float* __restrict__ w) {
    __shared__ __align__(16) float s_c[128 * 49];
    __shared__ __align__(16) float s_wv[32 * 128];
    int b = blockIdx.y, cog = blockIdx.x;
    int tid = threadIdx.x;
    int px = tid % 49, yq = tid / 49;

    for (int t = tid; t < 128 * 49; t += 196) {
        int ci = t / 49, p = t - ci * 49;
        int oh = p / 7, ow = p - oh * 7;
        s_c[t] = g_pool2[(b * 128 + ci) * 196 + oh * 28 + ow * 2];
    }
    for (int t = tid; t < 32 * 128; t += 196) {
        int co = t >> 7, ci = t & 127;
        s_wv[t] = w[(cog * 32 + co) * 128 + ci];
    }
    __syncthreads();

    float acc[8];
#pragma unroll
    for (int co = 0; co < 8; co++) acc[co] = 0.f;
#pragma unroll 1
    for (int cp = 0; cp < 64; cp++) {
        float in0 = s_c[(2 * cp) * 49 + px];
        float in1 = s_c[(2 * cp + 1) * 49 + px];
#pragma unroll
        for (int co = 0; co < 8; co++) {
            float2 wv = *(const float2*)(s_wv + (yq * 8 + co) * 128 + 2 * cp);
            acc[co] += wv.x * in0;
            acc[co] += wv.y * in1;
        }
    }
#pragma unroll
    for (int co = 0; co < 8; co++)
        g_rs[(b * 256 + cog * 32 + yq * 8 + co) * 49 + px] = acc[co];
}

// ---------------------------------------------------------------------------
// tail: y = mean relu(bn(rc2)+bn(rs)); out = y M^T + b2
// ---------------------------------------------------------------------------
__global__ void k_tail(float* __restrict__ out) {
    __shared__ float s_y[256];
    int b = blockIdx.x, c = threadIdx.x;
    float sc2 = g_scr2[c], sh2 = g_shr2[c], scs = g_scs[c], shs = g_shs[c];
    const float* p2 = g_rc2 + (b * 256 + c) * 49;
    const float* ps = g_rs + (b * 256 + c) * 49;
    float s = 0.f;
    for (int p = 0; p < 49; p++) {
        float v = p2[p] * sc2 + sh2 + ps[p] * scs + shs;
        s += fmaxf(v, 0.f);
    }
    s_y[c] = s * (1.f / 49.f);
    __syncthreads();
    if (c < 50) {
        float acc = g_b2[c];
        for (int k = 0; k < 256; k++) acc += s_y[k] * g_M[c * 256 + k];
        out[b * 50 + c] = acc;
    }
}

// ---------------------------------------------------------------------------
// Tail fold (softmax attention collapses to 1x1 conv: wo@wv)
// ---------------------------------------------------------------------------
__global__ void k_foldT(const float* __restrict__ fcw, const float* __restrict__ wo) {
    int idx = blockIdx.x * 256 + threadIdx.x;
    if (idx >= 50 * 1024) return;
    int i = idx / 1024, j = idx - i * 1024;
    float s = 0.f;
    for (int c = 0; c < 256; c++) s += fcw[i * 256 + c] * wo[c * 1024 + j];
    g_T[idx] = s;
}

__global__ void k_foldM(const float* __restrict__ wv) {
    int idx = blockIdx.x * 256 + threadIdx.x;
    if (idx >= 50 * 256) return;
    int i = idx / 256, c = idx - i * 256;
    float s = 0.f;
    for (int j = 0; j < 1024; j++) s += g_T[i * 1024 + j] * wv[j * 256 + c];
    g_M[idx] = s;
}

__global__ void k_foldb(const float* __restrict__ fcw, const float* __restrict__ bo,
                        const float* __restrict__ fcb) {
    int i = threadIdx.x;
    if (i >= 50) return;
    float s = 0.f;
    for (int c = 0; c < 256; c++) s += fcw[i * 256 + c] * bo[c];
    g_b2[i] = s + fcb[i];
}

// ---------------------------------------------------------------------------
// Launch (k_conv1 is the 4th launch -> ncu profile target)
// ---------------------------------------------------------------------------
extern "C" void kernel_launch(void* const* d_in, const int* in_sizes, int n_in,
                              void* d_out, int out_size) {
    const float* imgs   = (const float*)d_in[0];
    const float* a1f1   = (const float*)d_in[1];
    const float* a1f2   = (const float*)d_in[2];
    const float* a1f2b  = (const float*)d_in[3];
    const float* dy1    = (const float*)d_in[4];
    const float* bn1g   = (const float*)d_in[5];
    const float* bn1b   = (const float*)d_in[6];
    const float* a2f1   = (const float*)d_in[7];
    const float* a2f2   = (const float*)d_in[8];
    const float* a2f2b  = (const float*)d_in[9];
    const float* dy2    = (const float*)d_in[10];
    const float* bn2g   = (const float*)d_in[11];
    const float* bn2b   = (const float*)d_in[12];
    const float* rc1w   = (const float*)d_in[13];
    const float* rbn1g  = (const float*)d_in[14];
    const float* rbn1b  = (const float*)d_in[15];
    const float* rc2w   = (const float*)d_in[16];
    const float* rbn2g  = (const float*)d_in[17];
    const float* rbn2b  = (const float*)d_in[18];
    const float* rsw    = (const float*)d_in[19];
    const float* rbnsg  = (const float*)d_in[20];
    const float* rbnsb  = (const float*)d_in[21];
    const float* wv     = (const float*)d_in[24];
    const float* wo     = (const float*)d_in[25];
    const float* bo     = (const float*)d_in[26];
    const float* fcw    = (const float*)d_in[27];
    const float* fcb    = (const float*)d_in[28];
    float* out = (float*)d_out;
    (void)in_sizes; (void)n_in; (void)out_size;

    // stage 1 front (block 0 of pooled1 zeroes accumulators)
    k_pooled1<<<192, 256>>>(imgs);
    k_attn1<<<1, 64>>>(a1f1, a1f2, a1f2b);
    k_w1agg<<<(BB * 9408 + 255) / 256, 256>>>(dy1);
    k_conv1<<<dim3(28, 8, BB), 128>>>(imgs);   // <- 4th launch (profiled)

    // tail fold (independent)
    k_foldT<<<200, 256>>>(fcw, wo);
    k_foldM<<<50, 256>>>(wv);
    k_foldb<<<1, 64>>>(fcw, bo, fcb);

    k_bnscale<<<1, 64>>>(bn1g, bn1b, 802816.f, 0, 64);
    k_bnpool1<<<dim3(13, 64, BB), 256>>>();

    // stage 2
    k_attn2<<<1, 64>>>(a2f1, a2f2, a2f2b);
    k_w2agg<<<(BB * 73728 + 255) / 256, 256>>>(dy2);
    k_conv2<<<dim3(8, BB), 224>>>();
    k_bnscale<<<1, 128>>>(bn2g, bn2b, 50176.f, 1, 128);
    k_bnpool2<<<dim3(128, BB), 196>>>();

    // residual block
    k_resconv1<<<dim3(8, BB / 4), 196>>>(rc1w);
    k_shortcut<<<dim3(8, BB), 196>>>(rsw);
    k_chstats<<<256, 128>>>(0);
    k_bnscale<<<1, 256>>>(rbn1g, rbn1b, 3136.f, 2, 256);
    k_resconv2<<<dim3(8, BB / 4), 196>>>(rc2w);
    k_chstats2<<<256, 128>>>();
    k_bnscale<<<1, 256>>>(rbn2g, rbn2b, 3136.f, 3, 256);
    k_bnscale<<<1, 256>>>(rbnsg, rbnsb, 3136.f, 4, 256);

    k_tail<<<64, 256>>>(out);
}

// round 7
// speedup vs baseline: 2.2022x; 1.1339x over previous
#include <cuda_runtime.h>
#include <math.h>

#define BB 64

// ---------------------------------------------------------------------------
// Scratch
// ---------------------------------------------------------------------------
__device__ float g_pooled1[BB * 3];
__device__ float g_attn1[BB * 8];
__device__ float g_w1[BB * 64 * 3 * 49];
__device__ float g_conv1[BB * 64 * 112 * 112];
__device__ float g_pool1[BB * 64 * 56 * 56];
__device__ float g_pooled2[BB * 64];
__device__ float g_attn2[BB * 8];
__device__ float g_w2[BB * 128 * 64 * 9];
__device__ float g_conv2[BB * 128 * 28 * 28];
__device__ float g_pool2[BB * 128 * 14 * 14];
__device__ float g_rc1[BB * 256 * 49];
__device__ float g_rc2[BB * 256 * 49];
__device__ float g_rs[BB * 256 * 49];

__device__ float g_sum1[64],  g_sq1[64],  g_sc1[64],  g_sh1[64];
__device__ float g_sum2[128], g_sq2[128], g_sc2[128], g_sh2[128];
__device__ float g_sumr1[256], g_sqr1[256], g_scr1[256], g_shr1[256];
__device__ float g_sumr2[256], g_sqr2[256], g_scr2[256], g_shr2[256];
__device__ float g_sums[256],  g_sqs[256],  g_scs[256],  g_shs[256];

__device__ float g_T[50 * 1024];
__device__ float g_M[50 * 256];
__device__ float g_b2[50];

// ---------------------------------------------------------------------------
// bn scale/shift
// ---------------------------------------------------------------------------
__global__ void k_bnscale(const float* __restrict__ g, const float* __restrict__ be,
                          float cnt, int stage, int C) {
    int c = blockIdx.x * blockDim.x + threadIdx.x;
    if (c >= C) return;
    float *su, *sq, *sc, *sh;
    switch (stage) {
        case 0:  su = g_sum1;  sq = g_sq1;  sc = g_sc1;  sh = g_sh1;  break;
        case 1:  su = g_sum2;  sq = g_sq2;  sc = g_sc2;  sh = g_sh2;  break;
        case 2:  su = g_sumr1; sq = g_sqr1; sc = g_scr1; sh = g_shr1; break;
        case 3:  su = g_sumr2; sq = g_sqr2; sc = g_scr2; sh = g_shr2; break;
        default: su = g_sums;  sq = g_sqs;  sc = g_scs;  sh = g_shs;  break;
    }
    float m = su[c] / cnt;
    float v = sq[c] / cnt - m * m;
    float s = g[c] * rsqrtf(v + 1e-5f);
    sc[c] = s;
    sh[c] = be[c] - m * s;
}

// per-channel stats of rc1
__global__ void k_chstats(int which) {
    const float* src = which ? g_rc2 : g_rc1;
    float* su = which ? g_sumr2 : g_sumr1;
    float* sq = which ? g_sqr2 : g_sqr1;
    int c = blockIdx.x;
    float s = 0.f, q = 0.f;
    for (int t = threadIdx.x; t < BB * 49; t += 128) {
        int b = t / 49, p = t - b * 49;
        float v = src[(b * 256 + c) * 49 + p];
        s += v; q += v * v;
    }
    for (int o = 16; o; o >>= 1) {
        s += __shfl_down_sync(0xffffffffu, s, o);
        q += __shfl_down_sync(0xffffffffu, q, o);
    }
    __shared__ float rs[4], rq[4];
    int w = threadIdx.x >> 5;
    if ((threadIdx.x & 31) == 0) { rs[w] = s; rq[w] = q; }
    __syncthreads();
    if (threadIdx.x == 0) {
        su[c] = rs[0] + rs[1] + rs[2] + rs[3];
        sq[c] = rq[0] + rq[1] + rq[2] + rq[3];
    }
}

// stats of rc2 AND rs in one launch
__global__ void k_chstats2() {
    int c = blockIdx.x;
    float s2 = 0.f, q2 = 0.f, ss = 0.f, qs = 0.f;
    for (int t = threadIdx.x; t < BB * 49; t += 128) {
        int b = t / 49, p = t - b * 49;
        float v = g_rc2[(b * 256 + c) * 49 + p];
        s2 += v; q2 += v * v;
        float u = g_rs[(b * 256 + c) * 49 + p];
        ss += u; qs += u * u;
    }
    for (int o = 16; o; o >>= 1) {
        s2 += __shfl_down_sync(0xffffffffu, s2, o);
        q2 += __shfl_down_sync(0xffffffffu, q2, o);
        ss += __shfl_down_sync(0xffffffffu, ss, o);
        qs += __shfl_down_sync(0xffffffffu, qs, o);
    }
    __shared__ float r[4][4];
    int w = threadIdx.x >> 5;
    if ((threadIdx.x & 31) == 0) { r[w][0] = s2; r[w][1] = q2; r[w][2] = ss; r[w][3] = qs; }
    __syncthreads();
    if (threadIdx.x == 0) {
        g_sumr2[c] = r[0][0] + r[1][0] + r[2][0] + r[3][0];
        g_sqr2[c]  = r[0][1] + r[1][1] + r[2][1] + r[3][1];
        g_sums[c]  = r[0][2] + r[1][2] + r[2][2] + r[3][2];
        g_sqs[c]   = r[0][3] + r[1][3] + r[2][3] + r[3][3];
    }
}

// ---------------------------------------------------------------------------
// Stage-1 attention
// ---------------------------------------------------------------------------
__global__ void k_pooled1(const float* __restrict__ imgs) {
    int bc = blockIdx.x;
    int tid = threadIdx.x;
    if (bc == 0) {
        for (int i = tid; i < BB * 64; i += 256) g_pooled2[i] = 0.f;
        if (tid < 64)  { g_sum1[tid] = 0.f; g_sq1[tid] = 0.f; }
        if (tid < 128) { g_sum2[tid] = 0.f; g_sq2[tid] = 0.f; }
    }
    const float* p = imgs + (long)bc * 50176;
    float s = 0.f;
    for (int i = tid; i < 50176; i += 256) s += p[i];
    __shared__ float red[256];
    red[tid] = s; __syncthreads();
    for (int o = 128; o; o >>= 1) { if (tid < o) red[tid] += red[tid + o]; __syncthreads(); }
    if (tid == 0) g_pooled1[bc] = red[0] * (1.f / 50176.f);
}

__global__ void k_attn1(const float* __restrict__ fc1, const float* __restrict__ fc2,
                        const float* __restrict__ fc2b) {
    int b = threadIdx.x;
    if (b >= BB) return;
    float p[3];
    for (int c = 0; c < 3; c++) p[c] = g_pooled1[b * 3 + c];
    float h[8];
    for (int j = 0; j < 8; j++) {
        float s = 0.f;
        for (int c = 0; c < 3; c++) s += p[c] * fc1[j * 3 + c];
        h[j] = fmaxf(s, 0.f);
    }
    float lg[8], mx = -1e30f;
    for (int k = 0; k < 8; k++) {
        float s = fc2b[k];
        for (int j = 0; j < 8; j++) s += h[j] * fc2[k * 8 + j];
        lg[k] = s; mx = fmaxf(mx, s);
    }
    float den = 0.f;
    for (int k = 0; k < 8; k++) { lg[k] = expf(lg[k] - mx); den += lg[k]; }
    float inv = 1.f / den;
    for (int k = 0; k < 8; k++) g_attn1[b * 8 + k] = lg[k] * inv;
}

__global__ void k_w1agg(const float* __restrict__ dy1) {
    int idx = blockIdx.x * 256 + threadIdx.x;
    if (idx >= BB * 9408) return;
    int b = idx / 9408, i = idx - b * 9408;
    float s = 0.f;
#pragma unroll
    for (int k = 0; k < 8; k++) s += g_attn1[b * 8 + k] * dy1[k * 9408 + i];
    g_w1[idx] = s;
}

// ---------------------------------------------------------------------------
// Conv1 via tf32 mma.sync implicit GEMM.
// Block: 16x16 pixel tile, all 64 co. 256 threads (8 warps).
// Warp w: pixels [32w, 32w+32) -> 2 m-tiles of 16 (rows = owl, ohl fixed).
// K: 21 chunks of 8 (ci,kh; kw padded to 8, weight tap7 = 0).
// grid (49, 64). Dynamic smem: s_in 4224 + s_w 10752 + s_stat 128 floats.
// ---------------------------------------------------------------------------
extern __shared__ float smemBuf[];
__global__ void __launch_bounds__(256) k_conv1(const float* __restrict__ imgs) {
    float* s_in = smemBuf;                 // [ci][37][38] tf32 bits
    float* s_w = smemBuf + 4224;           // [co][ci][kh][8] tf32 bits, kw7=0
    float* s_stat = smemBuf + 4224 + 10752;
    int b = blockIdx.y;
    int tr = blockIdx.x / 7, tc = blockIdx.x - tr * 7;
    int oh0 = tr * 16, ow0 = tc * 16;
    int tid = threadIdx.x;

    if (tid < 128) s_stat[tid] = 0.f;

    int ih0 = 2 * oh0 - 3, iw0 = 2 * ow0 - 3;
    for (int t = tid; t < 4218; t += 256) {
        int ci = t / 1406, rem = t - ci * 1406;
        int r = rem / 38, c = rem - r * 38;
        int ih = ih0 + r, iw = iw0 + c;
        float v = 0.f;
        if ((unsigned)ih < 224u && (unsigned)iw < 224u)
            v = imgs[((b * 3 + ci) * 224 + ih) * 224 + iw];
        unsigned tv; asm("cvt.rna.tf32.f32 %0, %1;" : "=r"(tv) : "f"(v));
        s_in[t] = __uint_as_float(tv);
    }
    for (int t = tid; t < 10752; t += 256) {
        int co = t / 168, rem = t - co * 168;
        int ci = rem / 56, rem2 = rem - ci * 56;
        int kh = rem2 >> 3, kw = rem2 & 7;
        float v = 0.f;
        if (kw < 7) v = g_w1[b * 9408 + co * 147 + ci * 49 + kh * 7 + kw];
        unsigned tv; asm("cvt.rna.tf32.f32 %0, %1;" : "=r"(tv) : "f"(v));
        s_w[t] = __uint_as_float(tv);
    }
    __syncthreads();

    int w = tid >> 5, lane = tid & 31;
    int gid = lane >> 2, tig = lane & 3;

    float acc[2][8][4];
#pragma unroll
    for (int mt = 0; mt < 2; mt++)
#pragma unroll
        for (int nt = 0; nt < 8; nt++)
#pragma unroll
            for (int k = 0; k < 4; k++) acc[mt][nt][k] = 0.f;

#pragma unroll 1
    for (int ci = 0; ci < 3; ci++) {
#pragma unroll 1
        for (int kh = 0; kh < 7; kh++) {
            int wbase = ci * 56 + kh * 8;
            unsigned bf0[8], bf1[8];
#pragma unroll
            for (int nt = 0; nt < 8; nt++) {
                int co = nt * 8 + gid;
                bf0[nt] = __float_as_uint(s_w[co * 168 + wbase + tig]);
                bf1[nt] = __float_as_uint(s_w[co * 168 + wbase + tig + 4]);
            }
#pragma unroll
            for (int mt = 0; mt < 2; mt++) {
                int arow = ci * 1406 + (2 * (2 * w + mt) + kh) * 38;
                unsigned a0 = __float_as_uint(s_in[arow + 2 * gid + tig]);
                unsigned a1 = __float_as_uint(s_in[arow + 2 * (gid + 8) + tig]);
                unsigned a2 = __float_as_uint(s_in[arow + 2 * gid + tig + 4]);
                unsigned a3 = __float_as_uint(s_in[arow + 2 * (gid + 8) + tig + 4]);
#pragma unroll
                for (int nt = 0; nt < 8; nt++) {
                    asm volatile(
                        "mma.sync.aligned.m16n8k8.row.col.f32.tf32.tf32.f32 "
                        "{%0,%1,%2,%3}, {%4,%5,%6,%7}, {%8,%9}, {%0,%1,%2,%3};"
                        : "+f"(acc[mt][nt][0]), "+f"(acc[mt][nt][1]),
                          "+f"(acc[mt][nt][2]), "+f"(acc[mt][nt][3])
                        : "r"(a0), "r"(a1), "r"(a2), "r"(a3),
                          "r"(bf0[nt]), "r"(bf1[nt]));
                }
            }
        }
    }

    // store outputs: c0 (row gid, col 2tig), c1 (+1 col), c2 (row gid+8), c3
#pragma unroll
    for (int mt = 0; mt < 2; mt++) {
        int oh = oh0 + 2 * w + mt;
#pragma unroll
        for (int nt = 0; nt < 8; nt++) {
            int co = nt * 8 + 2 * tig;
            long base0 = ((long)(b * 64 + co)) * 12544 + oh * 112 + ow0;
            g_conv1[base0 + gid] = acc[mt][nt][0];
            g_conv1[base0 + 12544 + gid] = acc[mt][nt][1];
            g_conv1[base0 + gid + 8] = acc[mt][nt][2];
            g_conv1[base0 + 12544 + gid + 8] = acc[mt][nt][3];
        }
    }

    // bn stats
#pragma unroll
    for (int nt = 0; nt < 8; nt++) {
        float s0 = 0.f, q0 = 0.f, s1 = 0.f, q1 = 0.f;
#pragma unroll
        for (int mt = 0; mt < 2; mt++) {
            float v;
            v = acc[mt][nt][0]; s0 += v; q0 += v * v;
            v = acc[mt][nt][2]; s0 += v; q0 += v * v;
            v = acc[mt][nt][1]; s1 += v; q1 += v * v;
            v = acc[mt][nt][3]; s1 += v; q1 += v * v;
        }
#pragma unroll
        for (int o = 16; o >= 4; o >>= 1) {
            s0 += __shfl_xor_sync(0xffffffffu, s0, o);
            q0 += __shfl_xor_sync(0xffffffffu, q0, o);
            s1 += __shfl_xor_sync(0xffffffffu, s1, o);
            q1 += __shfl_xor_sync(0xffffffffu, q1, o);
        }
        if (gid == 0) {
            int co = nt * 8 + 2 * tig;
            atomicAdd(&s_stat[co], s0);
            atomicAdd(&s_stat[64 + co], q0);
            atomicAdd(&s_stat[co + 1], s1);
            atomicAdd(&s_stat[64 + co + 1], q1);
        }
    }
    __syncthreads();
    if (tid < 64) {
        atomicAdd(&g_sum1[tid], s_stat[tid]);
        atomicAdd(&g_sq1[tid], s_stat[64 + tid]);
    }
}

// ---------------------------------------------------------------------------
// BN1 + maxpool3 s2 p1: 112->56, accumulate pooled2
// ---------------------------------------------------------------------------
__global__ void k_bnpool1() {
    int b = blockIdx.z, c = blockIdx.y;
    int p = blockIdx.x * 256 + threadIdx.x;
    float outv = 0.f;
    bool valid = (p < 3136);
    if (valid) {
        int oh = p / 56, ow = p - oh * 56;
        float sc = g_sc1[c], sh = g_sh1[c];
        const float* ip = g_conv1 + (long)(b * 64 + c) * 12544;
        float m = -1e30f;
#pragma unroll
        for (int r = 0; r < 3; r++) {
            int ih = 2 * oh - 1 + r;
            if ((unsigned)ih >= 112u) continue;
#pragma unroll
            for (int cc = 0; cc < 3; cc++) {
                int iw = 2 * ow - 1 + cc;
                if ((unsigned)iw >= 112u) continue;
                m = fmaxf(m, ip[ih * 112 + iw] * sc + sh);
            }
        }
        g_pool1[(b * 64 + c) * 3136 + p] = m;
        outv = m;
    }
    float s = valid ? outv : 0.f;
    for (int o = 16; o; o >>= 1) s += __shfl_down_sync(0xffffffffu, s, o);
    __shared__ float s_red;
    if (threadIdx.x == 0) s_red = 0.f;
    __syncthreads();
    if ((threadIdx.x & 31) == 0) atomicAdd(&s_red, s);
    __syncthreads();
    if (threadIdx.x == 0) atomicAdd(&g_pooled2[b * 64 + c], s_red);
}

// ---------------------------------------------------------------------------
// Stage-2 attention
// ---------------------------------------------------------------------------
__global__ void k_attn2(const float* __restrict__ fc1, const float* __restrict__ fc2,
                        const float* __restrict__ fc2b) {
    int b = threadIdx.x;
    if (b >= BB) return;
    float h[17];
    for (int j = 0; j < 17; j++) {
        float s = 0.f;
        for (int c = 0; c < 64; c++)
            s += (g_pooled2[b * 64 + c] * (1.f / 3136.f)) * fc1[j * 64 + c];
        h[j] = fmaxf(s, 0.f);
    }
    float lg[8], mx = -1e30f;
    for (int k = 0; k < 8; k++) {
        float s = fc2b[k];
        for (int j = 0; j < 17; j++) s += h[j] * fc2[k * 17 + j];
        lg[k] = s; mx = fmaxf(mx, s);
    }
    float den = 0.f;
    for (int k = 0; k < 8; k++) { lg[k] = expf(lg[k] - mx); den += lg[k]; }
    float inv = 1.f / den;
    for (int k = 0; k < 8; k++) g_attn2[b * 8 + k] = lg[k] * inv;
}

__global__ void k_w2agg(const float* __restrict__ dy2) {
    int idx = blockIdx.x * 256 + threadIdx.x;
    if (idx >= BB * 73728) return;
    int b = idx / 73728, i = idx - b * 73728;
    float s = 0.f;
#pragma unroll
    for (int k = 0; k < 8; k++) s += g_attn2[b * 8 + k] * dy2[k * 73728 + i];
    g_w2[idx] = s;
}

// ---------------------------------------------------------------------------
// Conv2: 64->128, 3x3 s2 p1: 56->28. 16 co/block, register double-buffer
// pipeline. grid (8 cog, 64 b), 224 thr.
// ---------------------------------------------------------------------------
__global__ void __launch_bounds__(224) k_conv2() {
    __shared__ __align__(16) float s_in[2 * 3364];
    __shared__ __align__(16) float s_w[16 * 2 * 3 * 4];
    __shared__ float s_stat[32];
    int b = blockIdx.y, cog = blockIdx.x;
    int tid = threadIdx.x;
    int tx = tid % 28, tyq = tid / 28;

    for (int t = tid; t < 2 * 3364; t += 224) s_in[t] = 0.f;
    for (int t = tid; t < 384; t += 224) s_w[t] = 0.f;
    if (tid < 32) s_stat[tid] = 0.f;

    int sidx[28];
#pragma unroll
    for (int k = 0; k < 28; k++) {
        int t = tid + 224 * k;
        int ci = t / 3136, p = t - ci * 3136;
        int r = p / 56, c = p - r * 56;
        sidx[k] = ci * 3364 + (r + 1) * 58 + (c + 1);
    }
    int w_ld0, w_st0, w_ld1, w_st1;
    {
        int t = tid;
        int co = t / 18, rem = t - co * 18, ci = rem / 9, k9 = rem - ci * 9;
        int kh = k9 / 3, kw = k9 - kh * 3;
        w_ld0 = (cog * 16 + co) * 576 + ci * 9 + k9;
        w_st0 = co * 24 + ci * 12 + kh * 4 + kw;
        t = tid + 224;
        co = t / 18; rem = t - co * 18; ci = rem / 9; k9 = rem - ci * 9;
        kh = k9 / 3; kw = k9 - kh * 3;
        w_ld1 = (cog * 16 + co) * 576 + ci * 9 + k9;
        w_st1 = co * 24 + ci * 12 + kh * 4 + kw;
    }
    __syncthreads();

    const float* base = g_pool1 + (long)(b * 64) * 3136;
    const float* wbase = g_w2 + b * 73728;
    float r_in[28], r_w0, r_w1 = 0.f;
#pragma unroll
    for (int k = 0; k < 28; k++) r_in[k] = base[tid + 224 * k];
    r_w0 = wbase[w_ld0];
    if (tid < 64) r_w1 = wbase[w_ld1];

    float acc[4][16];
#pragma unroll
    for (int j = 0; j < 4; j++)
#pragma unroll
        for (int co = 0; co < 16; co++) acc[j][co] = 0.f;

#pragma unroll 1
    for (int c0 = 0; c0 < 64; c0 += 2) {
#pragma unroll
        for (int k = 0; k < 28; k++) s_in[sidx[k]] = r_in[k];
        s_w[w_st0] = r_w0;
        if (tid < 64) s_w[w_st1] = r_w1;
        __syncthreads();
        if (c0 + 2 < 64) {
            const float* src = base + (c0 + 2) * 3136;
#pragma unroll
            for (int k = 0; k < 28; k++) r_in[k] = src[tid + 224 * k];
            r_w0 = wbase[w_ld0 + (c0 + 2) * 9];
            if (tid < 64) r_w1 = wbase[w_ld1 + (c0 + 2) * 9];
        }
        if (tid < 196) {
#pragma unroll
            for (int ci = 0; ci < 2; ci++) {
#pragma unroll
                for (int kh = 0; kh < 3; kh++) {
                    int rbase = ci * 3364 + (8 * tyq + kh) * 58 + 2 * tx;
                    float in[4][4];
#pragma unroll
                    for (int j = 0; j < 4; j++) {
                        const float2* rp = (const float2*)(s_in + rbase + 116 * j);
                        float2 v0 = rp[0], v1 = rp[1];
                        in[j][0] = v0.x; in[j][1] = v0.y; in[j][2] = v1.x; in[j][3] = v1.y;
                    }
#pragma unroll
                    for (int co = 0; co < 16; co++) {
                        const float4* wp = (const float4*)(s_w + co * 24 + ci * 12 + kh * 4);
                        float4 w = wp[0];
#pragma unroll
                        for (int j = 0; j < 4; j++) {
                            acc[j][co] += w.x * in[j][0];
                            acc[j][co] += w.y * in[j][1];
                            acc[j][co] += w.z * in[j][2];
                        }
                    }
                }
            }
        }
        __syncthreads();
    }

    if (tid < 196) {
#pragma unroll
        for (int co = 0; co < 16; co++) {
            int cb = (b * 128 + cog * 16 + co) * 784;
#pragma unroll
            for (int j = 0; j < 4; j++) {
                int oh = 4 * tyq + j;
                g_conv2[cb + oh * 28 + tx] = acc[j][co];
            }
        }
    }
#pragma unroll
    for (int co = 0; co < 16; co++) {
        float s = acc[0][co] + acc[1][co] + acc[2][co] + acc[3][co];
        float q = acc[0][co] * acc[0][co] + acc[1][co] * acc[1][co]
                + acc[2][co] * acc[2][co] + acc[3][co] * acc[3][co];
        for (int o = 16; o; o >>= 1) {
            s += __shfl_down_sync(0xffffffffu, s, o);
            q += __shfl_down_sync(0xffffffffu, q, o);
        }
        if ((tid & 31) == 0) { atomicAdd(&s_stat[co], s); atomicAdd(&s_stat[16 + co], q); }
    }
    __syncthreads();
    if (tid < 16) {
        atomicAdd(&g_sum2[cog * 16 + tid], s_stat[tid]);
        atomicAdd(&g_sq2[cog * 16 + tid], s_stat[16 + tid]);
    }
}

// ---------------------------------------------------------------------------
// BN2 + maxpool3 s2 p1: 28->14
// ---------------------------------------------------------------------------
__global__ void k_bnpool2() {
    int b = blockIdx.y, c = blockIdx.x;
    int p = threadIdx.x;
    if (p >= 196) return;
    int oh = p / 14, ow = p - oh * 14;
    float sc = g_sc2[c], sh = g_sh2[c];
    const float* ip = g_conv2 + (b * 128 + c) * 784;
    float m = -1e30f;
#pragma unroll
    for (int r = 0; r < 3; r++) {
        int ih = 2 * oh - 1 + r;
        if ((unsigned)ih >= 28u) continue;
#pragma unroll
        for (int cc = 0; cc < 3; cc++) {
            int iw = 2 * ow - 1 + cc;
            if ((unsigned)iw >= 28u) continue;
            m = fmaxf(m, ip[ih * 28 + iw] * sc + sh);
        }
    }
    g_pool2[(b * 128 + c) * 196 + p] = m;
}

// ---------------------------------------------------------------------------
// resconv1: 128->256 3x3 s2, 14->7. 4 batches/block, pipelined staging.
// ---------------------------------------------------------------------------
__global__ void __launch_bounds__(196) k_resconv1(const float* __restrict__ w) {
    __shared__ __align__(16) float s_in[4 * 1080];
    __shared__ __align__(16) float s_w[32 * 48];
    int bq = blockIdx.y, cog = blockIdx.x;
    int b0 = bq * 4;
    int tid = threadIdx.x;
    int px = tid % 49, yq = tid / 49;
    int oh = px / 7, ow = px - oh * 7;

    for (int t = tid; t < 4320; t += 196) s_in[t] = 0.f;
    for (int t = tid; t < 1536; t += 196) s_w[t] = 0.f;

    int ld[16], sidx[16];
#pragma unroll
    for (int k = 0; k < 16; k++) {
        int t = tid + 196 * k;
        int bl = t / 784, rem = t - bl * 784;
        int ci = rem / 196, p = rem - ci * 196;
        int r = p / 14, c = p - r * 14;
        ld[k] = bl * 25088 + rem;
        sidx[k] = bl * 1080 + ci * 270 + (r + 1) * 18 + (c + 1);
    }
    int wld[6], wst[6];
#pragma unroll
    for (int k = 0; k < 6; k++) {
        int t = tid + 196 * k;
        if (t < 1152) {
            int co = t / 36, rem = t - co * 36;
            int ci = rem / 9, k9 = rem - ci * 9;
            int kh = k9 / 3, kw = k9 - kh * 3;
            wld[k] = (cog * 32 + co) * 1152 + ci * 9 + k9;
            wst[k] = co * 48 + ci * 12 + kh * 4 + kw;
        } else { wld[k] = -1; wst[k] = 1536 - 1; }
    }
    __syncthreads();

    const float* base = g_pool2 + (long)(b0 * 128) * 196;
    float r_in[16], r_w[6];
#pragma unroll
    for (int k = 0; k < 16; k++) r_in[k] = base[ld[k]];
#pragma unroll
    for (int k = 0; k < 6; k++) r_w[k] = (wld[k] >= 0) ? w[wld[k]] : 0.f;

    float acc[4][8];
#pragma unroll
    for (int bl = 0; bl < 4; bl++)
#pragma unroll
        for (int co = 0; co < 8; co++) acc[bl][co] = 0.f;

#pragma unroll 1
    for (int c0 = 0; c0 < 128; c0 += 4) {
#pragma unroll
        for (int k = 0; k < 16; k++) s_in[sidx[k]] = r_in[k];
#pragma unroll
        for (int k = 0; k < 6; k++) if (wld[k] >= 0) s_w[wst[k]] = r_w[k];
        __syncthreads();
        if (c0 + 4 < 128) {
            const float* src = base + (c0 + 4) * 196;
#pragma unroll
            for (int k = 0; k < 16; k++) r_in[k] = src[ld[k]];
#pragma unroll
            for (int k = 0; k < 6; k++)
                if (wld[k] >= 0) r_w[k] = w[wld[k] + (c0 + 4) * 9];
        }
#pragma unroll
        for (int ci = 0; ci < 4; ci++) {
#pragma unroll
            for (int kh = 0; kh < 3; kh++) {
                float in[4][3];
#pragma unroll
                for (int bl = 0; bl < 4; bl++) {
                    int bs = bl * 1080 + ci * 270 + (2 * oh + kh) * 18 + 2 * ow;
                    in[bl][0] = s_in[bs];
                    in[bl][1] = s_in[bs + 1];
                    in[bl][2] = s_in[bs + 2];
                }
#pragma unroll
                for (int co = 0; co < 8; co++) {
                    const float4* wp = (const float4*)(s_w + (yq * 8 + co) * 48 + ci * 12 + kh * 4);
                    float4 wv = wp[0];
#pragma unroll
                    for (int bl = 0; bl < 4; bl++) {
                        acc[bl][co] += wv.x * in[bl][0];
                        acc[bl][co] += wv.y * in[bl][1];
                        acc[bl][co] += wv.z * in[bl][2];
                    }
                }
            }
        }
        __syncthreads();
    }
#pragma unroll
    for (int bl = 0; bl < 4; bl++)
#pragma unroll
        for (int co = 0; co < 8; co++)
            g_rc1[((b0 + bl) * 256 + cog * 32 + yq * 8 + co) * 49 + px] = acc[bl][co];
}

// ---------------------------------------------------------------------------
// resconv2: 256->256 3x3 s1, 7x7. bn+relu at register-load time, pipelined.
// ---------------------------------------------------------------------------
__global__ void __launch_bounds__(196) k_resconv2(const float* __restrict__ w) {
    __shared__ __align__(16) float s_in[4 * 432];
    __shared__ __align__(16) float s_w[32 * 48];
    int bq = blockIdx.y, cog = blockIdx.x;
    int b0 = bq * 4;
    int tid = threadIdx.x;
    int px = tid % 49, yq = tid / 49;
    int oh = px / 7, ow = px - oh * 7;

    for (int t = tid; t < 1728; t += 196) s_in[t] = 0.f;
    for (int t = tid; t < 1536; t += 196) s_w[t] = 0.f;

    int ld[4], sidx[4], cidx[4];
#pragma unroll
    for (int k = 0; k < 4; k++) {
        int t = tid + 196 * k;
        int bl = t / 196, rem = t - bl * 196;
        int ci = rem / 49, p = rem - ci * 49;
        int r = p / 7, c = p - r * 7;
        ld[k] = bl * 12544 + rem;
        sidx[k] = bl * 432 + ci * 108 + (r + 1) * 12 + (c + 1);
        cidx[k] = ci;
    }
    int wld[6], wst[6];
#pragma unroll
    for (int k = 0; k < 6; k++) {
        int t = tid + 196 * k;
        if (t < 1152) {
            int co = t / 36, rem = t - co * 36;
            int ci = rem / 9, k9 = rem - ci * 9;
            int kh = k9 / 3, kw = k9 - kh * 3;
            wld[k] = (cog * 32 + co) * 2304 + ci * 9 + k9;
            wst[k] = co * 48 + ci * 12 + kh * 4 + kw;
        } else { wld[k] = -1; wst[k] = 0; }
    }
    __syncthreads();

    const float* base = g_rc1 + (long)(b0 * 256) * 49;
    float r_in[4], r_w[6];
#pragma unroll
    for (int k = 0; k < 4; k++) {
        float sc = g_scr1[cidx[k]], sh = g_shr1[cidx[k]];
        r_in[k] = fmaxf(base[ld[k]] * sc + sh, 0.f);
    }
#pragma unroll
    for (int k = 0; k < 6; k++) r_w[k] = (wld[k] >= 0) ? w[wld[k]] : 0.f;

    float acc[4][8];
#pragma unroll
    for (int bl = 0; bl < 4; bl++)
#pragma unroll
        for (int co = 0; co < 8; co++) acc[bl][co] = 0.f;

#pragma unroll 1
    for (int c0 = 0; c0 < 256; c0 += 4) {
#pragma unroll
        for (int k = 0; k < 4; k++) s_in[sidx[k]] = r_in[k];
#pragma unroll
        for (int k = 0; k < 6; k++) if (wld[k] >= 0) s_w[wst[k]] = r_w[k];
        __syncthreads();
        if (c0 + 4 < 256) {
            const float* src = base + (c0 + 4) * 49;
#pragma unroll
            for (int k = 0; k < 4; k++) {
                int ch = c0 + 4 + cidx[k];
                float sc = g_scr1[ch], sh = g_shr1[ch];
                r_in[k] = fmaxf(src[ld[k]] * sc + sh, 0.f);
            }
#pragma unroll
            for (int k = 0; k < 6; k++)
                if (wld[k] >= 0) r_w[k] = w[wld[k] + (c0 + 4) * 9];
        }
#pragma unroll
        for (int ci = 0; ci < 4; ci++) {
#pragma unroll
            for (int kh = 0; kh < 3; kh++) {
                float in[4][3];
#pragma unroll
                for (int bl = 0; bl < 4; bl++) {
                    int bs = bl * 432 + ci * 108 + (oh + kh) * 12 + ow;
                    in[bl][0] = s_in[bs];
                    in[bl][1] = s_in[bs + 1];
                    in[bl][2] = s_in[bs + 2];
                }
#pragma unroll
                for (int co = 0; co < 8; co++) {
                    const float4* wp = (const float4*)(s_w + (yq * 8 + co) * 48 + ci * 12 + kh * 4);
                    float4 wv = wp[0];
#pragma unroll
                    for (int bl = 0; bl < 4; bl++) {
                        acc[bl][co] += wv.x * in[bl][0];
                        acc[bl][co] += wv.y * in[bl][1];
                        acc[bl][co] += wv.z * in[bl][2];
                    }
                }
            }
        }
        __syncthreads();
    }
#pragma unroll
    for (int bl = 0; bl < 4; bl++)
#pragma unroll
        for (int co = 0; co < 8; co++)
            g_rc2[((b0 + bl) * 256 + cog * 32 + yq * 8 + co) * 49 + px] = acc[bl][co];
}

// ---------------------------------------------------------------------------
// shortcut 1x1 s2, smem staged, scalar. grid (8 cog, 64 b), block 196.
// ---------------------------------------------------------------------------
__global__ void __launch_bounds__(196) k_shortcut(const float* __restrict__ w) {
    __shared__ __align__(16) float s_c[128 * 49];
    __shared__ __align__(16) float s_wv[32 * 128];
    int b = blockIdx.y, cog = blockIdx.x;
    int tid = threadIdx.x;
    int px = tid % 49, yq = tid / 49;

    for (int t = tid; t < 128 * 49; t += 196) {
        int ci = t / 49, p = t - ci * 49;
        int oh = p / 7, ow = p - oh * 7;
        s_c[t] = g_pool2[(b * 128 + ci) * 196 + oh * 28 + ow * 2];
    }
    for (int t = tid; t < 32 * 128; t += 196) {
        int co = t >> 7, ci = t & 127;
        s_wv[t] = w[(cog * 32 + co) * 128 + ci];
    }
    __syncthreads();

    float acc[8];
#pragma unroll
    for (int co = 0; co < 8; co++) acc[co] = 0.f;
#pragma unroll 1
    for (int cp = 0; cp < 64; cp++) {
        float in0 = s_c[(2 * cp) * 49 + px];
        float in1 = s_c[(2 * cp + 1) * 49 + px];
#pragma unroll
        for (int co = 0; co < 8; co++) {
            float2 wv = *(const float2*)(s_wv + (yq * 8 + co) * 128 + 2 * cp);
            acc[co] += wv.x * in0;
            acc[co] += wv.y * in1;
        }
    }
#pragma unroll
    for (int co = 0; co < 8; co++)
        g_rs[(b * 256 + cog * 32 + yq * 8 + co) * 49 + px] = acc[co];
}

// ---------------------------------------------------------------------------
// tail: y = mean relu(bn(rc2)+bn(rs)); out = y M^T + b2
// ---------------------------------------------------------------------------
__global__ void k_tail(float* __restrict__ out) {
    __shared__ float s_y[256];
    int b = blockIdx.x, c = threadIdx.x;
    float sc2 = g_scr2[c], sh2 = g_shr2[c], scs = g_scs[c], shs = g_shs[c];
    const float* p2 = g_rc2 + (b * 256 + c) * 49;
    const float* ps = g_rs + (b * 256 + c) * 49;
    float s = 0.f;
    for (int p = 0; p < 49; p++) {
        float v = p2[p] * sc2 + sh2 + ps[p] * scs + shs;
        s += fmaxf(v, 0.f);
    }
    s_y[c] = s * (1.f / 49.f);
    __syncthreads();
    if (c < 50) {
        float acc = g_b2[c];
        for (int k = 0; k < 256; k++) acc += s_y[k] * g_M[c * 256 + k];
        out[b * 50 + c] = acc;
    }
}

// ---------------------------------------------------------------------------
// Tail fold (softmax attention collapses to 1x1 conv: wo@wv)
// ---------------------------------------------------------------------------
__global__ void k_foldT(const float* __restrict__ fcw, const float* __restrict__ wo) {
    int idx = blockIdx.x * 256 + threadIdx.x;
    if (idx >= 50 * 1024) return;
    int i = idx / 1024, j = idx - i * 1024;
    float s = 0.f;
    for (int c = 0; c < 256; c++) s += fcw[i * 256 + c] * wo[c * 1024 + j];
    g_T[idx] = s;
}

__global__ void k_foldM(const float* __restrict__ wv) {
    int idx = blockIdx.x * 256 + threadIdx.x;
    if (idx >= 50 * 256) return;
    int i = idx / 256, c = idx - i * 256;
    float s = 0.f;
    for (int j = 0; j < 1024; j++) s += g_T[i * 1024 + j] * wv[j * 256 + c];
    g_M[idx] = s;
}

__global__ void k_foldb(const float* __restrict__ fcw, const float* __restrict__ bo,
                        const float* __restrict__ fcb) {
    int i = threadIdx.x;
    if (i >= 50) return;
    float s = 0.f;
    for (int c = 0; c < 256; c++) s += fcw[i * 256 + c] * bo[c];
    g_b2[i] = s + fcb[i];
}

// ---------------------------------------------------------------------------
// Launch (k_conv1 is the 4th launch -> ncu profile target)
// ---------------------------------------------------------------------------
extern "C" void kernel_launch(void* const* d_in, const int* in_sizes, int n_in,
                              void* d_out, int out_size) {
    const float* imgs   = (const float*)d_in[0];
    const float* a1f1   = (const float*)d_in[1];
    const float* a1f2   = (const float*)d_in[2];
    const float* a1f2b  = (const float*)d_in[3];
    const float* dy1    = (const float*)d_in[4];
    const float* bn1g   = (const float*)d_in[5];
    const float* bn1b   = (const float*)d_in[6];
    const float* a2f1   = (const float*)d_in[7];
    const float* a2f2   = (const float*)d_in[8];
    const float* a2f2b  = (const float*)d_in[9];
    const float* dy2    = (const float*)d_in[10];
    const float* bn2g   = (const float*)d_in[11];
    const float* bn2b   = (const float*)d_in[12];
    const float* rc1w   = (const float*)d_in[13];
    const float* rbn1g  = (const float*)d_in[14];
    const float* rbn1b  = (const float*)d_in[15];
    const float* rc2w   = (const float*)d_in[16];
    const float* rbn2g  = (const float*)d_in[17];
    const float* rbn2b  = (const float*)d_in[18];
    const float* rsw    = (const float*)d_in[19];
    const float* rbnsg  = (const float*)d_in[20];
    const float* rbnsb  = (const float*)d_in[21];
    const float* wv     = (const float*)d_in[24];
    const float* wo     = (const float*)d_in[25];
    const float* bo     = (const float*)d_in[26];
    const float* fcw    = (const float*)d_in[27];
    const float* fcb    = (const float*)d_in[28];
    float* out = (float*)d_out;
    (void)in_sizes; (void)n_in; (void)out_size;

    static int smem_set = 0;
    if (!smem_set) {
        cudaFuncSetAttribute(k_conv1, cudaFuncAttributeMaxDynamicSharedMemorySize,
                             (4224 + 10752 + 128) * 4);
        smem_set = 1;
    }

    // stage 1 front (block 0 of pooled1 zeroes accumulators)
    k_pooled1<<<192, 256>>>(imgs);
    k_attn1<<<1, 64>>>(a1f1, a1f2, a1f2b);
    k_w1agg<<<(BB * 9408 + 255) / 256, 256>>>(dy1);
    k_conv1<<<dim3(49, BB), 256, (4224 + 10752 + 128) * 4>>>(imgs);  // 4th (profiled)

    // tail fold (independent)
    k_foldT<<<200, 256>>>(fcw, wo);
    k_foldM<<<50, 256>>>(wv);
    k_foldb<<<1, 64>>>(fcw, bo, fcb);

    k_bnscale<<<1, 64>>>(bn1g, bn1b, 802816.f, 0, 64);
    k_bnpool1<<<dim3(13, 64, BB), 256>>>();

    // stage 2
    k_attn2<<<1, 64>>>(a2f1, a2f2, a2f2b);
    k_w2agg<<<(BB * 73728 + 255) / 256, 256>>>(dy2);
    k_conv2<<<dim3(8, BB), 224>>>();
    k_bnscale<<<1, 128>>>(bn2g, bn2b, 50176.f, 1, 128);
    k_bnpool2<<<dim3(128, BB), 196>>>();

    // residual block
    k_resconv1<<<dim3(8, BB / 4), 196>>>(rc1w);
    k_shortcut<<<dim3(8, BB), 196>>>(rsw);
    k_chstats<<<256, 128>>>(0);
    k_bnscale<<<1, 256>>>(rbn1g, rbn1b, 3136.f, 2, 256);
    k_resconv2<<<dim3(8, BB / 4), 196>>>(rc2w);
    k_chstats2<<<256, 128>>>();
    k_bnscale<<<1, 256>>>(rbn2g, rbn2b, 3136.f, 3, 256);
    k_bnscale<<<1, 256>>>(rbnsg, rbnsb, 3136.f, 4, 256);

    k_tail<<<64, 256>>>(out);
}

// round 8
// speedup vs baseline: 2.3369x; 1.0611x over previous
#include <cuda_runtime.h>
#include <math.h>

#define BB 64

// ---------------------------------------------------------------------------
// Scratch
// ---------------------------------------------------------------------------
__device__ float g_pooled1[BB * 3];
__device__ float g_attn1[BB * 8];
__device__ float g_w1[BB * 64 * 3 * 49];
__device__ float g_conv1[BB * 64 * 112 * 112];
__device__ float g_pool1[BB * 64 * 56 * 56];
__device__ float g_pooled2[BB * 64];
__device__ float g_attn2[BB * 8];
__device__ float g_w2[BB * 128 * 64 * 9];
__device__ float g_conv2[BB * 128 * 28 * 28];
__device__ float g_pool2[BB * 128 * 14 * 14];
__device__ float g_rc1[BB * 256 * 49];
__device__ float g_rc2[BB * 256 * 49];
__device__ float g_rs[BB * 256 * 49];

__device__ float g_sum1[64],  g_sq1[64],  g_sc1[64],  g_sh1[64];
__device__ float g_sum2[128], g_sq2[128], g_sc2[128], g_sh2[128];
__device__ float g_sumr1[256], g_sqr1[256], g_scr1[256], g_shr1[256];
__device__ float g_sumr2[256], g_sqr2[256], g_scr2[256], g_shr2[256];
__device__ float g_sums[256],  g_sqs[256],  g_scs[256],  g_shs[256];

__device__ float g_T[50 * 1024];
__device__ float g_M[50 * 256];
__device__ float g_b2[50];

// ---------------------------------------------------------------------------
// bn scale/shift
// ---------------------------------------------------------------------------
__global__ void k_bnscale(const float* __restrict__ g, const float* __restrict__ be,
                          float cnt, int stage, int C) {
    int c = blockIdx.x * blockDim.x + threadIdx.x;
    if (c >= C) return;
    float *su, *sq, *sc, *sh;
    switch (stage) {
        case 0:  su = g_sum1;  sq = g_sq1;  sc = g_sc1;  sh = g_sh1;  break;
        case 1:  su = g_sum2;  sq = g_sq2;  sc = g_sc2;  sh = g_sh2;  break;
        case 2:  su = g_sumr1; sq = g_sqr1; sc = g_scr1; sh = g_shr1; break;
        case 3:  su = g_sumr2; sq = g_sqr2; sc = g_scr2; sh = g_shr2; break;
        default: su = g_sums;  sq = g_sqs;  sc = g_scs;  sh = g_shs;  break;
    }
    float m = su[c] / cnt;
    float v = sq[c] / cnt - m * m;
    float s = g[c] * rsqrtf(v + 1e-5f);
    sc[c] = s;
    sh[c] = be[c] - m * s;
}

// per-channel stats of rc1
__global__ void k_chstats(int which) {
    const float* src = which ? g_rc2 : g_rc1;
    float* su = which ? g_sumr2 : g_sumr1;
    float* sq = which ? g_sqr2 : g_sqr1;
    int c = blockIdx.x;
    float s = 0.f, q = 0.f;
    for (int t = threadIdx.x; t < BB * 49; t += 128) {
        int b = t / 49, p = t - b * 49;
        float v = src[(b * 256 + c) * 49 + p];
        s += v; q += v * v;
    }
    for (int o = 16; o; o >>= 1) {
        s += __shfl_down_sync(0xffffffffu, s, o);
        q += __shfl_down_sync(0xffffffffu, q, o);
    }
    __shared__ float rs[4], rq[4];
    int w = threadIdx.x >> 5;
    if ((threadIdx.x & 31) == 0) { rs[w] = s; rq[w] = q; }
    __syncthreads();
    if (threadIdx.x == 0) {
        su[c] = rs[0] + rs[1] + rs[2] + rs[3];
        sq[c] = rq[0] + rq[1] + rq[2] + rq[3];
    }
}

// stats of rc2 AND rs in one launch
__global__ void k_chstats2() {
    int c = blockIdx.x;
    float s2 = 0.f, q2 = 0.f, ss = 0.f, qs = 0.f;
    for (int t = threadIdx.x; t < BB * 49; t += 128) {
        int b = t / 49, p = t - b * 49;
        float v = g_rc2[(b * 256 + c) * 49 + p];
        s2 += v; q2 += v * v;
        float u = g_rs[(b * 256 + c) * 49 + p];
        ss += u; qs += u * u;
    }
    for (int o = 16; o; o >>= 1) {
        s2 += __shfl_down_sync(0xffffffffu, s2, o);
        q2 += __shfl_down_sync(0xffffffffu, q2, o);
        ss += __shfl_down_sync(0xffffffffu, ss, o);
        qs += __shfl_down_sync(0xffffffffu, qs, o);
    }
    __shared__ float r[4][4];
    int w = threadIdx.x >> 5;
    if ((threadIdx.x & 31) == 0) { r[w][0] = s2; r[w][1] = q2; r[w][2] = ss; r[w][3] = qs; }
    __syncthreads();
    if (threadIdx.x == 0) {
        g_sumr2[c] = r[0][0] + r[1][0] + r[2][0] + r[3][0];
        g_sqr2[c]  = r[0][1] + r[1][1] + r[2][1] + r[3][1];
        g_sums[c]  = r[0][2] + r[1][2] + r[2][2] + r[3][2];
        g_sqs[c]   = r[0][3] + r[1][3] + r[2][3] + r[3][3];
    }
}

// ---------------------------------------------------------------------------
// Stage-1 attention
// ---------------------------------------------------------------------------
__global__ void k_pooled1(const float* __restrict__ imgs) {
    int bc = blockIdx.x;
    int tid = threadIdx.x;
    if (bc == 0) {
        for (int i = tid; i < BB * 64; i += 256) g_pooled2[i] = 0.f;
        if (tid < 64)  { g_sum1[tid] = 0.f; g_sq1[tid] = 0.f; }
        if (tid < 128) { g_sum2[tid] = 0.f; g_sq2[tid] = 0.f; }
    }
    const float* p = imgs + (long)bc * 50176;
    float s = 0.f;
    for (int i = tid; i < 50176; i += 256) s += p[i];
    __shared__ float red[256];
    red[tid] = s; __syncthreads();
    for (int o = 128; o; o >>= 1) { if (tid < o) red[tid] += red[tid + o]; __syncthreads(); }
    if (tid == 0) g_pooled1[bc] = red[0] * (1.f / 50176.f);
}

__global__ void k_attn1(const float* __restrict__ fc1, const float* __restrict__ fc2,
                        const float* __restrict__ fc2b) {
    int b = threadIdx.x;
    if (b >= BB) return;
    float p[3];
    for (int c = 0; c < 3; c++) p[c] = g_pooled1[b * 3 + c];
    float h[8];
    for (int j = 0; j < 8; j++) {
        float s = 0.f;
        for (int c = 0; c < 3; c++) s += p[c] * fc1[j * 3 + c];
        h[j] = fmaxf(s, 0.f);
    }
    float lg[8], mx = -1e30f;
    for (int k = 0; k < 8; k++) {
        float s = fc2b[k];
        for (int j = 0; j < 8; j++) s += h[j] * fc2[k * 8 + j];
        lg[k] = s; mx = fmaxf(mx, s);
    }
    float den = 0.f;
    for (int k = 0; k < 8; k++) { lg[k] = expf(lg[k] - mx); den += lg[k]; }
    float inv = 1.f / den;
    for (int k = 0; k < 8; k++) g_attn1[b * 8 + k] = lg[k] * inv;
}

__global__ void k_w1agg(const float* __restrict__ dy1) {
    int idx = blockIdx.x * 256 + threadIdx.x;
    if (idx >= BB * 9408) return;
    int b = idx / 9408, i = idx - b * 9408;
    float s = 0.f;
#pragma unroll
    for (int k = 0; k < 8; k++) s += g_attn1[b * 8 + k] * dy1[k * 9408 + i];
    g_w1[idx] = s;
}

// ---------------------------------------------------------------------------
// Conv1 via tf32 mma.sync implicit GEMM.
// Block: 16x16 pixel tile, all 64 co. 256 threads (8 warps).
// K: 21 chunks of 8 (ci,kh; kw padded to 8, weight tap7 = 0).
// Weight smem stride 172 (bank-conflict-free). kh loop fully unrolled for ILP.
// grid (49, 64). Dynamic smem: s_in 4224 + s_w 11008 + s_stat 128 floats.
// ---------------------------------------------------------------------------
#define W_STRIDE 172
extern __shared__ float smemBuf[];
__global__ void __launch_bounds__(256) k_conv1(const float* __restrict__ imgs) {
    float* s_in = smemBuf;                   // [ci][37][38] tf32 bits
    float* s_w = smemBuf + 4224;             // [co][W_STRIDE] tf32 bits, kw7=0
    float* s_stat = smemBuf + 4224 + 64 * W_STRIDE;
    int b = blockIdx.y;
    int tr = blockIdx.x / 7, tc = blockIdx.x - tr * 7;
    int oh0 = tr * 16, ow0 = tc * 16;
    int tid = threadIdx.x;

    if (tid < 128) s_stat[tid] = 0.f;

    int ih0 = 2 * oh0 - 3, iw0 = 2 * ow0 - 3;
    for (int t = tid; t < 4218; t += 256) {
        int ci = t / 1406, rem = t - ci * 1406;
        int r = rem / 38, c = rem - r * 38;
        int ih = ih0 + r, iw = iw0 + c;
        float v = 0.f;
        if ((unsigned)ih < 224u && (unsigned)iw < 224u)
            v = imgs[((b * 3 + ci) * 224 + ih) * 224 + iw];
        unsigned tv; asm("cvt.rna.tf32.f32 %0, %1;" : "=r"(tv) : "f"(v));
        s_in[t] = __uint_as_float(tv);
    }
    for (int t = tid; t < 10752; t += 256) {
        int co = t / 168, rem = t - co * 168;
        int ci = rem / 56, rem2 = rem - ci * 56;
        int kh = rem2 >> 3, kw = rem2 & 7;
        float v = 0.f;
        if (kw < 7) v = g_w1[b * 9408 + co * 147 + ci * 49 + kh * 7 + kw];
        unsigned tv; asm("cvt.rna.tf32.f32 %0, %1;" : "=r"(tv) : "f"(v));
        s_w[co * W_STRIDE + rem] = __uint_as_float(tv);
    }
    __syncthreads();

    int w = tid >> 5, lane = tid & 31;
    int gid = lane >> 2, tig = lane & 3;

    float acc[2][8][4];
#pragma unroll
    for (int mt = 0; mt < 2; mt++)
#pragma unroll
        for (int nt = 0; nt < 8; nt++)
#pragma unroll
            for (int k = 0; k < 4; k++) acc[mt][nt][k] = 0.f;

#pragma unroll 1
    for (int ci = 0; ci < 3; ci++) {
#pragma unroll
        for (int kh = 0; kh < 7; kh++) {
            int wbase = ci * 56 + kh * 8;
            unsigned bf0[8], bf1[8];
#pragma unroll
            for (int nt = 0; nt < 8; nt++) {
                int co = nt * 8 + gid;
                bf0[nt] = __float_as_uint(s_w[co * W_STRIDE + wbase + tig]);
                bf1[nt] = __float_as_uint(s_w[co * W_STRIDE + wbase + tig + 4]);
            }
#pragma unroll
            for (int mt = 0; mt < 2; mt++) {
                int arow = ci * 1406 + (2 * (2 * w + mt) + kh) * 38;
                unsigned a0 = __float_as_uint(s_in[arow + 2 * gid + tig]);
                unsigned a1 = __float_as_uint(s_in[arow + 2 * (gid + 8) + tig]);
                unsigned a2 = __float_as_uint(s_in[arow + 2 * gid + tig + 4]);
                unsigned a3 = __float_as_uint(s_in[arow + 2 * (gid + 8) + tig + 4]);
#pragma unroll
                for (int nt = 0; nt < 8; nt++) {
                    asm volatile(
                        "mma.sync.aligned.m16n8k8.row.col.f32.tf32.tf32.f32 "
                        "{%0,%1,%2,%3}, {%4,%5,%6,%7}, {%8,%9}, {%0,%1,%2,%3};"
                        : "+f"(acc[mt][nt][0]), "+f"(acc[mt][nt][1]),
                          "+f"(acc[mt][nt][2]), "+f"(acc[mt][nt][3])
                        : "r"(a0), "r"(a1), "r"(a2), "r"(a3),
                          "r"(bf0[nt]), "r"(bf1[nt]));
                }
            }
        }
    }

    // store outputs: c0 (row gid, col 2tig), c1 (+1 col), c2 (row gid+8), c3
#pragma unroll
    for (int mt = 0; mt < 2; mt++) {
        int oh = oh0 + 2 * w + mt;
#pragma unroll
        for (int nt = 0; nt < 8; nt++) {
            int co = nt * 8 + 2 * tig;
            long base0 = ((long)(b * 64 + co)) * 12544 + oh * 112 + ow0;
            g_conv1[base0 + gid] = acc[mt][nt][0];
            g_conv1[base0 + 12544 + gid] = acc[mt][nt][1];
            g_conv1[base0 + gid + 8] = acc[mt][nt][2];
            g_conv1[base0 + 12544 + gid + 8] = acc[mt][nt][3];
        }
    }

    // bn stats
#pragma unroll
    for (int nt = 0; nt < 8; nt++) {
        float s0 = 0.f, q0 = 0.f, s1 = 0.f, q1 = 0.f;
#pragma unroll
        for (int mt = 0; mt < 2; mt++) {
            float v;
            v = acc[mt][nt][0]; s0 += v; q0 += v * v;
            v = acc[mt][nt][2]; s0 += v; q0 += v * v;
            v = acc[mt][nt][1]; s1 += v; q1 += v * v;
            v = acc[mt][nt][3]; s1 += v; q1 += v * v;
        }
#pragma unroll
        for (int o = 16; o >= 4; o >>= 1) {
            s0 += __shfl_xor_sync(0xffffffffu, s0, o);
            q0 += __shfl_xor_sync(0xffffffffu, q0, o);
            s1 += __shfl_xor_sync(0xffffffffu, s1, o);
            q1 += __shfl_xor_sync(0xffffffffu, q1, o);
        }
        if (gid == 0) {
            int co = nt * 8 + 2 * tig;
            atomicAdd(&s_stat[co], s0);
            atomicAdd(&s_stat[64 + co], q0);
            atomicAdd(&s_stat[co + 1], s1);
            atomicAdd(&s_stat[64 + co + 1], q1);
        }
    }
    __syncthreads();
    if (tid < 64) {
        atomicAdd(&g_sum1[tid], s_stat[tid]);
        atomicAdd(&g_sq1[tid], s_stat[64 + tid]);
    }
}
#define CONV1_SMEM ((4224 + 64 * W_STRIDE + 128) * 4)

// ---------------------------------------------------------------------------
// BN1 + maxpool3 s2 p1: 112->56, accumulate pooled2
// ---------------------------------------------------------------------------
__global__ void k_bnpool1() {
    int b = blockIdx.z, c = blockIdx.y;
    int p = blockIdx.x * 256 + threadIdx.x;
    float outv = 0.f;
    bool valid = (p < 3136);
    if (valid) {
        int oh = p / 56, ow = p - oh * 56;
        float sc = g_sc1[c], sh = g_sh1[c];
        const float* ip = g_conv1 + (long)(b * 64 + c) * 12544;
        float m = -1e30f;
#pragma unroll
        for (int r = 0; r < 3; r++) {
            int ih = 2 * oh - 1 + r;
            if ((unsigned)ih >= 112u) continue;
#pragma unroll
            for (int cc = 0; cc < 3; cc++) {
                int iw = 2 * ow - 1 + cc;
                if ((unsigned)iw >= 112u) continue;
                m = fmaxf(m, ip[ih * 112 + iw] * sc + sh);
            }
        }
        g_pool1[(b * 64 + c) * 3136 + p] = m;
        outv = m;
    }
    float s = valid ? outv : 0.f;
    for (int o = 16; o; o >>= 1) s += __shfl_down_sync(0xffffffffu, s, o);
    __shared__ float s_red;
    if (threadIdx.x == 0) s_red = 0.f;
    __syncthreads();
    if ((threadIdx.x & 31) == 0) atomicAdd(&s_red, s);
    __syncthreads();
    if (threadIdx.x == 0) atomicAdd(&g_pooled2[b * 64 + c], s_red);
}

// ---------------------------------------------------------------------------
// Stage-2 attention
// ---------------------------------------------------------------------------
__global__ void k_attn2(const float* __restrict__ fc1, const float* __restrict__ fc2,
                        const float* __restrict__ fc2b) {
    int b = threadIdx.x;
    if (b >= BB) return;
    float h[17];
    for (int j = 0; j < 17; j++) {
        float s = 0.f;
        for (int c = 0; c < 64; c++)
            s += (g_pooled2[b * 64 + c] * (1.f / 3136.f)) * fc1[j * 64 + c];
        h[j] = fmaxf(s, 0.f);
    }
    float lg[8], mx = -1e30f;
    for (int k = 0; k < 8; k++) {
        float s = fc2b[k];
        for (int j = 0; j < 17; j++) s += h[j] * fc2[k * 17 + j];
        lg[k] = s; mx = fmaxf(mx, s);
    }
    float den = 0.f;
    for (int k = 0; k < 8; k++) { lg[k] = expf(lg[k] - mx); den += lg[k]; }
    float inv = 1.f / den;
    for (int k = 0; k < 8; k++) g_attn2[b * 8 + k] = lg[k] * inv;
}

__global__ void k_w2agg(const float* __restrict__ dy2) {
    int idx = blockIdx.x * 256 + threadIdx.x;
    if (idx >= BB * 73728) return;
    int b = idx / 73728, i = idx - b * 73728;
    float s = 0.f;
#pragma unroll
    for (int k = 0; k < 8; k++) s += g_attn2[b * 8 + k] * dy2[k * 73728 + i];
    g_w2[idx] = s;
}

// ---------------------------------------------------------------------------
// Conv2: 64->128, 3x3 s2 p1: 56->28. 16 co/block, register double-buffer
// pipeline. grid (8 cog, 64 b), 224 thr.
// ---------------------------------------------------------------------------
__global__ void __launch_bounds__(224) k_conv2() {
    __shared__ __align__(16) float s_in[2 * 3364];
    __shared__ __align__(16) float s_w[16 * 2 * 3 * 4];
    __shared__ float s_stat[32];
    int b = blockIdx.y, cog = blockIdx.x;
    int tid = threadIdx.x;
    int tx = tid % 28, tyq = tid / 28;

    for (int t = tid; t < 2 * 3364; t += 224) s_in[t] = 0.f;
    for (int t = tid; t < 384; t += 224) s_w[t] = 0.f;
    if (tid < 32) s_stat[tid] = 0.f;

    int sidx[28];
#pragma unroll
    for (int k = 0; k < 28; k++) {
        int t = tid + 224 * k;
        int ci = t / 3136, p = t - ci * 3136;
        int r = p / 56, c = p - r * 56;
        sidx[k] = ci * 3364 + (r + 1) * 58 + (c + 1);
    }
    int w_ld0, w_st0, w_ld1, w_st1;
    {
        int t = tid;
        int co = t / 18, rem = t - co * 18, ci = rem / 9, k9 = rem - ci * 9;
        int kh = k9 / 3, kw = k9 - kh * 3;
        w_ld0 = (cog * 16 + co) * 576 + ci * 9 + k9;
        w_st0 = co * 24 + ci * 12 + kh * 4 + kw;
        t = tid + 224;
        co = t / 18; rem = t - co * 18; ci = rem / 9; k9 = rem - ci * 9;
        kh = k9 / 3; kw = k9 - kh * 3;
        w_ld1 = (cog * 16 + co) * 576 + ci * 9 + k9;
        w_st1 = co * 24 + ci * 12 + kh * 4 + kw;
    }
    __syncthreads();

    const float* base = g_pool1 + (long)(b * 64) * 3136;
    const float* wbase = g_w2 + b * 73728;
    float r_in[28], r_w0, r_w1 = 0.f;
#pragma unroll
    for (int k = 0; k < 28; k++) r_in[k] = base[tid + 224 * k];
    r_w0 = wbase[w_ld0];
    if (tid < 64) r_w1 = wbase[w_ld1];

    float acc[4][16];
#pragma unroll
    for (int j = 0; j < 4; j++)
#pragma unroll
        for (int co = 0; co < 16; co++) acc[j][co] = 0.f;

#pragma unroll 1
    for (int c0 = 0; c0 < 64; c0 += 2) {
#pragma unroll
        for (int k = 0; k < 28; k++) s_in[sidx[k]] = r_in[k];
        s_w[w_st0] = r_w0;
        if (tid < 64) s_w[w_st1] = r_w1;
        __syncthreads();
        if (c0 + 2 < 64) {
            const float* src = base + (c0 + 2) * 3136;
#pragma unroll
            for (int k = 0; k < 28; k++) r_in[k] = src[tid + 224 * k];
            r_w0 = wbase[w_ld0 + (c0 + 2) * 9];
            if (tid < 64) r_w1 = wbase[w_ld1 + (c0 + 2) * 9];
        }
        if (tid < 196) {
#pragma unroll
            for (int ci = 0; ci < 2; ci++) {
#pragma unroll
                for (int kh = 0; kh < 3; kh++) {
                    int rbase = ci * 3364 + (8 * tyq + kh) * 58 + 2 * tx;
                    float in[4][4];
#pragma unroll
                    for (int j = 0; j < 4; j++) {
                        const float2* rp = (const float2*)(s_in + rbase + 116 * j);
                        float2 v0 = rp[0], v1 = rp[1];
                        in[j][0] = v0.x; in[j][1] = v0.y; in[j][2] = v1.x; in[j][3] = v1.y;
                    }
#pragma unroll
                    for (int co = 0; co < 16; co++) {
                        const float4* wp = (const float4*)(s_w + co * 24 + ci * 12 + kh * 4);
                        float4 w = wp[0];
#pragma unroll
                        for (int j = 0; j < 4; j++) {
                            acc[j][co] += w.x * in[j][0];
                            acc[j][co] += w.y * in[j][1];
                            acc[j][co] += w.z * in[j][2];
                        }
                    }
                }
            }
        }
        __syncthreads();
    }

    if (tid < 196) {
#pragma unroll
        for (int co = 0; co < 16; co++) {
            int cb = (b * 128 + cog * 16 + co) * 784;
#pragma unroll
            for (int j = 0; j < 4; j++) {
                int oh = 4 * tyq + j;
                g_conv2[cb + oh * 28 + tx] = acc[j][co];
            }
        }
    }
#pragma unroll
    for (int co = 0; co < 16; co++) {
        float s = acc[0][co] + acc[1][co] + acc[2][co] + acc[3][co];
        float q = acc[0][co] * acc[0][co] + acc[1][co] * acc[1][co]
                + acc[2][co] * acc[2][co] + acc[3][co] * acc[3][co];
        for (int o = 16; o; o >>= 1) {
            s += __shfl_down_sync(0xffffffffu, s, o);
            q += __shfl_down_sync(0xffffffffu, q, o);
        }
        if ((tid & 31) == 0) { atomicAdd(&s_stat[co], s); atomicAdd(&s_stat[16 + co], q); }
    }
    __syncthreads();
    if (tid < 16) {
        atomicAdd(&g_sum2[cog * 16 + tid], s_stat[tid]);
        atomicAdd(&g_sq2[cog * 16 + tid], s_stat[16 + tid]);
    }
}

// ---------------------------------------------------------------------------
// BN2 + maxpool3 s2 p1: 28->14
// ---------------------------------------------------------------------------
__global__ void k_bnpool2() {
    int b = blockIdx.y, c = blockIdx.x;
    int p = threadIdx.x;
    if (p >= 196) return;
    int oh = p / 14, ow = p - oh * 14;
    float sc = g_sc2[c], sh = g_sh2[c];
    const float* ip = g_conv2 + (b * 128 + c) * 784;
    float m = -1e30f;
#pragma unroll
    for (int r = 0; r < 3; r++) {
        int ih = 2 * oh - 1 + r;
        if ((unsigned)ih >= 28u) continue;
#pragma unroll
        for (int cc = 0; cc < 3; cc++) {
            int iw = 2 * ow - 1 + cc;
            if ((unsigned)iw >= 28u) continue;
            m = fmaxf(m, ip[ih * 28 + iw] * sc + sh);
        }
    }
    g_pool2[(b * 128 + c) * 196 + p] = m;
}

// ---------------------------------------------------------------------------
// resconv1: 128->256 3x3 s2, 14->7. 4 batches/block, pipelined staging.
// ---------------------------------------------------------------------------
__global__ void __launch_bounds__(196) k_resconv1(const float* __restrict__ w) {
    __shared__ __align__(16) float s_in[4 * 1080];
    __shared__ __align__(16) float s_w[32 * 48];
    int bq = blockIdx.y, cog = blockIdx.x;
    int b0 = bq * 4;
    int tid = threadIdx.x;
    int px = tid % 49, yq = tid / 49;
    int oh = px / 7, ow = px - oh * 7;

    for (int t = tid; t < 4320; t += 196) s_in[t] = 0.f;
    for (int t = tid; t < 1536; t += 196) s_w[t] = 0.f;

    int ld[16], sidx[16];
#pragma unroll
    for (int k = 0; k < 16; k++) {
        int t = tid + 196 * k;
        int bl = t / 784, rem = t - bl * 784;
        int ci = rem / 196, p = rem - ci * 196;
        int r = p / 14, c = p - r * 14;
        ld[k] = bl * 25088 + rem;
        sidx[k] = bl * 1080 + ci * 270 + (r + 1) * 18 + (c + 1);
    }
    int wld[6], wst[6];
#pragma unroll
    for (int k = 0; k < 6; k++) {
        int t = tid + 196 * k;
        if (t < 1152) {
            int co = t / 36, rem = t - co * 36;
            int ci = rem / 9, k9 = rem - ci * 9;
            int kh = k9 / 3, kw = k9 - kh * 3;
            wld[k] = (cog * 32 + co) * 1152 + ci * 9 + k9;
            wst[k] = co * 48 + ci * 12 + kh * 4 + kw;
        } else { wld[k] = -1; wst[k] = 1536 - 1; }
    }
    __syncthreads();

    const float* base = g_pool2 + (long)(b0 * 128) * 196;
    float r_in[16], r_w[6];
#pragma unroll
    for (int k = 0; k < 16; k++) r_in[k] = base[ld[k]];
#pragma unroll
    for (int k = 0; k < 6; k++) r_w[k] = (wld[k] >= 0) ? w[wld[k]] : 0.f;

    float acc[4][8];
#pragma unroll
    for (int bl = 0; bl < 4; bl++)
#pragma unroll
        for (int co = 0; co < 8; co++) acc[bl][co] = 0.f;

#pragma unroll 1
    for (int c0 = 0; c0 < 128; c0 += 4) {
#pragma unroll
        for (int k = 0; k < 16; k++) s_in[sidx[k]] = r_in[k];
#pragma unroll
        for (int k = 0; k < 6; k++) if (wld[k] >= 0) s_w[wst[k]] = r_w[k];
        __syncthreads();
        if (c0 + 4 < 128) {
            const float* src = base + (c0 + 4) * 196;
#pragma unroll
            for (int k = 0; k < 16; k++) r_in[k] = src[ld[k]];
#pragma unroll
            for (int k = 0; k < 6; k++)
                if (wld[k] >= 0) r_w[k] = w[wld[k] + (c0 + 4) * 9];
        }
#pragma unroll
        for (int ci = 0; ci < 4; ci++) {
#pragma unroll
            for (int kh = 0; kh < 3; kh++) {
                float in[4][3];
#pragma unroll
                for (int bl = 0; bl < 4; bl++) {
                    int bs = bl * 1080 + ci * 270 + (2 * oh + kh) * 18 + 2 * ow;
                    in[bl][0] = s_in[bs];
                    in[bl][1] = s_in[bs + 1];
                    in[bl][2] = s_in[bs + 2];
                }
#pragma unroll
                for (int co = 0; co < 8; co++) {
                    const float4* wp = (const float4*)(s_w + (yq * 8 + co) * 48 + ci * 12 + kh * 4);
                    float4 wv = wp[0];
#pragma unroll
                    for (int bl = 0; bl < 4; bl++) {
                        acc[bl][co] += wv.x * in[bl][0];
                        acc[bl][co] += wv.y * in[bl][1];
                        acc[bl][co] += wv.z * in[bl][2];
                    }
                }
            }
        }
        __syncthreads();
    }
#pragma unroll
    for (int bl = 0; bl < 4; bl++)
#pragma unroll
        for (int co = 0; co < 8; co++)
            g_rc1[((b0 + bl) * 256 + cog * 32 + yq * 8 + co) * 49 + px] = acc[bl][co];
}

// ---------------------------------------------------------------------------
// resconv2: 256->256 3x3 s1, 7x7. bn+relu at register-load time, pipelined.
// ---------------------------------------------------------------------------
__global__ void __launch_bounds__(196) k_resconv2(const float* __restrict__ w) {
    __shared__ __align__(16) float s_in[4 * 432];
    __shared__ __align__(16) float s_w[32 * 48];
    int bq = blockIdx.y, cog = blockIdx.x;
    int b0 = bq * 4;
    int tid = threadIdx.x;
    int px = tid % 49, yq = tid / 49;
    int oh = px / 7, ow = px - oh * 7;

    for (int t = tid; t < 1728; t += 196) s_in[t] = 0.f;
    for (int t = tid; t < 1536; t += 196) s_w[t] = 0.f;

    int ld[4], sidx[4], cidx[4];
#pragma unroll
    for (int k = 0; k < 4; k++) {
        int t = tid + 196 * k;
        int bl = t / 196, rem = t - bl * 196;
        int ci = rem / 49, p = rem - ci * 49;
        int r = p / 7, c = p - r * 7;
        ld[k] = bl * 12544 + rem;
        sidx[k] = bl * 432 + ci * 108 + (r + 1) * 12 + (c + 1);
        cidx[k] = ci;
    }
    int wld[6], wst[6];
#pragma unroll
    for (int k = 0; k < 6; k++) {
        int t = tid + 196 * k;
        if (t < 1152) {
            int co = t / 36, rem = t - co * 36;
            int ci = rem / 9, k9 = rem - ci * 9;
            int kh = k9 / 3, kw = k9 - kh * 3;
            wld[k] = (cog * 32 + co) * 2304 + ci * 9 + k9;
            wst[k] = co * 48 + ci * 12 + kh * 4 + kw;
        } else { wld[k] = -1; wst[k] = 0; }
    }
    __syncthreads();

    const float* base = g_rc1 + (long)(b0 * 256) * 49;
    float r_in[4], r_w[6];
#pragma unroll
    for (int k = 0; k < 4; k++) {
        float sc = g_scr1[cidx[k]], sh = g_shr1[cidx[k]];
        r_in[k] = fmaxf(base[ld[k]] * sc + sh, 0.f);
    }
#pragma unroll
    for (int k = 0; k < 6; k++) r_w[k] = (wld[k] >= 0) ? w[wld[k]] : 0.f;

    float acc[4][8];
#pragma unroll
    for (int bl = 0; bl < 4; bl++)
#pragma unroll
        for (int co = 0; co < 8; co++) acc[bl][co] = 0.f;

#pragma unroll 1
    for (int c0 = 0; c0 < 256; c0 += 4) {
#pragma unroll
        for (int k = 0; k < 4; k++) s_in[sidx[k]] = r_in[k];
#pragma unroll
        for (int k = 0; k < 6; k++) if (wld[k] >= 0) s_w[wst[k]] = r_w[k];
        __syncthreads();
        if (c0 + 4 < 256) {
            const float* src = base + (c0 + 4) * 49;
#pragma unroll
            for (int k = 0; k < 4; k++) {
                int ch = c0 + 4 + cidx[k];
                float sc = g_scr1[ch], sh = g_shr1[ch];
                r_in[k] = fmaxf(src[ld[k]] * sc + sh, 0.f);
            }
#pragma unroll
            for (int k = 0; k < 6; k++)
                if (wld[k] >= 0) r_w[k] = w[wld[k] + (c0 + 4) * 9];
        }
#pragma unroll
        for (int ci = 0; ci < 4; ci++) {
#pragma unroll
            for (int kh = 0; kh < 3; kh++) {
                float in[4][3];
#pragma unroll
                for (int bl = 0; bl < 4; bl++) {
                    int bs = bl * 432 + ci * 108 + (oh + kh) * 12 + ow;
                    in[bl][0] = s_in[bs];
                    in[bl][1] = s_in[bs + 1];
                    in[bl][2] = s_in[bs + 2];
                }
#pragma unroll
                for (int co = 0; co < 8; co++) {
                    const float4* wp = (const float4*)(s_w + (yq * 8 + co) * 48 + ci * 12 + kh * 4);
                    float4 wv = wp[0];
#pragma unroll
                    for (int bl = 0; bl < 4; bl++) {
                        acc[bl][co] += wv.x * in[bl][0];
                        acc[bl][co] += wv.y * in[bl][1];
                        acc[bl][co] += wv.z * in[bl][2];
                    }
                }
            }
        }
        __syncthreads();
    }
#pragma unroll
    for (int bl = 0; bl < 4; bl++)
#pragma unroll
        for (int co = 0; co < 8; co++)
            g_rc2[((b0 + bl) * 256 + cog * 32 + yq * 8 + co) * 49 + px] = acc[bl][co];
}

// ---------------------------------------------------------------------------
// shortcut 1x1 s2, smem staged, scalar. grid (8 cog, 64 b), block 196.
// ---------------------------------------------------------------------------
__global__ void __launch_bounds__(196) k_shortcut(const float* __restrict__ w) {
    __shared__ __align__(16) float s_c[128 * 49];
    __shared__ __align__(16) float s_wv[32 * 128];
    int b = blockIdx.y, cog = blockIdx.x;
    int tid = threadIdx.x;
    int px = tid % 49, yq = tid / 49;

    for (int t = tid; t < 128 * 49; t += 196) {
        int ci = t / 49, p = t - ci * 49;
        int oh = p / 7, ow = p - oh * 7;
        s_c[t] = g_pool2[(b * 128 + ci) * 196 + oh * 28 + ow * 2];
    }
    for (int t = tid; t < 32 * 128; t += 196) {
        int co = t >> 7, ci = t & 127;
        s_wv[t] = w[(cog * 32 + co) * 128 + ci];
    }
    __syncthreads();

    float acc[8];
#pragma unroll
    for (int co = 0; co < 8; co++) acc[co] = 0.f;
#pragma unroll 1
    for (int cp = 0; cp < 64; cp++) {
        float in0 = s_c[(2 * cp) * 49 + px];
        float in1 = s_c[(2 * cp + 1) * 49 + px];
#pragma unroll
        for (int co = 0; co < 8; co++) {
            float2 wv = *(const float2*)(s_wv + (yq * 8 + co) * 128 + 2 * cp);
            acc[co] += wv.x * in0;
            acc[co] += wv.y * in1;
        }
    }
#pragma unroll
    for (int co = 0; co < 8; co++)
        g_rs[(b * 256 + cog * 32 + yq * 8 + co) * 49 + px] = acc[co];
}

// ---------------------------------------------------------------------------
// tail: y = mean relu(bn(rc2)+bn(rs)); out = y M^T + b2
// ---------------------------------------------------------------------------
__global__ void k_tail(float* __restrict__ out) {
    __shared__ float s_y[256];
    int b = blockIdx.x, c = threadIdx.x;
    float sc2 = g_scr2[c], sh2 = g_shr2[c], scs = g_scs[c], shs = g_shs[c];
    const float* p2 = g_rc2 + (b * 256 + c) * 49;
    const float* ps = g_rs + (b * 256 + c) * 49;
    float s = 0.f;
    for (int p = 0; p < 49; p++) {
        float v = p2[p] * sc2 + sh2 + ps[p] * scs + shs;
        s += fmaxf(v, 0.f);
    }
    s_y[c] = s * (1.f / 49.f);
    __syncthreads();
    if (c < 50) {
        float acc = g_b2[c];
        for (int k = 0; k < 256; k++) acc += s_y[k] * g_M[c * 256 + k];
        out[b * 50 + c] = acc;
    }
}

// ---------------------------------------------------------------------------
// Tail fold (softmax attention collapses to 1x1 conv: wo@wv)
// ---------------------------------------------------------------------------
__global__ void k_foldT(const float* __restrict__ fcw, const float* __restrict__ wo) {
    int idx = blockIdx.x * 256 + threadIdx.x;
    if (idx >= 50 * 1024) return;
    int i = idx / 1024, j = idx - i * 1024;
    float s = 0.f;
    for (int c = 0; c < 256; c++) s += fcw[i * 256 + c] * wo[c * 1024 + j];
    g_T[idx] = s;
}

__global__ void k_foldM(const float* __restrict__ wv) {
    int idx = blockIdx.x * 256 + threadIdx.x;
    if (idx >= 50 * 256) return;
    int i = idx / 256, c = idx - i * 256;
    float s = 0.f;
    for (int j = 0; j < 1024; j++) s += g_T[i * 1024 + j] * wv[j * 256 + c];
    g_M[idx] = s;
}

__global__ void k_foldb(const float* __restrict__ fcw, const float* __restrict__ bo,
                        const float* __restrict__ fcb) {
    int i = threadIdx.x;
    if (i >= 50) return;
    float s = 0.f;
    for (int c = 0; c < 256; c++) s += fcw[i * 256 + c] * bo[c];
    g_b2[i] = s + fcb[i];
}

// ---------------------------------------------------------------------------
// Launch (k_conv1 is the 4th launch -> ncu profile target)
// ---------------------------------------------------------------------------
extern "C" void kernel_launch(void* const* d_in, const int* in_sizes, int n_in,
                              void* d_out, int out_size) {
    const float* imgs   = (const float*)d_in[0];
    const float* a1f1   = (const float*)d_in[1];
    const float* a1f2   = (const float*)d_in[2];
    const float* a1f2b  = (const float*)d_in[3];
    const float* dy1    = (const float*)d_in[4];
    const float* bn1g   = (const float*)d_in[5];
    const float* bn1b   = (const float*)d_in[6];
    const float* a2f1   = (const float*)d_in[7];
    const float* a2f2   = (const float*)d_in[8];
    const float* a2f2b  = (const float*)d_in[9];
    const float* dy2    = (const float*)d_in[10];
    const float* bn2g   = (const float*)d_in[11];
    const float* bn2b   = (const float*)d_in[12];
    const float* rc1w   = (const float*)d_in[13];
    const float* rbn1g  = (const float*)d_in[14];
    const float* rbn1b  = (const float*)d_in[15];
    const float* rc2w   = (const float*)d_in[16];
    const float* rbn2g  = (const float*)d_in[17];
    const float* rbn2b  = (const float*)d_in[18];
    const float* rsw    = (const float*)d_in[19];
    const float* rbnsg  = (const float*)d_in[20];
    const float* rbnsb  = (const float*)d_in[21];
    const float* wv     = (const float*)d_in[24];
    const float* wo     = (const float*)d_in[25];
    const float* bo     = (const float*)d_in[26];
    const float* fcw    = (const float*)d_in[27];
    const float* fcb    = (const float*)d_in[28];
    float* out = (float*)d_out;
    (void)in_sizes; (void)n_in; (void)out_size;

    static int smem_set = 0;
    if (!smem_set) {
        cudaFuncSetAttribute(k_conv1, cudaFuncAttributeMaxDynamicSharedMemorySize,
                             CONV1_SMEM);
        smem_set = 1;
    }

    // stage 1 front (block 0 of pooled1 zeroes accumulators)
    k_pooled1<<<192, 256>>>(imgs);
    k_attn1<<<1, 64>>>(a1f1, a1f2, a1f2b);
    k_w1agg<<<(BB * 9408 + 255) / 256, 256>>>(dy1);
    k_conv1<<<dim3(49, BB), 256, CONV1_SMEM>>>(imgs);  // 4th (profiled)

    // tail fold (independent)
    k_foldT<<<200, 256>>>(fcw, wo);
    k_foldM<<<50, 256>>>(wv);
    k_foldb<<<1, 64>>>(fcw, bo, fcb);

    k_bnscale<<<1, 64>>>(bn1g, bn1b, 802816.f, 0, 64);
    k_bnpool1<<<dim3(13, 64, BB), 256>>>();

    // stage 2
    k_attn2<<<1, 64>>>(a2f1, a2f2, a2f2b);
    k_w2agg<<<(BB * 73728 + 255) / 256, 256>>>(dy2);
    k_conv2<<<dim3(8, BB), 224>>>();
    k_bnscale<<<1, 128>>>(bn2g, bn2b, 50176.f, 1, 128);
    k_bnpool2<<<dim3(128, BB), 196>>>();

    // residual block
    k_resconv1<<<dim3(8, BB / 4), 196>>>(rc1w);
    k_shortcut<<<dim3(8, BB), 196>>>(rsw);
    k_chstats<<<256, 128>>>(0);
    k_bnscale<<<1, 256>>>(rbn1g, rbn1b, 3136.f, 2, 256);
    k_resconv2<<<dim3(8, BB / 4), 196>>>(rc2w);
    k_chstats2<<<256, 128>>>();
    k_bnscale<<<1, 256>>>(rbn2g, rbn2b, 3136.f, 3, 256);
    k_bnscale<<<1, 256>>>(rbnsg, rbnsb, 3136.f, 4, 256);

    k_tail<<<64, 256>>>(out);
}

// round 9
// speedup vs baseline: 2.3589x; 1.0094x over previous
#include <cuda_runtime.h>
#include <math.h>

#define BB 64

// ---------------------------------------------------------------------------
// Scratch
// ---------------------------------------------------------------------------
__device__ float g_pooled1[BB * 3];
__device__ float g_attn1[BB * 8];
__device__ float g_w1t[BB * 64 * 168];           // tf32-rounded, padded [co][ci][kh][8]
__device__ float g_conv1[BB * 64 * 112 * 112];
__device__ float g_pool1[BB * 64 * 56 * 56];
__device__ float g_pooled2[BB * 64];
__device__ float g_attn2[BB * 8];
__device__ float g_w2[BB * 128 * 64 * 9];
__device__ float g_conv2[BB * 128 * 28 * 28];
__device__ float g_pool2[BB * 128 * 14 * 14];
__device__ float g_rc1[BB * 256 * 49];
__device__ float g_rc2[BB * 256 * 49];
__device__ float g_rs[BB * 256 * 49];

__device__ float g_sum1[64],  g_sq1[64],  g_sc1[64],  g_sh1[64];
__device__ float g_sum2[128], g_sq2[128], g_sc2[128], g_sh2[128];
__device__ float g_sumr1[256], g_sqr1[256], g_scr1[256], g_shr1[256];
__device__ float g_sumr2[256], g_sqr2[256], g_scr2[256], g_shr2[256];
__device__ float g_sums[256],  g_sqs[256],  g_scs[256],  g_shs[256];

__device__ float g_T[50 * 1024];
__device__ float g_M[50 * 256];
__device__ float g_b2[50];

// ---------------------------------------------------------------------------
// bn scale/shift
// ---------------------------------------------------------------------------
__global__ void k_bnscale(const float* __restrict__ g, const float* __restrict__ be,
                          float cnt, int stage, int C) {
    int c = blockIdx.x * blockDim.x + threadIdx.x;
    if (c >= C) return;
    float *su, *sq, *sc, *sh;
    switch (stage) {
        case 0:  su = g_sum1;  sq = g_sq1;  sc = g_sc1;  sh = g_sh1;  break;
        case 1:  su = g_sum2;  sq = g_sq2;  sc = g_sc2;  sh = g_sh2;  break;
        case 2:  su = g_sumr1; sq = g_sqr1; sc = g_scr1; sh = g_shr1; break;
        case 3:  su = g_sumr2; sq = g_sqr2; sc = g_scr2; sh = g_shr2; break;
        default: su = g_sums;  sq = g_sqs;  sc = g_scs;  sh = g_shs;  break;
    }
    float m = su[c] / cnt;
    float v = sq[c] / cnt - m * m;
    float s = g[c] * rsqrtf(v + 1e-5f);
    sc[c] = s;
    sh[c] = be[c] - m * s;
}

// per-channel stats of rc1
__global__ void k_chstats(int which) {
    const float* src = which ? g_rc2 : g_rc1;
    float* su = which ? g_sumr2 : g_sumr1;
    float* sq = which ? g_sqr2 : g_sqr1;
    int c = blockIdx.x;
    float s = 0.f, q = 0.f;
    for (int t = threadIdx.x; t < BB * 49; t += 128) {
        int b = t / 49, p = t - b * 49;
        float v = src[(b * 256 + c) * 49 + p];
        s += v; q += v * v;
    }
    for (int o = 16; o; o >>= 1) {
        s += __shfl_down_sync(0xffffffffu, s, o);
        q += __shfl_down_sync(0xffffffffu, q, o);
    }
    __shared__ float rs[4], rq[4];
    int w = threadIdx.x >> 5;
    if ((threadIdx.x & 31) == 0) { rs[w] = s; rq[w] = q; }
    __syncthreads();
    if (threadIdx.x == 0) {
        su[c] = rs[0] + rs[1] + rs[2] + rs[3];
        sq[c] = rq[0] + rq[1] + rq[2] + rq[3];
    }
}

// stats of rc2 AND rs in one launch
__global__ void k_chstats2() {
    int c = blockIdx.x;
    float s2 = 0.f, q2 = 0.f, ss = 0.f, qs = 0.f;
    for (int t = threadIdx.x; t < BB * 49; t += 128) {
        int b = t / 49, p = t - b * 49;
        float v = g_rc2[(b * 256 + c) * 49 + p];
        s2 += v; q2 += v * v;
        float u = g_rs[(b * 256 + c) * 49 + p];
        ss += u; qs += u * u;
    }
    for (int o = 16; o; o >>= 1) {
        s2 += __shfl_down_sync(0xffffffffu, s2, o);
        q2 += __shfl_down_sync(0xffffffffu, q2, o);
        ss += __shfl_down_sync(0xffffffffu, ss, o);
        qs += __shfl_down_sync(0xffffffffu, qs, o);
    }
    __shared__ float r[4][4];
    int w = threadIdx.x >> 5;
    if ((threadIdx.x & 31) == 0) { r[w][0] = s2; r[w][1] = q2; r[w][2] = ss; r[w][3] = qs; }
    __syncthreads();
    if (threadIdx.x == 0) {
        g_sumr2[c] = r[0][0] + r[1][0] + r[2][0] + r[3][0];
        g_sqr2[c]  = r[0][1] + r[1][1] + r[2][1] + r[3][1];
        g_sums[c]  = r[0][2] + r[1][2] + r[2][2] + r[3][2];
        g_sqs[c]   = r[0][3] + r[1][3] + r[2][3] + r[3][3];
    }
}

// ---------------------------------------------------------------------------
// Stage-1 attention
// ---------------------------------------------------------------------------
__global__ void k_pooled1(const float* __restrict__ imgs) {
    int bc = blockIdx.x;
    int tid = threadIdx.x;
    if (bc == 0) {
        for (int i = tid; i < BB * 64; i += 256) g_pooled2[i] = 0.f;
        if (tid < 64)  { g_sum1[tid] = 0.f; g_sq1[tid] = 0.f; }
        if (tid < 128) { g_sum2[tid] = 0.f; g_sq2[tid] = 0.f; }
    }
    const float* p = imgs + (long)bc * 50176;
    float s = 0.f;
    for (int i = tid; i < 50176; i += 256) s += p[i];
    __shared__ float red[256];
    red[tid] = s; __syncthreads();
    for (int o = 128; o; o >>= 1) { if (tid < o) red[tid] += red[tid + o]; __syncthreads(); }
    if (tid == 0) g_pooled1[bc] = red[0] * (1.f / 50176.f);
}

__global__ void k_attn1(const float* __restrict__ fc1, const float* __restrict__ fc2,
                        const float* __restrict__ fc2b) {
    int b = threadIdx.x;
    if (b >= BB) return;
    float p[3];
    for (int c = 0; c < 3; c++) p[c] = g_pooled1[b * 3 + c];
    float h[8];
    for (int j = 0; j < 8; j++) {
        float s = 0.f;
        for (int c = 0; c < 3; c++) s += p[c] * fc1[j * 3 + c];
        h[j] = fmaxf(s, 0.f);
    }
    float lg[8], mx = -1e30f;
    for (int k = 0; k < 8; k++) {
        float s = fc2b[k];
        for (int j = 0; j < 8; j++) s += h[j] * fc2[k * 8 + j];
        lg[k] = s; mx = fmaxf(mx, s);
    }
    float den = 0.f;
    for (int k = 0; k < 8; k++) { lg[k] = expf(lg[k] - mx); den += lg[k]; }
    float inv = 1.f / den;
    for (int k = 0; k < 8; k++) g_attn1[b * 8 + k] = lg[k] * inv;
}

// aggregate + tf32-round + pad into [b][co][ci][kh][8] (kw slot 7 = 0)
__global__ void k_w1agg(const float* __restrict__ dy1) {
    int idx = blockIdx.x * 256 + threadIdx.x;
    if (idx >= BB * 10752) return;
    int b = idx / 10752, r = idx - b * 10752;
    int co = r / 168, r2 = r - co * 168;
    int ci = r2 / 56, r3 = r2 - ci * 56;
    int kh = r3 >> 3, kw = r3 & 7;
    float s = 0.f;
    if (kw < 7) {
        int i = co * 147 + ci * 49 + kh * 7 + kw;
#pragma unroll
        for (int k = 0; k < 8; k++) s += g_attn1[b * 8 + k] * dy1[k * 9408 + i];
    }
    unsigned tv; asm("cvt.rna.tf32.f32 %0, %1;" : "=r"(tv) : "f"(s));
    g_w1t[idx] = __uint_as_float(tv);
}

// ---------------------------------------------------------------------------
// Conv1 via tf32 mma.sync implicit GEMM.
// Block: 16x16 pixel tile, all 64 co. 256 threads (8 warps).
// Input smem pitch 64 (divide-free staging); weights pre-rounded/padded.
// grid (49, 64). smem: s_in 7104 + s_w 11008 + s_stat 128 floats = 72960 B.
// ---------------------------------------------------------------------------
#define W_STRIDE 172
extern __shared__ float smemBuf[];
__global__ void __launch_bounds__(256, 2) k_conv1(const float* __restrict__ imgs) {
    float* s_in = smemBuf;                   // [ci][37][64] tf32 bits
    float* s_w = smemBuf + 7104;             // [co][W_STRIDE]
    float* s_stat = smemBuf + 7104 + 64 * W_STRIDE;
    int b = blockIdx.y;
    int tr = blockIdx.x / 7, tc = blockIdx.x - tr * 7;
    int oh0 = tr * 16, ow0 = tc * 16;
    int tid = threadIdx.x;

    if (tid < 128) s_stat[tid] = 0.f;

    // weights: strided copy (pre-rounded, pre-padded)
    const float* wt = g_w1t + b * 10752;
    for (int t = tid; t < 10752; t += 256)
        s_w[t + (t / 168) * 4] = wt[t];

    // input: pitch-64 rows, cols 0..37 used
    int ih0 = 2 * oh0 - 3, iw0 = 2 * ow0 - 3;
#pragma unroll 1
    for (int ci = 0; ci < 3; ci++) {
        const float* ip = imgs + (long)(b * 3 + ci) * 50176;
        for (int u = tid; u < 2368; u += 256) {
            int r = u >> 6, c = u & 63;
            if (c < 38) {
                int ih = ih0 + r, iw = iw0 + c;
                float v = 0.f;
                if ((unsigned)ih < 224u && (unsigned)iw < 224u)
                    v = ip[ih * 224 + iw];
                unsigned tv; asm("cvt.rna.tf32.f32 %0, %1;" : "=r"(tv) : "f"(v));
                s_in[ci * 2368 + u] = __uint_as_float(tv);
            }
        }
    }
    __syncthreads();

    int w = tid >> 5, lane = tid & 31;
    int gid = lane >> 2, tig = lane & 3;

    float acc[2][8][4];
#pragma unroll
    for (int mt = 0; mt < 2; mt++)
#pragma unroll
        for (int nt = 0; nt < 8; nt++)
#pragma unroll
            for (int k = 0; k < 4; k++) acc[mt][nt][k] = 0.f;

    int bq[8];
#pragma unroll
    for (int nt = 0; nt < 8; nt++) bq[nt] = (nt * 8 + gid) * W_STRIDE + tig;
    int abase0 = (2 * (2 * w + 0)) * 64 + 2 * gid + tig;
    int abase1 = (2 * (2 * w + 1)) * 64 + 2 * gid + tig;

#pragma unroll 1
    for (int ci = 0; ci < 3; ci++) {
#pragma unroll
        for (int kh = 0; kh < 7; kh++) {
            int wbase = ci * 56 + kh * 8;
            int aoff = ci * 2368 + kh * 64;
            unsigned bf0[8], bf1[8];
#pragma unroll
            for (int nt = 0; nt < 8; nt++) {
                bf0[nt] = __float_as_uint(s_w[bq[nt] + wbase]);
                bf1[nt] = __float_as_uint(s_w[bq[nt] + wbase + 4]);
            }
#pragma unroll
            for (int mt = 0; mt < 2; mt++) {
                int a = aoff + (mt ? abase1 : abase0);
                unsigned a0 = __float_as_uint(s_in[a]);
                unsigned a1 = __float_as_uint(s_in[a + 16]);
                unsigned a2 = __float_as_uint(s_in[a + 4]);
                unsigned a3 = __float_as_uint(s_in[a + 20]);
#pragma unroll
                for (int nt = 0; nt < 8; nt++) {
                    asm volatile(
                        "mma.sync.aligned.m16n8k8.row.col.f32.tf32.tf32.f32 "
                        "{%0,%1,%2,%3}, {%4,%5,%6,%7}, {%8,%9}, {%0,%1,%2,%3};"
                        : "+f"(acc[mt][nt][0]), "+f"(acc[mt][nt][1]),
                          "+f"(acc[mt][nt][2]), "+f"(acc[mt][nt][3])
                        : "r"(a0), "r"(a1), "r"(a2), "r"(a3),
                          "r"(bf0[nt]), "r"(bf1[nt]));
                }
            }
        }
    }

    // store outputs
#pragma unroll
    for (int mt = 0; mt < 2; mt++) {
        int oh = oh0 + 2 * w + mt;
#pragma unroll
        for (int nt = 0; nt < 8; nt++) {
            int co = nt * 8 + 2 * tig;
            long base0 = ((long)(b * 64 + co)) * 12544 + oh * 112 + ow0;
            g_conv1[base0 + gid] = acc[mt][nt][0];
            g_conv1[base0 + 12544 + gid] = acc[mt][nt][1];
            g_conv1[base0 + gid + 8] = acc[mt][nt][2];
            g_conv1[base0 + 12544 + gid + 8] = acc[mt][nt][3];
        }
    }

    // bn stats
#pragma unroll
    for (int nt = 0; nt < 8; nt++) {
        float s0 = 0.f, q0 = 0.f, s1 = 0.f, q1 = 0.f;
#pragma unroll
        for (int mt = 0; mt < 2; mt++) {
            float v;
            v = acc[mt][nt][0]; s0 += v; q0 += v * v;
            v = acc[mt][nt][2]; s0 += v; q0 += v * v;
            v = acc[mt][nt][1]; s1 += v; q1 += v * v;
            v = acc[mt][nt][3]; s1 += v; q1 += v * v;
        }
#pragma unroll
        for (int o = 16; o >= 4; o >>= 1) {
            s0 += __shfl_xor_sync(0xffffffffu, s0, o);
            q0 += __shfl_xor_sync(0xffffffffu, q0, o);
            s1 += __shfl_xor_sync(0xffffffffu, s1, o);
            q1 += __shfl_xor_sync(0xffffffffu, q1, o);
        }
        if (gid == 0) {
            int co = nt * 8 + 2 * tig;
            atomicAdd(&s_stat[co], s0);
            atomicAdd(&s_stat[64 + co], q0);
            atomicAdd(&s_stat[co + 1], s1);
            atomicAdd(&s_stat[64 + co + 1], q1);
        }
    }
    __syncthreads();
    if (tid < 64) {
        atomicAdd(&g_sum1[tid], s_stat[tid]);
        atomicAdd(&g_sq1[tid], s_stat[64 + tid]);
    }
}
#define CONV1_SMEM ((7104 + 64 * W_STRIDE + 128) * 4)

// ---------------------------------------------------------------------------
// BN1 + maxpool3 s2 p1: 112->56, accumulate pooled2
// ---------------------------------------------------------------------------
__global__ void k_bnpool1() {
    int b = blockIdx.z, c = blockIdx.y;
    int p = blockIdx.x * 256 + threadIdx.x;
    float outv = 0.f;
    bool valid = (p < 3136);
    if (valid) {
        int oh = p / 56, ow = p - oh * 56;
        float sc = g_sc1[c], sh = g_sh1[c];
        const float* ip = g_conv1 + (long)(b * 64 + c) * 12544;
        float m = -1e30f;
#pragma unroll
        for (int r = 0; r < 3; r++) {
            int ih = 2 * oh - 1 + r;
            if ((unsigned)ih >= 112u) continue;
#pragma unroll
            for (int cc = 0; cc < 3; cc++) {
                int iw = 2 * ow - 1 + cc;
                if ((unsigned)iw >= 112u) continue;
                m = fmaxf(m, ip[ih * 112 + iw] * sc + sh);
            }
        }
        g_pool1[(b * 64 + c) * 3136 + p] = m;
        outv = m;
    }
    float s = valid ? outv : 0.f;
    for (int o = 16; o; o >>= 1) s += __shfl_down_sync(0xffffffffu, s, o);
    __shared__ float s_red;
    if (threadIdx.x == 0) s_red = 0.f;
    __syncthreads();
    if ((threadIdx.x & 31) == 0) atomicAdd(&s_red, s);
    __syncthreads();
    if (threadIdx.x == 0) atomicAdd(&g_pooled2[b * 64 + c], s_red);
}

// ---------------------------------------------------------------------------
// Stage-2 attention
// ---------------------------------------------------------------------------
__global__ void k_attn2(const float* __restrict__ fc1, const float* __restrict__ fc2,
                        const float* __restrict__ fc2b) {
    int b = threadIdx.x;
    if (b >= BB) return;
    float h[17];
    for (int j = 0; j < 17; j++) {
        float s = 0.f;
        for (int c = 0; c < 64; c++)
            s += (g_pooled2[b * 64 + c] * (1.f / 3136.f)) * fc1[j * 64 + c];
        h[j] = fmaxf(s, 0.f);
    }
    float lg[8], mx = -1e30f;
    for (int k = 0; k < 8; k++) {
        float s = fc2b[k];
        for (int j = 0; j < 17; j++) s += h[j] * fc2[k * 17 + j];
        lg[k] = s; mx = fmaxf(mx, s);
    }
    float den = 0.f;
    for (int k = 0; k < 8; k++) { lg[k] = expf(lg[k] - mx); den += lg[k]; }
    float inv = 1.f / den;
    for (int k = 0; k < 8; k++) g_attn2[b * 8 + k] = lg[k] * inv;
}

__global__ void k_w2agg(const float* __restrict__ dy2) {
    int idx = blockIdx.x * 256 + threadIdx.x;
    if (idx >= BB * 73728) return;
    int b = idx / 73728, i = idx - b * 73728;
    float s = 0.f;
#pragma unroll
    for (int k = 0; k < 8; k++) s += g_attn2[b * 8 + k] * dy2[k * 73728 + i];
    g_w2[idx] = s;
}

// ---------------------------------------------------------------------------
// Conv2: 64->128, 3x3 s2 p1: 56->28. 16 co/block, register double-buffer
// pipeline. grid (8 cog, 64 b), 224 thr.
// ---------------------------------------------------------------------------
__global__ void __launch_bounds__(224) k_conv2() {
    __shared__ __align__(16) float s_in[2 * 3364];
    __shared__ __align__(16) float s_w[16 * 2 * 3 * 4];
    __shared__ float s_stat[32];
    int b = blockIdx.y, cog = blockIdx.x;
    int tid = threadIdx.x;
    int tx = tid % 28, tyq = tid / 28;

    for (int t = tid; t < 2 * 3364; t += 224) s_in[t] = 0.f;
    for (int t = tid; t < 384; t += 224) s_w[t] = 0.f;
    if (tid < 32) s_stat[tid] = 0.f;

    int sidx[28];
#pragma unroll
    for (int k = 0; k < 28; k++) {
        int t = tid + 224 * k;
        int ci = t / 3136, p = t - ci * 3136;
        int r = p / 56, c = p - r * 56;
        sidx[k] = ci * 3364 + (r + 1) * 58 + (c + 1);
    }
    int w_ld0, w_st0, w_ld1, w_st1;
    {
        int t = tid;
        int co = t / 18, rem = t - co * 18, ci = rem / 9, k9 = rem - ci * 9;
        int kh = k9 / 3, kw = k9 - kh * 3;
        w_ld0 = (cog * 16 + co) * 576 + ci * 9 + k9;
        w_st0 = co * 24 + ci * 12 + kh * 4 + kw;
        t = tid + 224;
        co = t / 18; rem = t - co * 18; ci = rem / 9; k9 = rem - ci * 9;
        kh = k9 / 3; kw = k9 - kh * 3;
        w_ld1 = (cog * 16 + co) * 576 + ci * 9 + k9;
        w_st1 = co * 24 + ci * 12 + kh * 4 + kw;
    }
    __syncthreads();

    const float* base = g_pool1 + (long)(b * 64) * 3136;
    const float* wbase = g_w2 + b * 73728;
    float r_in[28], r_w0, r_w1 = 0.f;
#pragma unroll
    for (int k = 0; k < 28; k++) r_in[k] = base[tid + 224 * k];
    r_w0 = wbase[w_ld0];
    if (tid < 64) r_w1 = wbase[w_ld1];

    float acc[4][16];
#pragma unroll
    for (int j = 0; j < 4; j++)
#pragma unroll
        for (int co = 0; co < 16; co++) acc[j][co] = 0.f;

#pragma unroll 1
    for (int c0 = 0; c0 < 64; c0 += 2) {
#pragma unroll
        for (int k = 0; k < 28; k++) s_in[sidx[k]] = r_in[k];
        s_w[w_st0] = r_w0;
        if (tid < 64) s_w[w_st1] = r_w1;
        __syncthreads();
        if (c0 + 2 < 64) {
            const float* src = base + (c0 + 2) * 3136;
#pragma unroll
            for (int k = 0; k < 28; k++) r_in[k] = src[tid + 224 * k];
            r_w0 = wbase[w_ld0 + (c0 + 2) * 9];
            if (tid < 64) r_w1 = wbase[w_ld1 + (c0 + 2) * 9];
        }
        if (tid < 196) {
#pragma unroll
            for (int ci = 0; ci < 2; ci++) {
#pragma unroll
                for (int kh = 0; kh < 3; kh++) {
                    int rbase = ci * 3364 + (8 * tyq + kh) * 58 + 2 * tx;
                    float in[4][4];
#pragma unroll
                    for (int j = 0; j < 4; j++) {
                        const float2* rp = (const float2*)(s_in + rbase + 116 * j);
                        float2 v0 = rp[0], v1 = rp[1];
                        in[j][0] = v0.x; in[j][1] = v0.y; in[j][2] = v1.x; in[j][3] = v1.y;
                    }
#pragma unroll
                    for (int co = 0; co < 16; co++) {
                        const float4* wp = (const float4*)(s_w + co * 24 + ci * 12 + kh * 4);
                        float4 w = wp[0];
#pragma unroll
                        for (int j = 0; j < 4; j++) {
                            acc[j][co] += w.x * in[j][0];
                            acc[j][co] += w.y * in[j][1];
                            acc[j][co] += w.z * in[j][2];
                        }
                    }
                }
            }
        }
        __syncthreads();
    }

    if (tid < 196) {
#pragma unroll
        for (int co = 0; co < 16; co++) {
            int cb = (b * 128 + cog * 16 + co) * 784;
#pragma unroll
            for (int j = 0; j < 4; j++) {
                int oh = 4 * tyq + j;
                g_conv2[cb + oh * 28 + tx] = acc[j][co];
            }
        }
    }
#pragma unroll
    for (int co = 0; co < 16; co++) {
        float s = acc[0][co] + acc[1][co] + acc[2][co] + acc[3][co];
        float q = acc[0][co] * acc[0][co] + acc[1][co] * acc[1][co]
                + acc[2][co] * acc[2][co] + acc[3][co] * acc[3][co];
        for (int o = 16; o; o >>= 1) {
            s += __shfl_down_sync(0xffffffffu, s, o);
            q += __shfl_down_sync(0xffffffffu, q, o);
        }
        if ((tid & 31) == 0) { atomicAdd(&s_stat[co], s); atomicAdd(&s_stat[16 + co], q); }
    }
    __syncthreads();
    if (tid < 16) {
        atomicAdd(&g_sum2[cog * 16 + tid], s_stat[tid]);
        atomicAdd(&g_sq2[cog * 16 + tid], s_stat[16 + tid]);
    }
}

// ---------------------------------------------------------------------------
// BN2 + maxpool3 s2 p1: 28->14
// ---------------------------------------------------------------------------
__global__ void k_bnpool2() {
    int b = blockIdx.y, c = blockIdx.x;
    int p = threadIdx.x;
    if (p >= 196) return;
    int oh = p / 14, ow = p - oh * 14;
    float sc = g_sc2[c], sh = g_sh2[c];
    const float* ip = g_conv2 + (b * 128 + c) * 784;
    float m = -1e30f;
#pragma unroll
    for (int r = 0; r < 3; r++) {
        int ih = 2 * oh - 1 + r;
        if ((unsigned)ih >= 28u) continue;
#pragma unroll
        for (int cc = 0; cc < 3; cc++) {
            int iw = 2 * ow - 1 + cc;
            if ((unsigned)iw >= 28u) continue;
            m = fmaxf(m, ip[ih * 28 + iw] * sc + sh);
        }
    }
    g_pool2[(b * 128 + c) * 196 + p] = m;
}

// ---------------------------------------------------------------------------
// resconv1: 128->256 3x3 s2, 14->7. 4 batches/block, pipelined staging.
// ---------------------------------------------------------------------------
__global__ void __launch_bounds__(196) k_resconv1(const float* __restrict__ w) {
    __shared__ __align__(16) float s_in[4 * 1080];
    __shared__ __align__(16) float s_w[32 * 48];
    int bq = blockIdx.y, cog = blockIdx.x;
    int b0 = bq * 4;
    int tid = threadIdx.x;
    int px = tid % 49, yq = tid / 49;
    int oh = px / 7, ow = px - oh * 7;

    for (int t = tid; t < 4320; t += 196) s_in[t] = 0.f;
    for (int t = tid; t < 1536; t += 196) s_w[t] = 0.f;

    int ld[16], sidx[16];
#pragma unroll
    for (int k = 0; k < 16; k++) {
        int t = tid + 196 * k;
        int bl = t / 784, rem = t - bl * 784;
        int ci = rem / 196, p = rem - ci * 196;
        int r = p / 14, c = p - r * 14;
        ld[k] = bl * 25088 + rem;
        sidx[k] = bl * 1080 + ci * 270 + (r + 1) * 18 + (c + 1);
    }
    int wld[6], wst[6];
#pragma unroll
    for (int k = 0; k < 6; k++) {
        int t = tid + 196 * k;
        if (t < 1152) {
            int co = t / 36, rem = t - co * 36;
            int ci = rem / 9, k9 = rem - ci * 9;
            int kh = k9 / 3, kw = k9 - kh * 3;
            wld[k] = (cog * 32 + co) * 1152 + ci * 9 + k9;
            wst[k] = co * 48 + ci * 12 + kh * 4 + kw;
        } else { wld[k] = -1; wst[k] = 1536 - 1; }
    }
    __syncthreads();

    const float* base = g_pool2 + (long)(b0 * 128) * 196;
    float r_in[16], r_w[6];
#pragma unroll
    for (int k = 0; k < 16; k++) r_in[k] = base[ld[k]];
#pragma unroll
    for (int k = 0; k < 6; k++) r_w[k] = (wld[k] >= 0) ? w[wld[k]] : 0.f;

    float acc[4][8];
#pragma unroll
    for (int bl = 0; bl < 4; bl++)
#pragma unroll
        for (int co = 0; co < 8; co++) acc[bl][co] = 0.f;

#pragma unroll 1
    for (int c0 = 0; c0 < 128; c0 += 4) {
#pragma unroll
        for (int k = 0; k < 16; k++) s_in[sidx[k]] = r_in[k];
#pragma unroll
        for (int k = 0; k < 6; k++) if (wld[k] >= 0) s_w[wst[k]] = r_w[k];
        __syncthreads();
        if (c0 + 4 < 128) {
            const float* src = base + (c0 + 4) * 196;
#pragma unroll
            for (int k = 0; k < 16; k++) r_in[k] = src[ld[k]];
#pragma unroll
            for (int k = 0; k < 6; k++)
                if (wld[k] >= 0) r_w[k] = w[wld[k] + (c0 + 4) * 9];
        }
#pragma unroll
        for (int ci = 0; ci < 4; ci++) {
#pragma unroll
            for (int kh = 0; kh < 3; kh++) {
                float in[4][3];
#pragma unroll
                for (int bl = 0; bl < 4; bl++) {
                    int bs = bl * 1080 + ci * 270 + (2 * oh + kh) * 18 + 2 * ow;
                    in[bl][0] = s_in[bs];
                    in[bl][1] = s_in[bs + 1];
                    in[bl][2] = s_in[bs + 2];
                }
#pragma unroll
                for (int co = 0; co < 8; co++) {
                    const float4* wp = (const float4*)(s_w + (yq * 8 + co) * 48 + ci * 12 + kh * 4);
                    float4 wv = wp[0];
#pragma unroll
                    for (int bl = 0; bl < 4; bl++) {
                        acc[bl][co] += wv.x * in[bl][0];
                        acc[bl][co] += wv.y * in[bl][1];
                        acc[bl][co] += wv.z * in[bl][2];
                    }
                }
            }
        }
        __syncthreads();
    }
#pragma unroll
    for (int bl = 0; bl < 4; bl++)
#pragma unroll
        for (int co = 0; co < 8; co++)
            g_rc1[((b0 + bl) * 256 + cog * 32 + yq * 8 + co) * 49 + px] = acc[bl][co];
}

// ---------------------------------------------------------------------------
// resconv2: 256->256 3x3 s1, 7x7. bn+relu at register-load time, pipelined.
// ---------------------------------------------------------------------------
__global__ void __launch_bounds__(196) k_resconv2(const float* __restrict__ w) {
    __shared__ __align__(16) float s_in[4 * 432];
    __shared__ __align__(16) float s_w[32 * 48];
    int bq = blockIdx.y, cog = blockIdx.x;
    int b0 = bq * 4;
    int tid = threadIdx.x;
    int px = tid % 49, yq = tid / 49;
    int oh = px / 7, ow = px - oh * 7;

    for (int t = tid; t < 1728; t += 196) s_in[t] = 0.f;
    for (int t = tid; t < 1536; t += 196) s_w[t] = 0.f;

    int ld[4], sidx[4], cidx[4];
#pragma unroll
    for (int k = 0; k < 4; k++) {
        int t = tid + 196 * k;
        int bl = t / 196, rem = t - bl * 196;
        int ci = rem / 49, p = rem - ci * 49;
        int r = p / 7, c = p - r * 7;
        ld[k] = bl * 12544 + rem;
        sidx[k] = bl * 432 + ci * 108 + (r + 1) * 12 + (c + 1);
        cidx[k] = ci;
    }
    int wld[6], wst[6];
#pragma unroll
    for (int k = 0; k < 6; k++) {
        int t = tid + 196 * k;
        if (t < 1152) {
            int co = t / 36, rem = t - co * 36;
            int ci = rem / 9, k9 = rem - ci * 9;
            int kh = k9 / 3, kw = k9 - kh * 3;
            wld[k] = (cog * 32 + co) * 2304 + ci * 9 + k9;
            wst[k] = co * 48 + ci * 12 + kh * 4 + kw;
        } else { wld[k] = -1; wst[k] = 0; }
    }
    __syncthreads();

    const float* base = g_rc1 + (long)(b0 * 256) * 49;
    float r_in[4], r_w[6];
#pragma unroll
    for (int k = 0; k < 4; k++) {
        float sc = g_scr1[cidx[k]], sh = g_shr1[cidx[k]];
        r_in[k] = fmaxf(base[ld[k]] * sc + sh, 0.f);
    }
#pragma unroll
    for (int k = 0; k < 6; k++) r_w[k] = (wld[k] >= 0) ? w[wld[k]] : 0.f;

    float acc[4][8];
#pragma unroll
    for (int bl = 0; bl < 4; bl++)
#pragma unroll
        for (int co = 0; co < 8; co++) acc[bl][co] = 0.f;

#pragma unroll 1
    for (int c0 = 0; c0 < 256; c0 += 4) {
#pragma unroll
        for (int k = 0; k < 4; k++) s_in[sidx[k]] = r_in[k];
#pragma unroll
        for (int k = 0; k < 6; k++) if (wld[k] >= 0) s_w[wst[k]] = r_w[k];
        __syncthreads();
        if (c0 + 4 < 256) {
            const float* src = base + (c0 + 4) * 49;
#pragma unroll
            for (int k = 0; k < 4; k++) {
                int ch = c0 + 4 + cidx[k];
                float sc = g_scr1[ch], sh = g_shr1[ch];
                r_in[k] = fmaxf(src[ld[k]] * sc + sh, 0.f);
            }
#pragma unroll
            for (int k = 0; k < 6; k++)
                if (wld[k] >= 0) r_w[k] = w[wld[k] + (c0 + 4) * 9];
        }
#pragma unroll
        for (int ci = 0; ci < 4; ci++) {
#pragma unroll
            for (int kh = 0; kh < 3; kh++) {
                float in[4][3];
#pragma unroll
                for (int bl = 0; bl < 4; bl++) {
                    int bs = bl * 432 + ci * 108 + (oh + kh) * 12 + ow;
                    in[bl][0] = s_in[bs];
                    in[bl][1] = s_in[bs + 1];
                    in[bl][2] = s_in[bs + 2];
                }
#pragma unroll
                for (int co = 0; co < 8; co++) {
                    const float4* wp = (const float4*)(s_w + (yq * 8 + co) * 48 + ci * 12 + kh * 4);
                    float4 wv = wp[0];
#pragma unroll
                    for (int bl = 0; bl < 4; bl++) {
                        acc[bl][co] += wv.x * in[bl][0];
                        acc[bl][co] += wv.y * in[bl][1];
                        acc[bl][co] += wv.z * in[bl][2];
                    }
                }
            }
        }
        __syncthreads();
    }
#pragma unroll
    for (int bl = 0; bl < 4; bl++)
#pragma unroll
        for (int co = 0; co < 8; co++)
            g_rc2[((b0 + bl) * 256 + cog * 32 + yq * 8 + co) * 49 + px] = acc[bl][co];
}

// ---------------------------------------------------------------------------
// shortcut 1x1 s2, smem staged, scalar. grid (8 cog, 64 b), block 196.
// ---------------------------------------------------------------------------
__global__ void __launch_bounds__(196) k_shortcut(const float* __restrict__ w) {
    __shared__ __align__(16) float s_c[128 * 49];
    __shared__ __align__(16) float s_wv[32 * 128];
    int b = blockIdx.y, cog = blockIdx.x;
    int tid = threadIdx.x;
    int px = tid % 49, yq = tid / 49;

    for (int t = tid; t < 128 * 49; t += 196) {
        int ci = t / 49, p = t - ci * 49;
        int oh = p / 7, ow = p - oh * 7;
        s_c[t] = g_pool2[(b * 128 + ci) * 196 + oh * 28 + ow * 2];
    }
    for (int t = tid; t < 32 * 128; t += 196) {
        int co = t >> 7, ci = t & 127;
        s_wv[t] = w[(cog * 32 + co) * 128 + ci];
    }
    __syncthreads();

    float acc[8];
#pragma unroll
    for (int co = 0; co < 8; co++) acc[co] = 0.f;
#pragma unroll 1
    for (int cp = 0; cp < 64; cp++) {
        float in0 = s_c[(2 * cp) * 49 + px];
        float in1 = s_c[(2 * cp + 1) * 49 + px];
#pragma unroll
        for (int co = 0; co < 8; co++) {
            float2 wv = *(const float2*)(s_wv + (yq * 8 + co) * 128 + 2 * cp);
            acc[co] += wv.x * in0;
            acc[co] += wv.y * in1;
        }
    }
#pragma unroll
    for (int co = 0; co < 8; co++)
        g_rs[(b * 256 + cog * 32 + yq * 8 + co) * 49 + px] = acc[co];
}

// ---------------------------------------------------------------------------
// tail: y = mean relu(bn(rc2)+bn(rs)); out = y M^T + b2
// ---------------------------------------------------------------------------
__global__ void k_tail(float* __restrict__ out) {
    __shared__ float s_y[256];
    int b = blockIdx.x, c = threadIdx.x;
    float sc2 = g_scr2[c], sh2 = g_shr2[c], scs = g_scs[c], shs = g_shs[c];
    const float* p2 = g_rc2 + (b * 256 + c) * 49;
    const float* ps = g_rs + (b * 256 + c) * 49;
    float s = 0.f;
    for (int p = 0; p < 49; p++) {
        float v = p2[p] * sc2 + sh2 + ps[p] * scs + shs;
        s += fmaxf(v, 0.f);
    }
    s_y[c] = s * (1.f / 49.f);
    __syncthreads();
    if (c < 50) {
        float acc = g_b2[c];
        for (int k = 0; k < 256; k++) acc += s_y[k] * g_M[c * 256 + k];
        out[b * 50 + c] = acc;
    }
}

// ---------------------------------------------------------------------------
// Tail fold (softmax attention collapses to 1x1 conv: wo@wv)
// ---------------------------------------------------------------------------
__global__ void k_foldT(const float* __restrict__ fcw, const float* __restrict__ wo) {
    int idx = blockIdx.x * 256 + threadIdx.x;
    if (idx >= 50 * 1024) return;
    int i = idx / 1024, j = idx - i * 1024;
    float s = 0.f;
    for (int c = 0; c < 256; c++) s += fcw[i * 256 + c] * wo[c * 1024 + j];
    g_T[idx] = s;
}

__global__ void k_foldM(const float* __restrict__ wv) {
    int idx = blockIdx.x * 256 + threadIdx.x;
    if (idx >= 50 * 256) return;
    int i = idx / 256, c = idx - i * 256;
    float s = 0.f;
    for (int j = 0; j < 1024; j++) s += g_T[i * 1024 + j] * wv[j * 256 + c];
    g_M[idx] = s;
}

__global__ void k_foldb(const float* __restrict__ fcw, const float* __restrict__ bo,
                        const float* __restrict__ fcb) {
    int i = threadIdx.x;
    if (i >= 50) return;
    float s = 0.f;
    for (int c = 0; c < 256; c++) s += fcw[i * 256 + c] * bo[c];
    g_b2[i] = s + fcb[i];
}

// ---------------------------------------------------------------------------
// Launch (k_conv1 is the 4th launch -> ncu profile target)
// ---------------------------------------------------------------------------
extern "C" void kernel_launch(void* const* d_in, const int* in_sizes, int n_in,
                              void* d_out, int out_size) {
    const float* imgs   = (const float*)d_in[0];
    const float* a1f1   = (const float*)d_in[1];
    const float* a1f2   = (const float*)d_in[2];
    const float* a1f2b  = (const float*)d_in[3];
    const float* dy1    = (const float*)d_in[4];
    const float* bn1g   = (const float*)d_in[5];
    const float* bn1b   = (const float*)d_in[6];
    const float* a2f1   = (const float*)d_in[7];
    const float* a2f2   = (const float*)d_in[8];
    const float* a2f2b  = (const float*)d_in[9];
    const float* dy2    = (const float*)d_in[10];
    const float* bn2g   = (const float*)d_in[11];
    const float* bn2b   = (const float*)d_in[12];
    const float* rc1w   = (const float*)d_in[13];
    const float* rbn1g  = (const float*)d_in[14];
    const float* rbn1b  = (const float*)d_in[15];
    const float* rc2w   = (const float*)d_in[16];
    const float* rbn2g  = (const float*)d_in[17];
    const float* rbn2b  = (const float*)d_in[18];
    const float* rsw    = (const float*)d_in[19];
    const float* rbnsg  = (const float*)d_in[20];
    const float* rbnsb  = (const float*)d_in[21];
    const float* wv     = (const float*)d_in[24];
    const float* wo     = (const float*)d_in[25];
    const float* bo     = (const float*)d_in[26];
    const float* fcw    = (const float*)d_in[27];
    const float* fcb    = (const float*)d_in[28];
    float* out = (float*)d_out;
    (void)in_sizes; (void)n_in; (void)out_size;

    static int smem_set = 0;
    if (!smem_set) {
        cudaFuncSetAttribute(k_conv1, cudaFuncAttributeMaxDynamicSharedMemorySize,
                             CONV1_SMEM);
        cudaFuncSetAttribute(k_conv1, cudaFuncAttributePreferredSharedMemoryCarveout,
                             100);
        smem_set = 1;
    }

    // stage 1 front (block 0 of pooled1 zeroes accumulators)
    k_pooled1<<<192, 256>>>(imgs);
    k_attn1<<<1, 64>>>(a1f1, a1f2, a1f2b);
    k_w1agg<<<(BB * 10752 + 255) / 256, 256>>>(dy1);
    k_conv1<<<dim3(49, BB), 256, CONV1_SMEM>>>(imgs);  // 4th (profiled)

    // tail fold (independent)
    k_foldT<<<200, 256>>>(fcw, wo);
    k_foldM<<<50, 256>>>(wv);
    k_foldb<<<1, 64>>>(fcw, bo, fcb);

    k_bnscale<<<1, 64>>>(bn1g, bn1b, 802816.f, 0, 64);
    k_bnpool1<<<dim3(13, 64, BB), 256>>>();

    // stage 2
    k_attn2<<<1, 64>>>(a2f1, a2f2, a2f2b);
    k_w2agg<<<(BB * 73728 + 255) / 256, 256>>>(dy2);
    k_conv2<<<dim3(8, BB), 224>>>();
    k_bnscale<<<1, 128>>>(bn2g, bn2b, 50176.f, 1, 128);
    k_bnpool2<<<dim3(128, BB), 196>>>();

    // residual block
    k_resconv1<<<dim3(8, BB / 4), 196>>>(rc1w);
    k_shortcut<<<dim3(8, BB), 196>>>(rsw);
    k_chstats<<<256, 128>>>(0);
    k_bnscale<<<1, 256>>>(rbn1g, rbn1b, 3136.f, 2, 256);
    k_resconv2<<<dim3(8, BB / 4), 196>>>(rc2w);
    k_chstats2<<<256, 128>>>();
    k_bnscale<<<1, 256>>>(rbn2g, rbn2b, 3136.f, 3, 256);
    k_bnscale<<<1, 256>>>(rbnsg, rbnsb, 3136.f, 4, 256);

    k_tail<<<64, 256>>>(out);
}

// round 10
// speedup vs baseline: 2.4554x; 1.0409x over previous
#include <cuda_runtime.h>
#include <math.h>

#define BB 64

// ---------------------------------------------------------------------------
// Scratch
// ---------------------------------------------------------------------------
__device__ float g_pooled1[BB * 3];
__device__ float g_attn1[BB * 8];
__device__ float g_w1t[BB * 64 * 168];           // tf32-rounded, padded [co][ci][kh][8]
__device__ float g_conv1[BB * 64 * 112 * 112];
__device__ float g_pool1[BB * 64 * 56 * 56];
__device__ float g_pooled2[BB * 64];
__device__ float g_attn2[BB * 8];
__device__ float g_w2[BB * 128 * 64 * 9];
__device__ float g_conv2[BB * 128 * 28 * 28];
__device__ float g_pool2[BB * 128 * 14 * 14];
__device__ float g_rc1[BB * 256 * 49];
__device__ float g_rc2[BB * 256 * 49];
__device__ float g_rs[BB * 256 * 49];

__device__ float g_sum1[64],  g_sq1[64],  g_sc1[64],  g_sh1[64];
__device__ float g_sum2[128], g_sq2[128], g_sc2[128], g_sh2[128];
__device__ float g_scr1[256], g_shr1[256];
__device__ float g_scr2[256], g_shr2[256];
__device__ float g_scs[256],  g_shs[256];

__device__ float g_T[50 * 1024];
__device__ float g_M[50 * 256];
__device__ float g_b2[50];

// ---------------------------------------------------------------------------
// bn scale/shift (stages 0,1 only; residual stages folded into stats kernels)
// ---------------------------------------------------------------------------
__global__ void k_bnscale(const float* __restrict__ g, const float* __restrict__ be,
                          float cnt, int stage, int C) {
    int c = blockIdx.x * blockDim.x + threadIdx.x;
    if (c >= C) return;
    float *su, *sq, *sc, *sh;
    if (stage == 0) { su = g_sum1; sq = g_sq1; sc = g_sc1; sh = g_sh1; }
    else            { su = g_sum2; sq = g_sq2; sc = g_sc2; sh = g_sh2; }
    float m = su[c] / cnt;
    float v = sq[c] / cnt - m * m;
    float s = g[c] * rsqrtf(v + 1e-5f);
    sc[c] = s;
    sh[c] = be[c] - m * s;
}

// per-channel stats of rc1 + finalize scale/shift in-kernel
__global__ void k_chstats(const float* __restrict__ g, const float* __restrict__ be) {
    int c = blockIdx.x;
    float s = 0.f, q = 0.f;
    for (int t = threadIdx.x; t < BB * 49; t += 128) {
        int b = t / 49, p = t - b * 49;
        float v = g_rc1[(b * 256 + c) * 49 + p];
        s += v; q += v * v;
    }
    for (int o = 16; o; o >>= 1) {
        s += __shfl_down_sync(0xffffffffu, s, o);
        q += __shfl_down_sync(0xffffffffu, q, o);
    }
    __shared__ float rs[4], rq[4];
    int w = threadIdx.x >> 5;
    if ((threadIdx.x & 31) == 0) { rs[w] = s; rq[w] = q; }
    __syncthreads();
    if (threadIdx.x == 0) {
        float su = rs[0] + rs[1] + rs[2] + rs[3];
        float sq = rq[0] + rq[1] + rq[2] + rq[3];
        float m = su * (1.f / 3136.f);
        float v = sq * (1.f / 3136.f) - m * m;
        float sc = g[c] * rsqrtf(v + 1e-5f);
        g_scr1[c] = sc;
        g_shr1[c] = be[c] - m * sc;
    }
}

// stats of rc2 AND rs + finalize both scale/shifts
__global__ void k_chstats2(const float* __restrict__ g2, const float* __restrict__ be2,
                           const float* __restrict__ gs, const float* __restrict__ bes) {
    int c = blockIdx.x;
    float s2 = 0.f, q2 = 0.f, ss = 0.f, qs = 0.f;
    for (int t = threadIdx.x; t < BB * 49; t += 128) {
        int b = t / 49, p = t - b * 49;
        float v = g_rc2[(b * 256 + c) * 49 + p];
        s2 += v; q2 += v * v;
        float u = g_rs[(b * 256 + c) * 49 + p];
        ss += u; qs += u * u;
    }
    for (int o = 16; o; o >>= 1) {
        s2 += __shfl_down_sync(0xffffffffu, s2, o);
        q2 += __shfl_down_sync(0xffffffffu, q2, o);
        ss += __shfl_down_sync(0xffffffffu, ss, o);
        qs += __shfl_down_sync(0xffffffffu, qs, o);
    }
    __shared__ float r[4][4];
    int w = threadIdx.x >> 5;
    if ((threadIdx.x & 31) == 0) { r[w][0] = s2; r[w][1] = q2; r[w][2] = ss; r[w][3] = qs; }
    __syncthreads();
    if (threadIdx.x == 0) {
        float su2 = r[0][0] + r[1][0] + r[2][0] + r[3][0];
        float sq2 = r[0][1] + r[1][1] + r[2][1] + r[3][1];
        float sus = r[0][2] + r[1][2] + r[2][2] + r[3][2];
        float sqs = r[0][3] + r[1][3] + r[2][3] + r[3][3];
        float m2 = su2 * (1.f / 3136.f);
        float v2 = sq2 * (1.f / 3136.f) - m2 * m2;
        float c2 = g2[c] * rsqrtf(v2 + 1e-5f);
        g_scr2[c] = c2;
        g_shr2[c] = be2[c] - m2 * c2;
        float ms = sus * (1.f / 3136.f);
        float vs = sqs * (1.f / 3136.f) - ms * ms;
        float cs = gs[c] * rsqrtf(vs + 1e-5f);
        g_scs[c] = cs;
        g_shs[c] = bes[c] - ms * cs;
    }
}

// ---------------------------------------------------------------------------
// Stage-1 attention
// ---------------------------------------------------------------------------
__global__ void k_pooled1(const float* __restrict__ imgs) {
    int bc = blockIdx.x;
    int tid = threadIdx.x;
    if (bc == 0) {
        for (int i = tid; i < BB * 64; i += 256) g_pooled2[i] = 0.f;
        if (tid < 64)  { g_sum1[tid] = 0.f; g_sq1[tid] = 0.f; }
        if (tid < 128) { g_sum2[tid] = 0.f; g_sq2[tid] = 0.f; }
    }
    const float* p = imgs + (long)bc * 50176;
    float s = 0.f;
    for (int i = tid; i < 50176; i += 256) s += p[i];
    __shared__ float red[256];
    red[tid] = s; __syncthreads();
    for (int o = 128; o; o >>= 1) { if (tid < o) red[tid] += red[tid + o]; __syncthreads(); }
    if (tid == 0) g_pooled1[bc] = red[0] * (1.f / 50176.f);
}

__global__ void k_attn1(const float* __restrict__ fc1, const float* __restrict__ fc2,
                        const float* __restrict__ fc2b) {
    int b = threadIdx.x;
    if (b >= BB) return;
    float p[3];
    for (int c = 0; c < 3; c++) p[c] = g_pooled1[b * 3 + c];
    float h[8];
    for (int j = 0; j < 8; j++) {
        float s = 0.f;
        for (int c = 0; c < 3; c++) s += p[c] * fc1[j * 3 + c];
        h[j] = fmaxf(s, 0.f);
    }
    float lg[8], mx = -1e30f;
    for (int k = 0; k < 8; k++) {
        float s = fc2b[k];
        for (int j = 0; j < 8; j++) s += h[j] * fc2[k * 8 + j];
        lg[k] = s; mx = fmaxf(mx, s);
    }
    float den = 0.f;
    for (int k = 0; k < 8; k++) { lg[k] = expf(lg[k] - mx); den += lg[k]; }
    float inv = 1.f / den;
    for (int k = 0; k < 8; k++) g_attn1[b * 8 + k] = lg[k] * inv;
}

// aggregate + tf32-round + pad into [b][co][ci][kh][8] (kw slot 7 = 0)
__global__ void k_w1agg(const float* __restrict__ dy1) {
    int idx = blockIdx.x * 256 + threadIdx.x;
    if (idx >= BB * 10752) return;
    int b = idx / 10752, r = idx - b * 10752;
    int co = r / 168, r2 = r - co * 168;
    int ci = r2 / 56, r3 = r2 - ci * 56;
    int kh = r3 >> 3, kw = r3 & 7;
    float s = 0.f;
    if (kw < 7) {
        int i = co * 147 + ci * 49 + kh * 7 + kw;
#pragma unroll
        for (int k = 0; k < 8; k++) s += g_attn1[b * 8 + k] * dy1[k * 9408 + i];
    }
    unsigned tv; asm("cvt.rna.tf32.f32 %0, %1;" : "=r"(tv) : "f"(s));
    g_w1t[idx] = __uint_as_float(tv);
}

// ---------------------------------------------------------------------------
// Conv1 via tf32 mma.sync implicit GEMM (proven R9 form, unchanged).
// ---------------------------------------------------------------------------
#define W_STRIDE 172
extern __shared__ float smemBuf[];
__global__ void __launch_bounds__(256, 2) k_conv1(const float* __restrict__ imgs) {
    float* s_in = smemBuf;                   // [ci][37][64] tf32 bits
    float* s_w = smemBuf + 7104;             // [co][W_STRIDE]
    float* s_stat = smemBuf + 7104 + 64 * W_STRIDE;
    int b = blockIdx.y;
    int tr = blockIdx.x / 7, tc = blockIdx.x - tr * 7;
    int oh0 = tr * 16, ow0 = tc * 16;
    int tid = threadIdx.x;

    if (tid < 128) s_stat[tid] = 0.f;

    const float* wt = g_w1t + b * 10752;
    for (int t = tid; t < 10752; t += 256)
        s_w[t + (t / 168) * 4] = wt[t];

    int ih0 = 2 * oh0 - 3, iw0 = 2 * ow0 - 3;
#pragma unroll 1
    for (int ci = 0; ci < 3; ci++) {
        const float* ip = imgs + (long)(b * 3 + ci) * 50176;
        for (int u = tid; u < 2368; u += 256) {
            int r = u >> 6, c = u & 63;
            if (c < 38) {
                int ih = ih0 + r, iw = iw0 + c;
                float v = 0.f;
                if ((unsigned)ih < 224u && (unsigned)iw < 224u)
                    v = ip[ih * 224 + iw];
                unsigned tv; asm("cvt.rna.tf32.f32 %0, %1;" : "=r"(tv) : "f"(v));
                s_in[ci * 2368 + u] = __uint_as_float(tv);
            }
        }
    }
    __syncthreads();

    int w = tid >> 5, lane = tid & 31;
    int gid = lane >> 2, tig = lane & 3;

    float acc[2][8][4];
#pragma unroll
    for (int mt = 0; mt < 2; mt++)
#pragma unroll
        for (int nt = 0; nt < 8; nt++)
#pragma unroll
            for (int k = 0; k < 4; k++) acc[mt][nt][k] = 0.f;

    int bq[8];
#pragma unroll
    for (int nt = 0; nt < 8; nt++) bq[nt] = (nt * 8 + gid) * W_STRIDE + tig;
    int abase0 = (2 * (2 * w + 0)) * 64 + 2 * gid + tig;
    int abase1 = (2 * (2 * w + 1)) * 64 + 2 * gid + tig;

#pragma unroll 1
    for (int ci = 0; ci < 3; ci++) {
#pragma unroll
        for (int kh = 0; kh < 7; kh++) {
            int wbase = ci * 56 + kh * 8;
            int aoff = ci * 2368 + kh * 64;
            unsigned bf0[8], bf1[8];
#pragma unroll
            for (int nt = 0; nt < 8; nt++) {
                bf0[nt] = __float_as_uint(s_w[bq[nt] + wbase]);
                bf1[nt] = __float_as_uint(s_w[bq[nt] + wbase + 4]);
            }
#pragma unroll
            for (int mt = 0; mt < 2; mt++) {
                int a = aoff + (mt ? abase1 : abase0);
                unsigned a0 = __float_as_uint(s_in[a]);
                unsigned a1 = __float_as_uint(s_in[a + 16]);
                unsigned a2 = __float_as_uint(s_in[a + 4]);
                unsigned a3 = __float_as_uint(s_in[a + 20]);
#pragma unroll
                for (int nt = 0; nt < 8; nt++) {
                    asm volatile(
                        "mma.sync.aligned.m16n8k8.row.col.f32.tf32.tf32.f32 "
                        "{%0,%1,%2,%3}, {%4,%5,%6,%7}, {%8,%9}, {%0,%1,%2,%3};"
                        : "+f"(acc[mt][nt][0]), "+f"(acc[mt][nt][1]),
                          "+f"(acc[mt][nt][2]), "+f"(acc[mt][nt][3])
                        : "r"(a0), "r"(a1), "r"(a2), "r"(a3),
                          "r"(bf0[nt]), "r"(bf1[nt]));
                }
            }
        }
    }

#pragma unroll
    for (int mt = 0; mt < 2; mt++) {
        int oh = oh0 + 2 * w + mt;
#pragma unroll
        for (int nt = 0; nt < 8; nt++) {
            int co = nt * 8 + 2 * tig;
            long base0 = ((long)(b * 64 + co)) * 12544 + oh * 112 + ow0;
            g_conv1[base0 + gid] = acc[mt][nt][0];
            g_conv1[base0 + 12544 + gid] = acc[mt][nt][1];
            g_conv1[base0 + gid + 8] = acc[mt][nt][2];
            g_conv1[base0 + 12544 + gid + 8] = acc[mt][nt][3];
        }
    }

#pragma unroll
    for (int nt = 0; nt < 8; nt++) {
        float s0 = 0.f, q0 = 0.f, s1 = 0.f, q1 = 0.f;
#pragma unroll
        for (int mt = 0; mt < 2; mt++) {
            float v;
            v = acc[mt][nt][0]; s0 += v; q0 += v * v;
            v = acc[mt][nt][2]; s0 += v; q0 += v * v;
            v = acc[mt][nt][1]; s1 += v; q1 += v * v;
            v = acc[mt][nt][3]; s1 += v; q1 += v * v;
        }
#pragma unroll
        for (int o = 16; o >= 4; o >>= 1) {
            s0 += __shfl_xor_sync(0xffffffffu, s0, o);
            q0 += __shfl_xor_sync(0xffffffffu, q0, o);
            s1 += __shfl_xor_sync(0xffffffffu, s1, o);
            q1 += __shfl_xor_sync(0xffffffffu, q1, o);
        }
        if (gid == 0) {
            int co = nt * 8 + 2 * tig;
            atomicAdd(&s_stat[co], s0);
            atomicAdd(&s_stat[64 + co], q0);
            atomicAdd(&s_stat[co + 1], s1);
            atomicAdd(&s_stat[64 + co + 1], q1);
        }
    }
    __syncthreads();
    if (tid < 64) {
        atomicAdd(&g_sum1[tid], s_stat[tid]);
        atomicAdd(&g_sq1[tid], s_stat[64 + tid]);
    }
}
#define CONV1_SMEM ((7104 + 64 * W_STRIDE + 128) * 4)

// ---------------------------------------------------------------------------
// BN1 + maxpool3 s2 p1: 112->56, plane-tiled. One block per (c,b).
// Stage the full 112x112 plane in dynamic smem (coalesced), pool from smem.
// ---------------------------------------------------------------------------
extern __shared__ float s_plane[];
__global__ void __launch_bounds__(256) k_bnpool1() {
    int c = blockIdx.x, b = blockIdx.y;
    int tid = threadIdx.x;
    const float* ip = g_conv1 + (long)(b * 64 + c) * 12544;
#pragma unroll
    for (int k = 0; k < 49; k++) s_plane[tid + 256 * k] = ip[tid + 256 * k];
    __syncthreads();

    float sc = g_sc1[c], sh = g_sh1[c];
    float* op = g_pool1 + (b * 64 + c) * 3136;
    float s = 0.f;
#pragma unroll
    for (int k = 0; k < 13; k++) {
        int p = tid + 256 * k;
        if (p < 3136) {
            int oh = p / 56, ow = p - oh * 56;
            float m = -1e30f;
#pragma unroll
            for (int r = 0; r < 3; r++) {
                int ih = 2 * oh - 1 + r;
                if ((unsigned)ih >= 112u) continue;
#pragma unroll
                for (int cc = 0; cc < 3; cc++) {
                    int iw = 2 * ow - 1 + cc;
                    if ((unsigned)iw >= 112u) continue;
                    m = fmaxf(m, s_plane[ih * 112 + iw] * sc + sh);
                }
            }
            op[p] = m;
            s += m;
        }
    }
    for (int o = 16; o; o >>= 1) s += __shfl_down_sync(0xffffffffu, s, o);
    __shared__ float s_red;
    if (tid == 0) s_red = 0.f;
    __syncthreads();
    if ((tid & 31) == 0) atomicAdd(&s_red, s);
    __syncthreads();
    if (tid == 0) atomicAdd(&g_pooled2[b * 64 + c], s_red);
}
#define POOL1_SMEM (12544 * 4)

// ---------------------------------------------------------------------------
// Stage-2 attention
// ---------------------------------------------------------------------------
__global__ void k_attn2(const float* __restrict__ fc1, const float* __restrict__ fc2,
                        const float* __restrict__ fc2b) {
    int b = threadIdx.x;
    if (b >= BB) return;
    float h[17];
    for (int j = 0; j < 17; j++) {
        float s = 0.f;
        for (int c = 0; c < 64; c++)
            s += (g_pooled2[b * 64 + c] * (1.f / 3136.f)) * fc1[j * 64 + c];
        h[j] = fmaxf(s, 0.f);
    }
    float lg[8], mx = -1e30f;
    for (int k = 0; k < 8; k++) {
        float s = fc2b[k];
        for (int j = 0; j < 17; j++) s += h[j] * fc2[k * 17 + j];
        lg[k] = s; mx = fmaxf(mx, s);
    }
    float den = 0.f;
    for (int k = 0; k < 8; k++) { lg[k] = expf(lg[k] - mx); den += lg[k]; }
    float inv = 1.f / den;
    for (int k = 0; k < 8; k++) g_attn2[b * 8 + k] = lg[k] * inv;
}

__global__ void k_w2agg(const float* __restrict__ dy2) {
    int idx = blockIdx.x * 256 + threadIdx.x;
    if (idx >= BB * 73728) return;
    int b = idx / 73728, i = idx - b * 73728;
    float s = 0.f;
#pragma unroll
    for (int k = 0; k < 8; k++) s += g_attn2[b * 8 + k] * dy2[k * 73728 + i];
    g_w2[idx] = s;
}

// ---------------------------------------------------------------------------
// Conv2: 64->128, 3x3 s2 p1: 56->28. 16 co/block, register double-buffer
// pipeline. grid (8 cog, 64 b), 224 thr.
// ---------------------------------------------------------------------------
__global__ void __launch_bounds__(224) k_conv2() {
    __shared__ __align__(16) float s_in[2 * 3364];
    __shared__ __align__(16) float s_w[16 * 2 * 3 * 4];
    __shared__ float s_stat[32];
    int b = blockIdx.y, cog = blockIdx.x;
    int tid = threadIdx.x;
    int tx = tid % 28, tyq = tid / 28;

    for (int t = tid; t < 2 * 3364; t += 224) s_in[t] = 0.f;
    for (int t = tid; t < 384; t += 224) s_w[t] = 0.f;
    if (tid < 32) s_stat[tid] = 0.f;

    int sidx[28];
#pragma unroll
    for (int k = 0; k < 28; k++) {
        int t = tid + 224 * k;
        int ci = t / 3136, p = t - ci * 3136;
        int r = p / 56, c = p - r * 56;
        sidx[k] = ci * 3364 + (r + 1) * 58 + (c + 1);
    }
    int w_ld0, w_st0, w_ld1, w_st1;
    {
        int t = tid;
        int co = t / 18, rem = t - co * 18, ci = rem / 9, k9 = rem - ci * 9;
        int kh = k9 / 3, kw = k9 - kh * 3;
        w_ld0 = (cog * 16 + co) * 576 + ci * 9 + k9;
        w_st0 = co * 24 + ci * 12 + kh * 4 + kw;
        t = tid + 224;
        co = t / 18; rem = t - co * 18; ci = rem / 9; k9 = rem - ci * 9;
        kh = k9 / 3; kw = k9 - kh * 3;
        w_ld1 = (cog * 16 + co) * 576 + ci * 9 + k9;
        w_st1 = co * 24 + ci * 12 + kh * 4 + kw;
    }
    __syncthreads();

    const float* base = g_pool1 + (long)(b * 64) * 3136;
    const float* wbase = g_w2 + b * 73728;
    float r_in[28], r_w0, r_w1 = 0.f;
#pragma unroll
    for (int k = 0; k < 28; k++) r_in[k] = base[tid + 224 * k];
    r_w0 = wbase[w_ld0];
    if (tid < 64) r_w1 = wbase[w_ld1];

    float acc[4][16];
#pragma unroll
    for (int j = 0; j < 4; j++)
#pragma unroll
        for (int co = 0; co < 16; co++) acc[j][co] = 0.f;

#pragma unroll 1
    for (int c0 = 0; c0 < 64; c0 += 2) {
#pragma unroll
        for (int k = 0; k < 28; k++) s_in[sidx[k]] = r_in[k];
        s_w[w_st0] = r_w0;
        if (tid < 64) s_w[w_st1] = r_w1;
        __syncthreads();
        if (c0 + 2 < 64) {
            const float* src = base + (c0 + 2) * 3136;
#pragma unroll
            for (int k = 0; k < 28; k++) r_in[k] = src[tid + 224 * k];
            r_w0 = wbase[w_ld0 + (c0 + 2) * 9];
            if (tid < 64) r_w1 = wbase[w_ld1 + (c0 + 2) * 9];
        }
        if (tid < 196) {
#pragma unroll
            for (int ci = 0; ci < 2; ci++) {
#pragma unroll
                for (int kh = 0; kh < 3; kh++) {
                    int rbase = ci * 3364 + (8 * tyq + kh) * 58 + 2 * tx;
                    float in[4][4];
#pragma unroll
                    for (int j = 0; j < 4; j++) {
                        const float2* rp = (const float2*)(s_in + rbase + 116 * j);
                        float2 v0 = rp[0], v1 = rp[1];
                        in[j][0] = v0.x; in[j][1] = v0.y; in[j][2] = v1.x; in[j][3] = v1.y;
                    }
#pragma unroll
                    for (int co = 0; co < 16; co++) {
                        const float4* wp = (const float4*)(s_w + co * 24 + ci * 12 + kh * 4);
                        float4 w = wp[0];
#pragma unroll
                        for (int j = 0; j < 4; j++) {
                            acc[j][co] += w.x * in[j][0];
                            acc[j][co] += w.y * in[j][1];
                            acc[j][co] += w.z * in[j][2];
                        }
                    }
                }
            }
        }
        __syncthreads();
    }

    if (tid < 196) {
#pragma unroll
        for (int co = 0; co < 16; co++) {
            int cb = (b * 128 + cog * 16 + co) * 784;
#pragma unroll
            for (int j = 0; j < 4; j++) {
                int oh = 4 * tyq + j;
                g_conv2[cb + oh * 28 + tx] = acc[j][co];
            }
        }
    }
#pragma unroll
    for (int co = 0; co < 16; co++) {
        float s = acc[0][co] + acc[1][co] + acc[2][co] + acc[3][co];
        float q = acc[0][co] * acc[0][co] + acc[1][co] * acc[1][co]
                + acc[2][co] * acc[2][co] + acc[3][co] * acc[3][co];
        for (int o = 16; o; o >>= 1) {
            s += __shfl_down_sync(0xffffffffu, s, o);
            q += __shfl_down_sync(0xffffffffu, q, o);
        }
        if ((tid & 31) == 0) { atomicAdd(&s_stat[co], s); atomicAdd(&s_stat[16 + co], q); }
    }
    __syncthreads();
    if (tid < 16) {
        atomicAdd(&g_sum2[cog * 16 + tid], s_stat[tid]);
        atomicAdd(&g_sq2[cog * 16 + tid], s_stat[16 + tid]);
    }
}

// ---------------------------------------------------------------------------
// BN2 + maxpool3 s2 p1: 28->14
// ---------------------------------------------------------------------------
__global__ void k_bnpool2() {
    int b = blockIdx.y, c = blockIdx.x;
    int p = threadIdx.x;
    if (p >= 196) return;
    int oh = p / 14, ow = p - oh * 14;
    float sc = g_sc2[c], sh = g_sh2[c];
    const float* ip = g_conv2 + (b * 128 + c) * 784;
    float m = -1e30f;
#pragma unroll
    for (int r = 0; r < 3; r++) {
        int ih = 2 * oh - 1 + r;
        if ((unsigned)ih >= 28u) continue;
#pragma unroll
        for (int cc = 0; cc < 3; cc++) {
            int iw = 2 * ow - 1 + cc;
            if ((unsigned)iw >= 28u) continue;
            m = fmaxf(m, ip[ih * 28 + iw] * sc + sh);
        }
    }
    g_pool2[(b * 128 + c) * 196 + p] = m;
}

// ---------------------------------------------------------------------------
// resconv1: 128->256 3x3 s2, 14->7. 4 batches/block, pipelined staging.
// ---------------------------------------------------------------------------
__global__ void __launch_bounds__(196) k_resconv1(const float* __restrict__ w) {
    __shared__ __align__(16) float s_in[4 * 1080];
    __shared__ __align__(16) float s_w[32 * 48];
    int bq = blockIdx.y, cog = blockIdx.x;
    int b0 = bq * 4;
    int tid = threadIdx.x;
    int px = tid % 49, yq = tid / 49;
    int oh = px / 7, ow = px - oh * 7;

    for (int t = tid; t < 4320; t += 196) s_in[t] = 0.f;
    for (int t = tid; t < 1536; t += 196) s_w[t] = 0.f;

    int ld[16], sidx[16];
#pragma unroll
    for (int k = 0; k < 16; k++) {
        int t = tid + 196 * k;
        int bl = t / 784, rem = t - bl * 784;
        int ci = rem / 196, p = rem - ci * 196;
        int r = p / 14, c = p - r * 14;
        ld[k] = bl * 25088 + rem;
        sidx[k] = bl * 1080 + ci * 270 + (r + 1) * 18 + (c + 1);
    }
    int wld[6], wst[6];
#pragma unroll
    for (int k = 0; k < 6; k++) {
        int t = tid + 196 * k;
        if (t < 1152) {
            int co = t / 36, rem = t - co * 36;
            int ci = rem / 9, k9 = rem - ci * 9;
            int kh = k9 / 3, kw = k9 - kh * 3;
            wld[k] = (cog * 32 + co) * 1152 + ci * 9 + k9;
            wst[k] = co * 48 + ci * 12 + kh * 4 + kw;
        } else { wld[k] = -1; wst[k] = 1536 - 1; }
    }
    __syncthreads();

    const float* base = g_pool2 + (long)(b0 * 128) * 196;
    float r_in[16], r_w[6];
#pragma unroll
    for (int k = 0; k < 16; k++) r_in[k] = base[ld[k]];
#pragma unroll
    for (int k = 0; k < 6; k++) r_w[k] = (wld[k] >= 0) ? w[wld[k]] : 0.f;

    float acc[4][8];
#pragma unroll
    for (int bl = 0; bl < 4; bl++)
#pragma unroll
        for (int co = 0; co < 8; co++) acc[bl][co] = 0.f;

#pragma unroll 1
    for (int c0 = 0; c0 < 128; c0 += 4) {
#pragma unroll
        for (int k = 0; k < 16; k++) s_in[sidx[k]] = r_in[k];
#pragma unroll
        for (int k = 0; k < 6; k++) if (wld[k] >= 0) s_w[wst[k]] = r_w[k];
        __syncthreads();
        if (c0 + 4 < 128) {
            const float* src = base + (c0 + 4) * 196;
#pragma unroll
            for (int k = 0; k < 16; k++) r_in[k] = src[ld[k]];
#pragma unroll
            for (int k = 0; k < 6; k++)
                if (wld[k] >= 0) r_w[k] = w[wld[k] + (c0 + 4) * 9];
        }
#pragma unroll
        for (int ci = 0; ci < 4; ci++) {
#pragma unroll
            for (int kh = 0; kh < 3; kh++) {
                float in[4][3];
#pragma unroll
                for (int bl = 0; bl < 4; bl++) {
                    int bs = bl * 1080 + ci * 270 + (2 * oh + kh) * 18 + 2 * ow;
                    in[bl][0] = s_in[bs];
                    in[bl][1] = s_in[bs + 1];
                    in[bl][2] = s_in[bs + 2];
                }
#pragma unroll
                for (int co = 0; co < 8; co++) {
                    const float4* wp = (const float4*)(s_w + (yq * 8 + co) * 48 + ci * 12 + kh * 4);
                    float4 wv = wp[0];
#pragma unroll
                    for (int bl = 0; bl < 4; bl++) {
                        acc[bl][co] += wv.x * in[bl][0];
                        acc[bl][co] += wv.y * in[bl][1];
                        acc[bl][co] += wv.z * in[bl][2];
                    }
                }
            }
        }
        __syncthreads();
    }
#pragma unroll
    for (int bl = 0; bl < 4; bl++)
#pragma unroll
        for (int co = 0; co < 8; co++)
            g_rc1[((b0 + bl) * 256 + cog * 32 + yq * 8 + co) * 49 + px] = acc[bl][co];
}

// ---------------------------------------------------------------------------
// resconv2: 256->256 3x3 s1, 7x7. bn+relu at register-load time, pipelined.
// ---------------------------------------------------------------------------
__global__ void __launch_bounds__(196) k_resconv2(const float* __restrict__ w) {
    __shared__ __align__(16) float s_in[4 * 432];
    __shared__ __align__(16) float s_w[32 * 48];
    int bq = blockIdx.y, cog = blockIdx.x;
    int b0 = bq * 4;
    int tid = threadIdx.x;
    int px = tid % 49, yq = tid / 49;
    int oh = px / 7, ow = px - oh * 7;

    for (int t = tid; t < 1728; t += 196) s_in[t] = 0.f;
    for (int t = tid; t < 1536; t += 196) s_w[t] = 0.f;

    int ld[4], sidx[4], cidx[4];
#pragma unroll
    for (int k = 0; k < 4; k++) {
        int t = tid + 196 * k;
        int bl = t / 196, rem = t - bl * 196;
        int ci = rem / 49, p = rem - ci * 49;
        int r = p / 7, c = p - r * 7;
        ld[k] = bl * 12544 + rem;
        sidx[k] = bl * 432 + ci * 108 + (r + 1) * 12 + (c + 1);
        cidx[k] = ci;
    }
    int wld[6], wst[6];
#pragma unroll
    for (int k = 0; k < 6; k++) {
        int t = tid + 196 * k;
        if (t < 1152) {
            int co = t / 36, rem = t - co * 36;
            int ci = rem / 9, k9 = rem - ci * 9;
            int kh = k9 / 3, kw = k9 - kh * 3;
            wld[k] = (cog * 32 + co) * 2304 + ci * 9 + k9;
            wst[k] = co * 48 + ci * 12 + kh * 4 + kw;
        } else { wld[k] = -1; wst[k] = 0; }
    }
    __syncthreads();

    const float* base = g_rc1 + (long)(b0 * 256) * 49;
    float r_in[4], r_w[6];
#pragma unroll
    for (int k = 0; k < 4; k++) {
        float sc = g_scr1[cidx[k]], sh = g_shr1[cidx[k]];
        r_in[k] = fmaxf(base[ld[k]] * sc + sh, 0.f);
    }
#pragma unroll
    for (int k = 0; k < 6; k++) r_w[k] = (wld[k] >= 0) ? w[wld[k]] : 0.f;

    float acc[4][8];
#pragma unroll
    for (int bl = 0; bl < 4; bl++)
#pragma unroll
        for (int co = 0; co < 8; co++) acc[bl][co] = 0.f;

#pragma unroll 1
    for (int c0 = 0; c0 < 256; c0 += 4) {
#pragma unroll
        for (int k = 0; k < 4; k++) s_in[sidx[k]] = r_in[k];
#pragma unroll
        for (int k = 0; k < 6; k++) if (wld[k] >= 0) s_w[wst[k]] = r_w[k];
        __syncthreads();
        if (c0 + 4 < 256) {
            const float* src = base + (c0 + 4) * 49;
#pragma unroll
            for (int k = 0; k < 4; k++) {
                int ch = c0 + 4 + cidx[k];
                float sc = g_scr1[ch], sh = g_shr1[ch];
                r_in[k] = fmaxf(src[ld[k]] * sc + sh, 0.f);
            }
#pragma unroll
            for (int k = 0; k < 6; k++)
                if (wld[k] >= 0) r_w[k] = w[wld[k] + (c0 + 4) * 9];
        }
#pragma unroll
        for (int ci = 0; ci < 4; ci++) {
#pragma unroll
            for (int kh = 0; kh < 3; kh++) {
                float in[4][3];
#pragma unroll
                for (int bl = 0; bl < 4; bl++) {
                    int bs = bl * 432 + ci * 108 + (oh + kh) * 12 + ow;
                    in[bl][0] = s_in[bs];
                    in[bl][1] = s_in[bs + 1];
                    in[bl][2] = s_in[bs + 2];
                }
#pragma unroll
                for (int co = 0; co < 8; co++) {
                    const float4* wp = (const float4*)(s_w + (yq * 8 + co) * 48 + ci * 12 + kh * 4);
                    float4 wv = wp[0];
#pragma unroll
                    for (int bl = 0; bl < 4; bl++) {
                        acc[bl][co] += wv.x * in[bl][0];
                        acc[bl][co] += wv.y * in[bl][1];
                        acc[bl][co] += wv.z * in[bl][2];
                    }
                }
            }
        }
        __syncthreads();
    }
#pragma unroll
    for (int bl = 0; bl < 4; bl++)
#pragma unroll
        for (int co = 0; co < 8; co++)
            g_rc2[((b0 + bl) * 256 + cog * 32 + yq * 8 + co) * 49 + px] = acc[bl][co];
}

// ---------------------------------------------------------------------------
// shortcut 1x1 s2, smem staged, scalar. grid (8 cog, 64 b), block 196.
// ---------------------------------------------------------------------------
__global__ void __launch_bounds__(196) k_shortcut(const float* __restrict__ w) {
    __shared__ __align__(16) float s_c[128 * 49];
    __shared__ __align__(16) float s_wv[32 * 128];
    int b = blockIdx.y, cog = blockIdx.x;
    int tid = threadIdx.x;
    int px = tid % 49, yq = tid / 49;

    for (int t = tid; t < 128 * 49; t += 196) {
        int ci = t / 49, p = t - ci * 49;
        int oh = p / 7, ow = p - oh * 7;
        s_c[t] = g_pool2[(b * 128 + ci) * 196 + oh * 28 + ow * 2];
    }
    for (int t = tid; t < 32 * 128; t += 196) {
        int co = t >> 7, ci = t & 127;
        s_wv[t] = w[(cog * 32 + co) * 128 + ci];
    }
    __syncthreads();

    float acc[8];
#pragma unroll
    for (int co = 0; co < 8; co++) acc[co] = 0.f;
#pragma unroll 1
    for (int cp = 0; cp < 64; cp++) {
        float in0 = s_c[(2 * cp) * 49 + px];
        float in1 = s_c[(2 * cp + 1) * 49 + px];
#pragma unroll
        for (int co = 0; co < 8; co++) {
            float2 wv = *(const float2*)(s_wv + (yq * 8 + co) * 128 + 2 * cp);
            acc[co] += wv.x * in0;
            acc[co] += wv.y * in1;
        }
    }
#pragma unroll
    for (int co = 0; co < 8; co++)
        g_rs[(b * 256 + cog * 32 + yq * 8 + co) * 49 + px] = acc[co];
}

// ---------------------------------------------------------------------------
// tail: y = mean relu(bn(rc2)+bn(rs)); out = y M^T + b2
// ---------------------------------------------------------------------------
__global__ void k_tail(float* __restrict__ out) {
    __shared__ float s_y[256];
    int b = blockIdx.x, c = threadIdx.x;
    float sc2 = g_scr2[c], sh2 = g_shr2[c], scs = g_scs[c], shs = g_shs[c];
    const float* p2 = g_rc2 + (b * 256 + c) * 49;
    const float* ps = g_rs + (b * 256 + c) * 49;
    float s = 0.f;
    for (int p = 0; p < 49; p++) {
        float v = p2[p] * sc2 + sh2 + ps[p] * scs + shs;
        s += fmaxf(v, 0.f);
    }
    s_y[c] = s * (1.f / 49.f);
    __syncthreads();
    if (c < 50) {
        float acc = g_b2[c];
        for (int k = 0; k < 256; k++) acc += s_y[k] * g_M[c * 256 + k];
        out[b * 50 + c] = acc;
    }
}

// ---------------------------------------------------------------------------
// Tail fold (softmax attention collapses to 1x1 conv: wo@wv)
// ---------------------------------------------------------------------------
__global__ void k_foldT(const float* __restrict__ fcw, const float* __restrict__ wo) {
    int idx = blockIdx.x * 256 + threadIdx.x;
    if (idx >= 50 * 1024) return;
    int i = idx / 1024, j = idx - i * 1024;
    float s = 0.f;
    for (int c = 0; c < 256; c++) s += fcw[i * 256 + c] * wo[c * 1024 + j];
    g_T[idx] = s;
}

__global__ void k_foldM(const float* __restrict__ wv) {
    int idx = blockIdx.x * 256 + threadIdx.x;
    if (idx >= 50 * 256) return;
    int i = idx / 256, c = idx - i * 256;
    float s = 0.f;
    for (int j = 0; j < 1024; j++) s += g_T[i * 1024 + j] * wv[j * 256 + c];
    g_M[idx] = s;
}

__global__ void k_foldb(const float* __restrict__ fcw, const float* __restrict__ bo,
                        const float* __restrict__ fcb) {
    int i = threadIdx.x;
    if (i >= 50) return;
    float s = 0.f;
    for (int c = 0; c < 256; c++) s += fcw[i * 256 + c] * bo[c];
    g_b2[i] = s + fcb[i];
}

// ---------------------------------------------------------------------------
// Launch (k_conv1 is the 4th launch -> ncu profile target)
// ---------------------------------------------------------------------------
extern "C" void kernel_launch(void* const* d_in, const int* in_sizes, int n_in,
                              void* d_out, int out_size) {
    const float* imgs   = (const float*)d_in[0];
    const float* a1f1   = (const float*)d_in[1];
    const float* a1f2   = (const float*)d_in[2];
    const float* a1f2b  = (const float*)d_in[3];
    const float* dy1    = (const float*)d_in[4];
    const float* bn1g   = (const float*)d_in[5];
    const float* bn1b   = (const float*)d_in[6];
    const float* a2f1   = (const float*)d_in[7];
    const float* a2f2   = (const float*)d_in[8];
    const float* a2f2b  = (const float*)d_in[9];
    const float* dy2    = (const float*)d_in[10];
    const float* bn2g   = (const float*)d_in[11];
    const float* bn2b   = (const float*)d_in[12];
    const float* rc1w   = (const float*)d_in[13];
    const float* rbn1g  = (const float*)d_in[14];
    const float* rbn1b  = (const float*)d_in[15];
    const float* rc2w   = (const float*)d_in[16];
    const float* rbn2g  = (const float*)d_in[17];
    const float* rbn2b  = (const float*)d_in[18];
    const float* rsw    = (const float*)d_in[19];
    const float* rbnsg  = (const float*)d_in[20];
    const float* rbnsb  = (const float*)d_in[21];
    const float* wv     = (const float*)d_in[24];
    const float* wo     = (const float*)d_in[25];
    const float* bo     = (const float*)d_in[26];
    const float* fcw    = (const float*)d_in[27];
    const float* fcb    = (const float*)d_in[28];
    float* out = (float*)d_out;
    (void)in_sizes; (void)n_in; (void)out_size;

    static int smem_set = 0;
    if (!smem_set) {
        cudaFuncSetAttribute(k_conv1, cudaFuncAttributeMaxDynamicSharedMemorySize,
                             CONV1_SMEM);
        cudaFuncSetAttribute(k_conv1, cudaFuncAttributePreferredSharedMemoryCarveout,
                             100);
        cudaFuncSetAttribute(k_bnpool1, cudaFuncAttributeMaxDynamicSharedMemorySize,
                             POOL1_SMEM);
        smem_set = 1;
    }

    // stage 1 front (block 0 of pooled1 zeroes accumulators)
    k_pooled1<<<192, 256>>>(imgs);
    k_attn1<<<1, 64>>>(a1f1, a1f2, a1f2b);
    k_w1agg<<<(BB * 10752 + 255) / 256, 256>>>(dy1);
    k_conv1<<<dim3(49, BB), 256, CONV1_SMEM>>>(imgs);  // 4th (profiled)

    // tail fold (independent)
    k_foldT<<<200, 256>>>(fcw, wo);
    k_foldM<<<50, 256>>>(wv);
    k_foldb<<<1, 64>>>(fcw, bo, fcb);

    k_bnscale<<<1, 64>>>(bn1g, bn1b, 802816.f, 0, 64);
    k_bnpool1<<<dim3(64, BB), 256, POOL1_SMEM>>>();

    // stage 2
    k_attn2<<<1, 64>>>(a2f1, a2f2, a2f2b);
    k_w2agg<<<(BB * 73728 + 255) / 256, 256>>>(dy2);
    k_conv2<<<dim3(8, BB), 224>>>();
    k_bnscale<<<1, 128>>>(bn2g, bn2b, 50176.f, 1, 128);
    k_bnpool2<<<dim3(128, BB), 196>>>();

    // residual block
    k_resconv1<<<dim3(8, BB / 4), 196>>>(rc1w);
    k_shortcut<<<dim3(8, BB), 196>>>(rsw);
    k_chstats<<<256, 128>>>(rbn1g, rbn1b);
    k_resconv2<<<dim3(8, BB / 4), 196>>>(rc2w);
    k_chstats2<<<256, 128>>>(rbn2g, rbn2b, rbnsg, rbnsb);

    k_tail<<<64, 256>>>(out);
}

// round 11
// speedup vs baseline: 2.7941x; 1.1379x over previous
#include <cuda_runtime.h>
#include <math.h>

#define BB 64

// ---------------------------------------------------------------------------
// Scratch
// ---------------------------------------------------------------------------
__device__ float g_pooled1[BB * 3];
__device__ float g_attn1[BB * 8];
__device__ float g_w1t[BB * 64 * 168];           // tf32-rounded, padded [co][ci][kh][8]
__device__ float g_conv1[BB * 64 * 112 * 112];
__device__ float g_pool1[BB * 64 * 56 * 56];     // tf32-rounded (conv2 input)
__device__ float g_pooled2[BB * 64];
__device__ float g_attn2[BB * 8];
__device__ float g_w2[BB * 128 * 64 * 9];        // tf32-rounded
__device__ float g_conv2[BB * 128 * 28 * 28];
__device__ float g_pool2[BB * 128 * 14 * 14];
__device__ float g_rc1[BB * 256 * 49];
__device__ float g_rc2[BB * 256 * 49];
__device__ float g_rs[BB * 256 * 49];

__device__ float g_sum1[64],  g_sq1[64],  g_sc1[64],  g_sh1[64];
__device__ float g_sum2[128], g_sq2[128], g_sc2[128], g_sh2[128];
__device__ float g_scr1[256], g_shr1[256];
__device__ float g_scr2[256], g_shr2[256];
__device__ float g_scs[256],  g_shs[256];

__device__ float g_T[50 * 1024];
__device__ float g_M[50 * 256];
__device__ float g_b2[50];

// ---------------------------------------------------------------------------
// bn scale/shift (stages 0,1)
// ---------------------------------------------------------------------------
__global__ void k_bnscale(const float* __restrict__ g, const float* __restrict__ be,
                          float cnt, int stage, int C) {
    int c = blockIdx.x * blockDim.x + threadIdx.x;
    if (c >= C) return;
    float *su, *sq, *sc, *sh;
    if (stage == 0) { su = g_sum1; sq = g_sq1; sc = g_sc1; sh = g_sh1; }
    else            { su = g_sum2; sq = g_sq2; sc = g_sc2; sh = g_sh2; }
    float m = su[c] / cnt;
    float v = sq[c] / cnt - m * m;
    float s = g[c] * rsqrtf(v + 1e-5f);
    sc[c] = s;
    sh[c] = be[c] - m * s;
}

// per-channel stats of rc1 + finalize scale/shift
__global__ void k_chstats(const float* __restrict__ g, const float* __restrict__ be) {
    int c = blockIdx.x;
    float s = 0.f, q = 0.f;
    for (int t = threadIdx.x; t < BB * 49; t += 128) {
        int b = t / 49, p = t - b * 49;
        float v = g_rc1[(b * 256 + c) * 49 + p];
        s += v; q += v * v;
    }
    for (int o = 16; o; o >>= 1) {
        s += __shfl_down_sync(0xffffffffu, s, o);
        q += __shfl_down_sync(0xffffffffu, q, o);
    }
    __shared__ float rs[4], rq[4];
    int w = threadIdx.x >> 5;
    if ((threadIdx.x & 31) == 0) { rs[w] = s; rq[w] = q; }
    __syncthreads();
    if (threadIdx.x == 0) {
        float su = rs[0] + rs[1] + rs[2] + rs[3];
        float sq = rq[0] + rq[1] + rq[2] + rq[3];
        float m = su * (1.f / 3136.f);
        float v = sq * (1.f / 3136.f) - m * m;
        float sc = g[c] * rsqrtf(v + 1e-5f);
        g_scr1[c] = sc;
        g_shr1[c] = be[c] - m * sc;
    }
}

// stats of rc2 AND rs + finalize both scale/shifts
__global__ void k_chstats2(const float* __restrict__ g2, const float* __restrict__ be2,
                           const float* __restrict__ gs, const float* __restrict__ bes) {
    int c = blockIdx.x;
    float s2 = 0.f, q2 = 0.f, ss = 0.f, qs = 0.f;
    for (int t = threadIdx.x; t < BB * 49; t += 128) {
        int b = t / 49, p = t - b * 49;
        float v = g_rc2[(b * 256 + c) * 49 + p];
        s2 += v; q2 += v * v;
        float u = g_rs[(b * 256 + c) * 49 + p];
        ss += u; qs += u * u;
    }
    for (int o = 16; o; o >>= 1) {
        s2 += __shfl_down_sync(0xffffffffu, s2, o);
        q2 += __shfl_down_sync(0xffffffffu, q2, o);
        ss += __shfl_down_sync(0xffffffffu, ss, o);
        qs += __shfl_down_sync(0xffffffffu, qs, o);
    }
    __shared__ float r[4][4];
    int w = threadIdx.x >> 5;
    if ((threadIdx.x & 31) == 0) { r[w][0] = s2; r[w][1] = q2; r[w][2] = ss; r[w][3] = qs; }
    __syncthreads();
    if (threadIdx.x == 0) {
        float su2 = r[0][0] + r[1][0] + r[2][0] + r[3][0];
        float sq2 = r[0][1] + r[1][1] + r[2][1] + r[3][1];
        float sus = r[0][2] + r[1][2] + r[2][2] + r[3][2];
        float sqs = r[0][3] + r[1][3] + r[2][3] + r[3][3];
        float m2 = su2 * (1.f / 3136.f);
        float v2 = sq2 * (1.f / 3136.f) - m2 * m2;
        float c2 = g2[c] * rsqrtf(v2 + 1e-5f);
        g_scr2[c] = c2;
        g_shr2[c] = be2[c] - m2 * c2;
        float ms = sus * (1.f / 3136.f);
        float vs = sqs * (1.f / 3136.f) - ms * ms;
        float cs = gs[c] * rsqrtf(vs + 1e-5f);
        g_scs[c] = cs;
        g_shs[c] = bes[c] - ms * cs;
    }
}

// ---------------------------------------------------------------------------
// Stage-1 attention
// ---------------------------------------------------------------------------
__global__ void k_pooled1(const float* __restrict__ imgs) {
    int bc = blockIdx.x;
    int tid = threadIdx.x;
    if (bc == 0) {
        for (int i = tid; i < BB * 64; i += 256) g_pooled2[i] = 0.f;
        if (tid < 64)  { g_sum1[tid] = 0.f; g_sq1[tid] = 0.f; }
        if (tid < 128) { g_sum2[tid] = 0.f; g_sq2[tid] = 0.f; }
    }
    const float* p = imgs + (long)bc * 50176;
    float s = 0.f;
    for (int i = tid; i < 50176; i += 256) s += p[i];
    __shared__ float red[256];
    red[tid] = s; __syncthreads();
    for (int o = 128; o; o >>= 1) { if (tid < o) red[tid] += red[tid + o]; __syncthreads(); }
    if (tid == 0) g_pooled1[bc] = red[0] * (1.f / 50176.f);
}

__global__ void k_attn1(const float* __restrict__ fc1, const float* __restrict__ fc2,
                        const float* __restrict__ fc2b) {
    int b = threadIdx.x;
    if (b >= BB) return;
    float p[3];
    for (int c = 0; c < 3; c++) p[c] = g_pooled1[b * 3 + c];
    float h[8];
    for (int j = 0; j < 8; j++) {
        float s = 0.f;
        for (int c = 0; c < 3; c++) s += p[c] * fc1[j * 3 + c];
        h[j] = fmaxf(s, 0.f);
    }
    float lg[8], mx = -1e30f;
    for (int k = 0; k < 8; k++) {
        float s = fc2b[k];
        for (int j = 0; j < 8; j++) s += h[j] * fc2[k * 8 + j];
        lg[k] = s; mx = fmaxf(mx, s);
    }
    float den = 0.f;
    for (int k = 0; k < 8; k++) { lg[k] = expf(lg[k] - mx); den += lg[k]; }
    float inv = 1.f / den;
    for (int k = 0; k < 8; k++) g_attn1[b * 8 + k] = lg[k] * inv;
}

// aggregate + tf32-round + pad into [b][co][ci][kh][8] (kw slot 7 = 0)
__global__ void k_w1agg(const float* __restrict__ dy1) {
    int idx = blockIdx.x * 256 + threadIdx.x;
    if (idx >= BB * 10752) return;
    int b = idx / 10752, r = idx - b * 10752;
    int co = r / 168, r2 = r - co * 168;
    int ci = r2 / 56, r3 = r2 - ci * 56;
    int kh = r3 >> 3, kw = r3 & 7;
    float s = 0.f;
    if (kw < 7) {
        int i = co * 147 + ci * 49 + kh * 7 + kw;
#pragma unroll
        for (int k = 0; k < 8; k++) s += g_attn1[b * 8 + k] * dy1[k * 9408 + i];
    }
    unsigned tv; asm("cvt.rna.tf32.f32 %0, %1;" : "=r"(tv) : "f"(s));
    g_w1t[idx] = __uint_as_float(tv);
}

// ---------------------------------------------------------------------------
// Conv1 via tf32 mma.sync implicit GEMM (proven form, unchanged).
// ---------------------------------------------------------------------------
#define W_STRIDE 172
extern __shared__ float smemBuf[];
__global__ void __launch_bounds__(256, 2) k_conv1(const float* __restrict__ imgs) {
    float* s_in = smemBuf;                   // [ci][37][64]
    float* s_w = smemBuf + 7104;             // [co][W_STRIDE]
    float* s_stat = smemBuf + 7104 + 64 * W_STRIDE;
    int b = blockIdx.y;
    int tr = blockIdx.x / 7, tc = blockIdx.x - tr * 7;
    int oh0 = tr * 16, ow0 = tc * 16;
    int tid = threadIdx.x;

    if (tid < 128) s_stat[tid] = 0.f;

    const float* wt = g_w1t + b * 10752;
    for (int t = tid; t < 10752; t += 256)
        s_w[t + (t / 168) * 4] = wt[t];

    int ih0 = 2 * oh0 - 3, iw0 = 2 * ow0 - 3;
#pragma unroll 1
    for (int ci = 0; ci < 3; ci++) {
        const float* ip = imgs + (long)(b * 3 + ci) * 50176;
        for (int u = tid; u < 2368; u += 256) {
            int r = u >> 6, c = u & 63;
            if (c < 38) {
                int ih = ih0 + r, iw = iw0 + c;
                float v = 0.f;
                if ((unsigned)ih < 224u && (unsigned)iw < 224u)
                    v = ip[ih * 224 + iw];
                unsigned tv; asm("cvt.rna.tf32.f32 %0, %1;" : "=r"(tv) : "f"(v));
                s_in[ci * 2368 + u] = __uint_as_float(tv);
            }
        }
    }
    __syncthreads();

    int w = tid >> 5, lane = tid & 31;
    int gid = lane >> 2, tig = lane & 3;

    float acc[2][8][4];
#pragma unroll
    for (int mt = 0; mt < 2; mt++)
#pragma unroll
        for (int nt = 0; nt < 8; nt++)
#pragma unroll
            for (int k = 0; k < 4; k++) acc[mt][nt][k] = 0.f;

    int bq[8];
#pragma unroll
    for (int nt = 0; nt < 8; nt++) bq[nt] = (nt * 8 + gid) * W_STRIDE + tig;
    int abase0 = (2 * (2 * w + 0)) * 64 + 2 * gid + tig;
    int abase1 = (2 * (2 * w + 1)) * 64 + 2 * gid + tig;

#pragma unroll 1
    for (int ci = 0; ci < 3; ci++) {
#pragma unroll
        for (int kh = 0; kh < 7; kh++) {
            int wbase = ci * 56 + kh * 8;
            int aoff = ci * 2368 + kh * 64;
            unsigned bf0[8], bf1[8];
#pragma unroll
            for (int nt = 0; nt < 8; nt++) {
                bf0[nt] = __float_as_uint(s_w[bq[nt] + wbase]);
                bf1[nt] = __float_as_uint(s_w[bq[nt] + wbase + 4]);
            }
#pragma unroll
            for (int mt = 0; mt < 2; mt++) {
                int a = aoff + (mt ? abase1 : abase0);
                unsigned a0 = __float_as_uint(s_in[a]);
                unsigned a1 = __float_as_uint(s_in[a + 16]);
                unsigned a2 = __float_as_uint(s_in[a + 4]);
                unsigned a3 = __float_as_uint(s_in[a + 20]);
#pragma unroll
                for (int nt = 0; nt < 8; nt++) {
                    asm volatile(
                        "mma.sync.aligned.m16n8k8.row.col.f32.tf32.tf32.f32 "
                        "{%0,%1,%2,%3}, {%4,%5,%6,%7}, {%8,%9}, {%0,%1,%2,%3};"
                        : "+f"(acc[mt][nt][0]), "+f"(acc[mt][nt][1]),
                          "+f"(acc[mt][nt][2]), "+f"(acc[mt][nt][3])
                        : "r"(a0), "r"(a1), "r"(a2), "r"(a3),
                          "r"(bf0[nt]), "r"(bf1[nt]));
                }
            }
        }
    }

#pragma unroll
    for (int mt = 0; mt < 2; mt++) {
        int oh = oh0 + 2 * w + mt;
#pragma unroll
        for (int nt = 0; nt < 8; nt++) {
            int co = nt * 8 + 2 * tig;
            long base0 = ((long)(b * 64 + co)) * 12544 + oh * 112 + ow0;
            g_conv1[base0 + gid] = acc[mt][nt][0];
            g_conv1[base0 + 12544 + gid] = acc[mt][nt][1];
            g_conv1[base0 + gid + 8] = acc[mt][nt][2];
            g_conv1[base0 + 12544 + gid + 8] = acc[mt][nt][3];
        }
    }

#pragma unroll
    for (int nt = 0; nt < 8; nt++) {
        float s0 = 0.f, q0 = 0.f, s1 = 0.f, q1 = 0.f;
#pragma unroll
        for (int mt = 0; mt < 2; mt++) {
            float v;
            v = acc[mt][nt][0]; s0 += v; q0 += v * v;
            v = acc[mt][nt][2]; s0 += v; q0 += v * v;
            v = acc[mt][nt][1]; s1 += v; q1 += v * v;
            v = acc[mt][nt][3]; s1 += v; q1 += v * v;
        }
#pragma unroll
        for (int o = 16; o >= 4; o >>= 1) {
            s0 += __shfl_xor_sync(0xffffffffu, s0, o);
            q0 += __shfl_xor_sync(0xffffffffu, q0, o);
            s1 += __shfl_xor_sync(0xffffffffu, s1, o);
            q1 += __shfl_xor_sync(0xffffffffu, q1, o);
        }
        if (gid == 0) {
            int co = nt * 8 + 2 * tig;
            atomicAdd(&s_stat[co], s0);
            atomicAdd(&s_stat[64 + co], q0);
            atomicAdd(&s_stat[co + 1], s1);
            atomicAdd(&s_stat[64 + co + 1], q1);
        }
    }
    __syncthreads();
    if (tid < 64) {
        atomicAdd(&g_sum1[tid], s_stat[tid]);
        atomicAdd(&g_sq1[tid], s_stat[64 + tid]);
    }
}
#define CONV1_SMEM ((7104 + 64 * W_STRIDE + 128) * 4)

// ---------------------------------------------------------------------------
// BN1 + maxpool3 s2 p1: 112->56, plane-tiled; output tf32-rounded (conv2 input)
// ---------------------------------------------------------------------------
extern __shared__ float s_plane[];
__global__ void __launch_bounds__(256) k_bnpool1() {
    int c = blockIdx.x, b = blockIdx.y;
    int tid = threadIdx.x;
    const float* ip = g_conv1 + (long)(b * 64 + c) * 12544;
#pragma unroll
    for (int k = 0; k < 49; k++) s_plane[tid + 256 * k] = ip[tid + 256 * k];
    __syncthreads();

    float sc = g_sc1[c], sh = g_sh1[c];
    float* op = g_pool1 + (b * 64 + c) * 3136;
    float s = 0.f;
#pragma unroll
    for (int k = 0; k < 13; k++) {
        int p = tid + 256 * k;
        if (p < 3136) {
            int oh = p / 56, ow = p - oh * 56;
            float m = -1e30f;
#pragma unroll
            for (int r = 0; r < 3; r++) {
                int ih = 2 * oh - 1 + r;
                if ((unsigned)ih >= 112u) continue;
#pragma unroll
                for (int cc = 0; cc < 3; cc++) {
                    int iw = 2 * ow - 1 + cc;
                    if ((unsigned)iw >= 112u) continue;
                    m = fmaxf(m, s_plane[ih * 112 + iw] * sc + sh);
                }
            }
            unsigned tv; asm("cvt.rna.tf32.f32 %0, %1;" : "=r"(tv) : "f"(m));
            op[p] = __uint_as_float(tv);
            s += m;
        }
    }
    for (int o = 16; o; o >>= 1) s += __shfl_down_sync(0xffffffffu, s, o);
    __shared__ float s_red;
    if (tid == 0) s_red = 0.f;
    __syncthreads();
    if ((tid & 31) == 0) atomicAdd(&s_red, s);
    __syncthreads();
    if (tid == 0) atomicAdd(&g_pooled2[b * 64 + c], s_red);
}
#define POOL1_SMEM (12544 * 4)

// ---------------------------------------------------------------------------
// Stage-2 attention
// ---------------------------------------------------------------------------
__global__ void k_attn2(const float* __restrict__ fc1, const float* __restrict__ fc2,
                        const float* __restrict__ fc2b) {
    int b = threadIdx.x;
    if (b >= BB) return;
    float h[17];
    for (int j = 0; j < 17; j++) {
        float s = 0.f;
        for (int c = 0; c < 64; c++)
            s += (g_pooled2[b * 64 + c] * (1.f / 3136.f)) * fc1[j * 64 + c];
        h[j] = fmaxf(s, 0.f);
    }
    float lg[8], mx = -1e30f;
    for (int k = 0; k < 8; k++) {
        float s = fc2b[k];
        for (int j = 0; j < 17; j++) s += h[j] * fc2[k * 17 + j];
        lg[k] = s; mx = fmaxf(mx, s);
    }
    float den = 0.f;
    for (int k = 0; k < 8; k++) { lg[k] = expf(lg[k] - mx); den += lg[k]; }
    float inv = 1.f / den;
    for (int k = 0; k < 8; k++) g_attn2[b * 8 + k] = lg[k] * inv;
}

// aggregate + tf32-round
__global__ void k_w2agg(const float* __restrict__ dy2) {
    int idx = blockIdx.x * 256 + threadIdx.x;
    if (idx >= BB * 73728) return;
    int b = idx / 73728, i = idx - b * 73728;
    float s = 0.f;
#pragma unroll
    for (int k = 0; k < 8; k++) s += g_attn2[b * 8 + k] * dy2[k * 73728 + i];
    unsigned tv; asm("cvt.rna.tf32.f32 %0, %1;" : "=r"(tv) : "f"(s));
    g_w2[idx] = __uint_as_float(tv);
}

// ---------------------------------------------------------------------------
// Conv2 via tf32 mma.sync: 9-tap GEMM over ci (K=8 per chunk, no padding).
// Block = sample b x 4 output rows (112 px = 7 m16 tiles) x 128 co.
// 256 threads: warps 0-6 = mma (1 mtile x 16 n8-tiles each), all warps stage.
// smem: s_in [9 ir][58 iw][pitch 9, ci 0..7] = 4698; s_w [9 tap][co*9+ci] = 10368;
// s_stat 256.  grid (7 rowblk, 64 b).
// ---------------------------------------------------------------------------
__global__ void __launch_bounds__(256, 2) k_conv2() {
    float* s_in = smemBuf;                 // 4698
    float* s_w = smemBuf + 4698;           // 10368
    float* s_stat = smemBuf + 4698 + 10368;
    int rowblk = blockIdx.x, b = blockIdx.y;
    int tid = threadIdx.x;

    for (int t = tid; t < 4698; t += 256) s_in[t] = 0.f;
    s_stat[tid] = 0.f;

    // input staging offsets: 2016 float2-pairs, 8 per thread
    int ih0 = 8 * rowblk - 1;
    int ldp[8], stp[8];
#pragma unroll
    for (int k = 0; k < 8; k++) {
        int e2 = tid + 256 * k;
        if (e2 < 2016) {
            int ci = e2 / 252, rem = e2 - ci * 252;
            int ir = rem / 28, iw2 = rem - ir * 28;
            int ih = ih0 + ir;
            ldp[k] = (ih >= 0) ? (ci * 3136 + ih * 56 + 2 * iw2) : -1;
            stp[k] = ir * 522 + (2 * iw2 + 1) * 9 + ci;
        } else { ldp[k] = -1; stp[k] = 0; }
    }

    int w = tid >> 5, lane = tid & 31;
    int gid = lane >> 2, tig = lane & 3;
    int q0 = 16 * w + gid, q1 = q0 + 8;
    int ohl0 = q0 / 28, owl0 = q0 - 28 * ohl0;
    int ohl1 = q1 / 28, owl1 = q1 - 28 * ohl1;
    int pb0 = 2 * ohl0 * 522 + 2 * owl0 * 9 + tig;
    int pb1 = 2 * ohl1 * 522 + 2 * owl1 * 9 + tig;

    float acc[16][4];
#pragma unroll
    for (int nt = 0; nt < 16; nt++)
#pragma unroll
        for (int k = 0; k < 4; k++) acc[nt][k] = 0.f;

    const float* ib = g_pool1 + (long)(b * 64) * 3136;
    const float* wb = g_w2 + b * 73728;
    int half = tid & 1, co_t = tid >> 1;

#pragma unroll 1
    for (int c0 = 0; c0 < 64; c0 += 8) {
        __syncthreads();
        // stage input (8 ci x 9 ir x 56 iw), float2 per thread-slot
#pragma unroll
        for (int k = 0; k < 8; k++) {
            if (ldp[k] >= 0) {
                float2 v = *(const float2*)(ib + c0 * 3136 + ldp[k]);
                s_in[stp[k]] = v.x;
                s_in[stp[k] + 9] = v.y;
            }
        }
        // stage weights: thread (co_t, half) loads 9 float4 (contiguous 36-run)
        {
            const float4* src = (const float4*)(wb + co_t * 576 + c0 * 9 + half * 36);
            int sb = co_t * 9;
            int cb = half * 4;
#pragma unroll
            for (int q = 0; q < 9; q++) {
                float4 f = src[q];
                int e0 = 4 * q;
                s_w[((e0    ) % 9) * 1152 + sb + cb + (e0    ) / 9] = f.x;
                s_w[((e0 + 1) % 9) * 1152 + sb + cb + (e0 + 1) / 9] = f.y;
                s_w[((e0 + 2) % 9) * 1152 + sb + cb + (e0 + 2) / 9] = f.z;
                s_w[((e0 + 3) % 9) * 1152 + sb + cb + (e0 + 3) / 9] = f.w;
            }
        }
        __syncthreads();
        if (w < 7) {
#pragma unroll
            for (int tap = 0; tap < 9; tap++) {
                int kh = tap / 3, kw = tap - 3 * (tap / 3);
                int toff = kh * 522 + kw * 9;
                unsigned a0 = __float_as_uint(s_in[pb0 + toff]);
                unsigned a1 = __float_as_uint(s_in[pb1 + toff]);
                unsigned a2 = __float_as_uint(s_in[pb0 + toff + 4]);
                unsigned a3 = __float_as_uint(s_in[pb1 + toff + 4]);
#pragma unroll
                for (int nt = 0; nt < 16; nt++) {
                    int wq = tap * 1152 + (nt * 8 + gid) * 9 + tig;
                    unsigned b0 = __float_as_uint(s_w[wq]);
                    unsigned b1 = __float_as_uint(s_w[wq + 4]);
                    asm volatile(
                        "mma.sync.aligned.m16n8k8.row.col.f32.tf32.tf32.f32 "
                        "{%0,%1,%2,%3}, {%4,%5,%6,%7}, {%8,%9}, {%0,%1,%2,%3};"
                        : "+f"(acc[nt][0]), "+f"(acc[nt][1]),
                          "+f"(acc[nt][2]), "+f"(acc[nt][3])
                        : "r"(a0), "r"(a1), "r"(a2), "r"(a3),
                          "r"(b0), "r"(b1));
                }
            }
        }
    }

    if (w < 7) {
#pragma unroll
        for (int nt = 0; nt < 16; nt++) {
            int co = nt * 8 + 2 * tig;
            long o0 = ((long)(b * 128 + co)) * 784 + rowblk * 112;
            g_conv2[o0 + q0] = acc[nt][0];
            g_conv2[o0 + 784 + q0] = acc[nt][1];
            g_conv2[o0 + q1] = acc[nt][2];
            g_conv2[o0 + 784 + q1] = acc[nt][3];
            float s0 = acc[nt][0] + acc[nt][2];
            float sq0 = acc[nt][0] * acc[nt][0] + acc[nt][2] * acc[nt][2];
            float s1 = acc[nt][1] + acc[nt][3];
            float sq1 = acc[nt][1] * acc[nt][1] + acc[nt][3] * acc[nt][3];
#pragma unroll
            for (int o = 16; o >= 4; o >>= 1) {
                s0 += __shfl_xor_sync(0xffffffffu, s0, o);
                sq0 += __shfl_xor_sync(0xffffffffu, sq0, o);
                s1 += __shfl_xor_sync(0xffffffffu, s1, o);
                sq1 += __shfl_xor_sync(0xffffffffu, sq1, o);
            }
            if (gid == 0) {
                atomicAdd(&s_stat[co], s0);
                atomicAdd(&s_stat[128 + co], sq0);
                atomicAdd(&s_stat[co + 1], s1);
                atomicAdd(&s_stat[128 + co + 1], sq1);
            }
        }
    }
    __syncthreads();
    if (tid < 128) {
        atomicAdd(&g_sum2[tid], s_stat[tid]);
        atomicAdd(&g_sq2[tid], s_stat[128 + tid]);
    }
}
#define CONV2_SMEM ((4698 + 10368 + 256) * 4)

// ---------------------------------------------------------------------------
// BN2 + maxpool3 s2 p1: 28->14
// ---------------------------------------------------------------------------
__global__ void k_bnpool2() {
    int b = blockIdx.y, c = blockIdx.x;
    int p = threadIdx.x;
    if (p >= 196) return;
    int oh = p / 14, ow = p - oh * 14;
    float sc = g_sc2[c], sh = g_sh2[c];
    const float* ip = g_conv2 + (b * 128 + c) * 784;
    float m = -1e30f;
#pragma unroll
    for (int r = 0; r < 3; r++) {
        int ih = 2 * oh - 1 + r;
        if ((unsigned)ih >= 28u) continue;
#pragma unroll
        for (int cc = 0; cc < 3; cc++) {
            int iw = 2 * ow - 1 + cc;
            if ((unsigned)iw >= 28u) continue;
            m = fmaxf(m, ip[ih * 28 + iw] * sc + sh);
        }
    }
    g_pool2[(b * 128 + c) * 196 + p] = m;
}

// ---------------------------------------------------------------------------
// resconv1: 128->256 3x3 s2, 14->7. 4 batches/block, pipelined staging.
// ---------------------------------------------------------------------------
__global__ void __launch_bounds__(196) k_resconv1(const float* __restrict__ w) {
    __shared__ __align__(16) float s_in[4 * 1080];
    __shared__ __align__(16) float s_w[32 * 48];
    int bq = blockIdx.y, cog = blockIdx.x;
    int b0 = bq * 4;
    int tid = threadIdx.x;
    int px = tid % 49, yq = tid / 49;
    int oh = px / 7, ow = px - oh * 7;

    for (int t = tid; t < 4320; t += 196) s_in[t] = 0.f;
    for (int t = tid; t < 1536; t += 196) s_w[t] = 0.f;

    int ld[16], sidx[16];
#pragma unroll
    for (int k = 0; k < 16; k++) {
        int t = tid + 196 * k;
        int bl = t / 784, rem = t - bl * 784;
        int ci = rem / 196, p = rem - ci * 196;
        int r = p / 14, c = p - r * 14;
        ld[k] = bl * 25088 + rem;
        sidx[k] = bl * 1080 + ci * 270 + (r + 1) * 18 + (c + 1);
    }
    int wld[6], wst[6];
#pragma unroll
    for (int k = 0; k < 6; k++) {
        int t = tid + 196 * k;
        if (t < 1152) {
            int co = t / 36, rem = t - co * 36;
            int ci = rem / 9, k9 = rem - ci * 9;
            int kh = k9 / 3, kw = k9 - kh * 3;
            wld[k] = (cog * 32 + co) * 1152 + ci * 9 + k9;
            wst[k] = co * 48 + ci * 12 + kh * 4 + kw;
        } else { wld[k] = -1; wst[k] = 1536 - 1; }
    }
    __syncthreads();

    const float* base = g_pool2 + (long)(b0 * 128) * 196;
    float r_in[16], r_w[6];
#pragma unroll
    for (int k = 0; k < 16; k++) r_in[k] = base[ld[k]];
#pragma unroll
    for (int k = 0; k < 6; k++) r_w[k] = (wld[k] >= 0) ? w[wld[k]] : 0.f;

    float acc[4][8];
#pragma unroll
    for (int bl = 0; bl < 4; bl++)
#pragma unroll
        for (int co = 0; co < 8; co++) acc[bl][co] = 0.f;

#pragma unroll 1
    for (int c0 = 0; c0 < 128; c0 += 4) {
#pragma unroll
        for (int k = 0; k < 16; k++) s_in[sidx[k]] = r_in[k];
#pragma unroll
        for (int k = 0; k < 6; k++) if (wld[k] >= 0) s_w[wst[k]] = r_w[k];
        __syncthreads();
        if (c0 + 4 < 128) {
            const float* src = base + (c0 + 4) * 196;
#pragma unroll
            for (int k = 0; k < 16; k++) r_in[k] = src[ld[k]];
#pragma unroll
            for (int k = 0; k < 6; k++)
                if (wld[k] >= 0) r_w[k] = w[wld[k] + (c0 + 4) * 9];
        }
#pragma unroll
        for (int ci = 0; ci < 4; ci++) {
#pragma unroll
            for (int kh = 0; kh < 3; kh++) {
                float in[4][3];
#pragma unroll
                for (int bl = 0; bl < 4; bl++) {
                    int bs = bl * 1080 + ci * 270 + (2 * oh + kh) * 18 + 2 * ow;
                    in[bl][0] = s_in[bs];
                    in[bl][1] = s_in[bs + 1];
                    in[bl][2] = s_in[bs + 2];
                }
#pragma unroll
                for (int co = 0; co < 8; co++) {
                    const float4* wp = (const float4*)(s_w + (yq * 8 + co) * 48 + ci * 12 + kh * 4);
                    float4 wv = wp[0];
#pragma unroll
                    for (int bl = 0; bl < 4; bl++) {
                        acc[bl][co] += wv.x * in[bl][0];
                        acc[bl][co] += wv.y * in[bl][1];
                        acc[bl][co] += wv.z * in[bl][2];
                    }
                }
            }
        }
        __syncthreads();
    }
#pragma unroll
    for (int bl = 0; bl < 4; bl++)
#pragma unroll
        for (int co = 0; co < 8; co++)
            g_rc1[((b0 + bl) * 256 + cog * 32 + yq * 8 + co) * 49 + px] = acc[bl][co];
}

// ---------------------------------------------------------------------------
// resconv2: 256->256 3x3 s1, 7x7. bn+relu at register-load time, pipelined.
// ---------------------------------------------------------------------------
__global__ void __launch_bounds__(196) k_resconv2(const float* __restrict__ w) {
    __shared__ __align__(16) float s_in[4 * 432];
    __shared__ __align__(16) float s_w[32 * 48];
    int bq = blockIdx.y, cog = blockIdx.x;
    int b0 = bq * 4;
    int tid = threadIdx.x;
    int px = tid % 49, yq = tid / 49;
    int oh = px / 7, ow = px - oh * 7;

    for (int t = tid; t < 1728; t += 196) s_in[t] = 0.f;
    for (int t = tid; t < 1536; t += 196) s_w[t] = 0.f;

    int ld[4], sidx[4], cidx[4];
#pragma unroll
    for (int k = 0; k < 4; k++) {
        int t = tid + 196 * k;
        int bl = t / 196, rem = t - bl * 196;
        int ci = rem / 49, p = rem - ci * 49;
        int r = p / 7, c = p - r * 7;
        ld[k] = bl * 12544 + rem;
        sidx[k] = bl * 432 + ci * 108 + (r + 1) * 12 + (c + 1);
        cidx[k] = ci;
    }
    int wld[6], wst[6];
#pragma unroll
    for (int k = 0; k < 6; k++) {
        int t = tid + 196 * k;
        if (t < 1152) {
            int co = t / 36, rem = t - co * 36;
            int ci = rem / 9, k9 = rem - ci * 9;
            int kh = k9 / 3, kw = k9 - kh * 3;
            wld[k] = (cog * 32 + co) * 2304 + ci * 9 + k9;
            wst[k] = co * 48 + ci * 12 + kh * 4 + kw;
        } else { wld[k] = -1; wst[k] = 0; }
    }
    __syncthreads();

    const float* base = g_rc1 + (long)(b0 * 256) * 49;
    float r_in[4], r_w[6];
#pragma unroll
    for (int k = 0; k < 4; k++) {
        float sc = g_scr1[cidx[k]], sh = g_shr1[cidx[k]];
        r_in[k] = fmaxf(base[ld[k]] * sc + sh, 0.f);
    }
#pragma unroll
    for (int k = 0; k < 6; k++) r_w[k] = (wld[k] >= 0) ? w[wld[k]] : 0.f;

    float acc[4][8];
#pragma unroll
    for (int bl = 0; bl < 4; bl++)
#pragma unroll
        for (int co = 0; co < 8; co++) acc[bl][co] = 0.f;

#pragma unroll 1
    for (int c0 = 0; c0 < 256; c0 += 4) {
#pragma unroll
        for (int k = 0; k < 4; k++) s_in[sidx[k]] = r_in[k];
#pragma unroll
        for (int k = 0; k < 6; k++) if (wld[k] >= 0) s_w[wst[k]] = r_w[k];
        __syncthreads();
        if (c0 + 4 < 256) {
            const float* src = base + (c0 + 4) * 49;
#pragma unroll
            for (int k = 0; k < 4; k++) {
                int ch = c0 + 4 + cidx[k];
                float sc = g_scr1[ch], sh = g_shr1[ch];
                r_in[k] = fmaxf(src[ld[k]] * sc + sh, 0.f);
            }
#pragma unroll
            for (int k = 0; k < 6; k++)
                if (wld[k] >= 0) r_w[k] = w[wld[k] + (c0 + 4) * 9];
        }
#pragma unroll
        for (int ci = 0; ci < 4; ci++) {
#pragma unroll
            for (int kh = 0; kh < 3; kh++) {
                float in[4][3];
#pragma unroll
                for (int bl = 0; bl < 4; bl++) {
                    int bs = bl * 432 + ci * 108 + (oh + kh) * 12 + ow;
                    in[bl][0] = s_in[bs];
                    in[bl][1] = s_in[bs + 1];
                    in[bl][2] = s_in[bs + 2];
                }
#pragma unroll
                for (int co = 0; co < 8; co++) {
                    const float4* wp = (const float4*)(s_w + (yq * 8 + co) * 48 + ci * 12 + kh * 4);
                    float4 wv = wp[0];
#pragma unroll
                    for (int bl = 0; bl < 4; bl++) {
                        acc[bl][co] += wv.x * in[bl][0];
                        acc[bl][co] += wv.y * in[bl][1];
                        acc[bl][co] += wv.z * in[bl][2];
                    }
                }
            }
        }
        __syncthreads();
    }
#pragma unroll
    for (int bl = 0; bl < 4; bl++)
#pragma unroll
        for (int co = 0; co < 8; co++)
            g_rc2[((b0 + bl) * 256 + cog * 32 + yq * 8 + co) * 49 + px] = acc[bl][co];
}

// ---------------------------------------------------------------------------
// shortcut 1x1 s2, smem staged, scalar. grid (8 cog, 64 b), block 196.
// ---------------------------------------------------------------------------
__global__ void __launch_bounds__(196) k_shortcut(const float* __restrict__ w) {
    __shared__ __align__(16) float s_c[128 * 49];
    __shared__ __align__(16) float s_wv[32 * 128];
    int b = blockIdx.y, cog = blockIdx.x;
    int tid = threadIdx.x;
    int px = tid % 49, yq = tid / 49;

    for (int t = tid; t < 128 * 49; t += 196) {
        int ci = t / 49, p = t - ci * 49;
        int oh = p / 7, ow = p - oh * 7;
        s_c[t] = g_pool2[(b * 128 + ci) * 196 + oh * 28 + ow * 2];
    }
    for (int t = tid; t < 32 * 128; t += 196) {
        int co = t >> 7, ci = t & 127;
        s_wv[t] = w[(cog * 32 + co) * 128 + ci];
    }
    __syncthreads();

    float acc[8];
#pragma unroll
    for (int co = 0; co < 8; co++) acc[co] = 0.f;
#pragma unroll 1
    for (int cp = 0; cp < 64; cp++) {
        float in0 = s_c[(2 * cp) * 49 + px];
        float in1 = s_c[(2 * cp + 1) * 49 + px];
#pragma unroll
        for (int co = 0; co < 8; co++) {
            float2 wv = *(const float2*)(s_wv + (yq * 8 + co) * 128 + 2 * cp);
            acc[co] += wv.x * in0;
            acc[co] += wv.y * in1;
        }
    }
#pragma unroll
    for (int co = 0; co < 8; co++)
        g_rs[(b * 256 + cog * 32 + yq * 8 + co) * 49 + px] = acc[co];
}

// ---------------------------------------------------------------------------
// tail: y = mean relu(bn(rc2)+bn(rs)); out = y M^T + b2
// ---------------------------------------------------------------------------
__global__ void k_tail(float* __restrict__ out) {
    __shared__ float s_y[256];
    int b = blockIdx.x, c = threadIdx.x;
    float sc2 = g_scr2[c], sh2 = g_shr2[c], scs = g_scs[c], shs = g_shs[c];
    const float* p2 = g_rc2 + (b * 256 + c) * 49;
    const float* ps = g_rs + (b * 256 + c) * 49;
    float s = 0.f;
    for (int p = 0; p < 49; p++) {
        float v = p2[p] * sc2 + sh2 + ps[p] * scs + shs;
        s += fmaxf(v, 0.f);
    }
    s_y[c] = s * (1.f / 49.f);
    __syncthreads();
    if (c < 50) {
        float acc = g_b2[c];
        for (int k = 0; k < 256; k++) acc += s_y[k] * g_M[c * 256 + k];
        out[b * 50 + c] = acc;
    }
}

// ---------------------------------------------------------------------------
// Tail fold (softmax attention collapses to 1x1 conv: wo@wv)
// ---------------------------------------------------------------------------
__global__ void k_foldT(const float* __restrict__ fcw, const float* __restrict__ wo) {
    int idx = blockIdx.x * 256 + threadIdx.x;
    if (idx >= 50 * 1024) return;
    int i = idx / 1024, j = idx - i * 1024;
    float s = 0.f;
    for (int c = 0; c < 256; c++) s += fcw[i * 256 + c] * wo[c * 1024 + j];
    g_T[idx] = s;
}

__global__ void k_foldM(const float* __restrict__ wv) {
    int idx = blockIdx.x * 256 + threadIdx.x;
    if (idx >= 50 * 256) return;
    int i = idx / 256, c = idx - i * 256;
    float s = 0.f;
    for (int j = 0; j < 1024; j++) s += g_T[i * 1024 + j] * wv[j * 256 + c];
    g_M[idx] = s;
}

__global__ void k_foldb(const float* __restrict__ fcw, const float* __restrict__ bo,
                        const float* __restrict__ fcb) {
    int i = threadIdx.x;
    if (i >= 50) return;
    float s = 0.f;
    for (int c = 0; c < 256; c++) s += fcw[i * 256 + c] * bo[c];
    g_b2[i] = s + fcb[i];
}

// ---------------------------------------------------------------------------
// Launch (k_conv1 is the 4th launch -> ncu profile target / control)
// ---------------------------------------------------------------------------
extern "C" void kernel_launch(void* const* d_in, const int* in_sizes, int n_in,
                              void* d_out, int out_size) {
    const float* imgs   = (const float*)d_in[0];
    const float* a1f1   = (const float*)d_in[1];
    const float* a1f2   = (const float*)d_in[2];
    const float* a1f2b  = (const float*)d_in[3];
    const float* dy1    = (const float*)d_in[4];
    const float* bn1g   = (const float*)d_in[5];
    const float* bn1b   = (const float*)d_in[6];
    const float* a2f1   = (const float*)d_in[7];
    const float* a2f2   = (const float*)d_in[8];
    const float* a2f2b  = (const float*)d_in[9];
    const float* dy2    = (const float*)d_in[10];
    const float* bn2g   = (const float*)d_in[11];
    const float* bn2b   = (const float*)d_in[12];
    const float* rc1w   = (const float*)d_in[13];
    const float* rbn1g  = (const float*)d_in[14];
    const float* rbn1b  = (const float*)d_in[15];
    const float* rc2w   = (const float*)d_in[16];
    const float* rbn2g  = (const float*)d_in[17];
    const float* rbn2b  = (const float*)d_in[18];
    const float* rsw    = (const float*)d_in[19];
    const float* rbnsg  = (const float*)d_in[20];
    const float* rbnsb  = (const float*)d_in[21];
    const float* wv     = (const float*)d_in[24];
    const float* wo     = (const float*)d_in[25];
    const float* bo     = (const float*)d_in[26];
    const float* fcw    = (const float*)d_in[27];
    const float* fcb    = (const float*)d_in[28];
    float* out = (float*)d_out;
    (void)in_sizes; (void)n_in; (void)out_size;

    static int smem_set = 0;
    if (!smem_set) {
        cudaFuncSetAttribute(k_conv1, cudaFuncAttributeMaxDynamicSharedMemorySize,
                             CONV1_SMEM);
        cudaFuncSetAttribute(k_conv1, cudaFuncAttributePreferredSharedMemoryCarveout,
                             100);
        cudaFuncSetAttribute(k_conv2, cudaFuncAttributeMaxDynamicSharedMemorySize,
                             CONV2_SMEM);
        cudaFuncSetAttribute(k_conv2, cudaFuncAttributePreferredSharedMemoryCarveout,
                             100);
        cudaFuncSetAttribute(k_bnpool1, cudaFuncAttributeMaxDynamicSharedMemorySize,
                             POOL1_SMEM);
        smem_set = 1;
    }

    // stage 1 front (block 0 of pooled1 zeroes accumulators)
    k_pooled1<<<192, 256>>>(imgs);
    k_attn1<<<1, 64>>>(a1f1, a1f2, a1f2b);
    k_w1agg<<<(BB * 10752 + 255) / 256, 256>>>(dy1);
    k_conv1<<<dim3(49, BB), 256, CONV1_SMEM>>>(imgs);  // 4th (profiled, control)

    // tail fold (independent)
    k_foldT<<<200, 256>>>(fcw, wo);
    k_foldM<<<50, 256>>>(wv);
    k_foldb<<<1, 64>>>(fcw, bo, fcb);

    k_bnscale<<<1, 64>>>(bn1g, bn1b, 802816.f, 0, 64);
    k_bnpool1<<<dim3(64, BB), 256, POOL1_SMEM>>>();

    // stage 2
    k_attn2<<<1, 64>>>(a2f1, a2f2, a2f2b);
    k_w2agg<<<(BB * 73728 + 255) / 256, 256>>>(dy2);
    k_conv2<<<dim3(7, BB), 256, CONV2_SMEM>>>();
    k_bnscale<<<1, 128>>>(bn2g, bn2b, 50176.f, 1, 128);
    k_bnpool2<<<dim3(128, BB), 196>>>();

    // residual block
    k_resconv1<<<dim3(8, BB / 4), 196>>>(rc1w);
    k_shortcut<<<dim3(8, BB), 196>>>(rsw);
    k_chstats<<<256, 128>>>(rbn1g, rbn1b);
    k_resconv2<<<dim3(8, BB / 4), 196>>>(rc2w);
    k_chstats2<<<256, 128>>>(rbn2g, rbn2b, rbnsg, rbnsb);

    k_tail<<<64, 256>>>(out);
}